// round 1
// baseline (speedup 1.0000x reference)
#include <cuda_runtime.h>

// ---------------------------------------------------------------------------
// QuantumAttention  (B=2, S=2048, E=1024, H=16, dk=64, NQ=4, NL=2)
// Inputs (metadata order): x[2,2048,1024], params[2,4,3],
//                          w_q[1024,1024], w_k[1024,1024], w_v[1024,1024], w_o[1024,1024]
// Output: float32 [2,2048,1024]
// ---------------------------------------------------------------------------

#define BQ   64     // query rows per attention block
#define BKT  32     // key tile

// Scratch (allocation-free rule: __device__ globals)
__device__ float g_q [2*16*2048*64];   // [b][h][s][d]
__device__ float g_k [2*16*2048*64];
__device__ float g_v [2*16*2048*64];
__device__ float g_ao[2*2048*1024];    // attention out, [b][s][h*64+d]

// ---------------------------------------------------------------------------
// 128x128x8 fp32 GEMM body:  C[m][n] = sum_k A[m][k] * B[n][k]   (K = 1024)
// 256 threads, each computes 8x8.
// ---------------------------------------------------------------------------
__device__ __forceinline__ void sgemm_body(const float* __restrict__ A,
                                           const float* __restrict__ B,
                                           float (&acc)[8][8], int m0, int n0)
{
    __shared__ float As[8][128];
    __shared__ float Bs[8][128];

    const int t    = threadIdx.x;
    const int tx   = t & 15;
    const int ty   = t >> 4;
    const int lrow = t >> 1;          // 0..127
    const int lcol = (t & 1) << 2;    // 0 or 4

#pragma unroll
    for (int i = 0; i < 8; i++)
#pragma unroll
        for (int j = 0; j < 8; j++) acc[i][j] = 0.f;

    const float* Ap = A + (size_t)(m0 + lrow) * 1024 + lcol;
    const float* Bp = B + (size_t)(n0 + lrow) * 1024 + lcol;

    for (int k0 = 0; k0 < 1024; k0 += 8) {
        float4 av = *(const float4*)(Ap + k0);
        float4 bv = *(const float4*)(Bp + k0);
        __syncthreads();   // protect previous iteration's reads
        As[lcol + 0][lrow] = av.x;  As[lcol + 1][lrow] = av.y;
        As[lcol + 2][lrow] = av.z;  As[lcol + 3][lrow] = av.w;
        Bs[lcol + 0][lrow] = bv.x;  Bs[lcol + 1][lrow] = bv.y;
        Bs[lcol + 2][lrow] = bv.z;  Bs[lcol + 3][lrow] = bv.w;
        __syncthreads();

#pragma unroll
        for (int kk = 0; kk < 8; kk++) {
            float4 a0 = *(const float4*)&As[kk][ty * 8];
            float4 a1 = *(const float4*)&As[kk][ty * 8 + 4];
            float4 b0 = *(const float4*)&Bs[kk][tx * 8];
            float4 b1 = *(const float4*)&Bs[kk][tx * 8 + 4];
            float a[8] = {a0.x, a0.y, a0.z, a0.w, a1.x, a1.y, a1.z, a1.w};
            float b[8] = {b0.x, b0.y, b0.z, b0.w, b1.x, b1.y, b1.z, b1.w};
#pragma unroll
            for (int i = 0; i < 8; i++)
#pragma unroll
                for (int j = 0; j < 8; j++)
                    acc[i][j] += a[i] * b[j];
        }
    }
}

// ---------------------------------------------------------------------------
// QKV projection: grid (N/128=8, M/128=32, 3). Writes [b][h][s][d] layout.
// ---------------------------------------------------------------------------
__global__ __launch_bounds__(256, 2)
void gemm_qkv_kernel(const float* __restrict__ X,
                     const float* __restrict__ Wq,
                     const float* __restrict__ Wk,
                     const float* __restrict__ Wv)
{
    const float* W = (blockIdx.z == 0) ? Wq : (blockIdx.z == 1) ? Wk : Wv;
    float*       O = (blockIdx.z == 0) ? g_q : (blockIdx.z == 1) ? g_k : g_v;

    const int m0 = blockIdx.y * 128;
    const int n0 = blockIdx.x * 128;

    float acc[8][8];
    sgemm_body(X, W, acc, m0, n0);

    const int tx = threadIdx.x & 15;
    const int ty = threadIdx.x >> 4;
    const int n  = n0 + tx * 8;          // 8 cols always inside one head (8 | 64)
    const int h  = n >> 6;
    const int d  = n & 63;

#pragma unroll
    for (int i = 0; i < 8; i++) {
        const int m = m0 + ty * 8 + i;
        const int b = m >> 11;
        const int s = m & 2047;
        float* dst = O + ((size_t)(((b << 4) + h) * 2048 + s) << 6) + d;
        *(float4*)(dst)     = make_float4(acc[i][0], acc[i][1], acc[i][2], acc[i][3]);
        *(float4*)(dst + 4) = make_float4(acc[i][4], acc[i][5], acc[i][6], acc[i][7]);
    }
}

// ---------------------------------------------------------------------------
// Output projection: C[m][n] = sum_k g_ao[m][k] * Wo[n][k]
// ---------------------------------------------------------------------------
__global__ __launch_bounds__(256, 2)
void gemm_out_kernel(const float* __restrict__ Wo, float* __restrict__ C)
{
    const int m0 = blockIdx.y * 128;
    const int n0 = blockIdx.x * 128;

    float acc[8][8];
    sgemm_body(g_ao, Wo, acc, m0, n0);

    const int tx = threadIdx.x & 15;
    const int ty = threadIdx.x >> 4;
#pragma unroll
    for (int i = 0; i < 8; i++) {
        const int m = m0 + ty * 8 + i;
        float* dst = C + (size_t)m * 1024 + n0 + tx * 8;
        *(float4*)(dst)     = make_float4(acc[i][0], acc[i][1], acc[i][2], acc[i][3]);
        *(float4*)(dst + 4) = make_float4(acc[i][4], acc[i][5], acc[i][6], acc[i][7]);
    }
}

// ---------------------------------------------------------------------------
// Quantum block: 4-qubit statevector per (tensor, b, h, s).
// In-place: replaces first 4 of 64 dims with Pauli-Z expectation values.
// Wire q <-> bit (3-q)  (wire 0 = MSB), matching the reference reshape.
// ---------------------------------------------------------------------------
__global__ void quantum_kernel(const float* __restrict__ params)
{
    const int id = blockIdx.x * 256 + threadIdx.x;
    if (id >= 3 * 65536) return;

    float* base = (id < 65536) ? g_q : (id < 2 * 65536 ? g_k : g_v);
    float* vec  = base + (size_t)(id & 65535) * 64;

    float ax[4];
#pragma unroll
    for (int w = 0; w < 4; w++) ax[w] = vec[w];

    float sr[16], si[16];
#pragma unroll
    for (int i = 0; i < 16; i++) { sr[i] = 0.f; si[i] = 0.f; }
    sr[0] = 1.f;

    // AngleEmbedding: RX(ax[w]) on wire w.  RX = [[c, -i s], [-i s, c]]
#pragma unroll
    for (int w = 0; w < 4; w++) {
        const float a = 0.5f * ax[w];
        float s, c;
        sincosf(a, &s, &c);
        const int st = 8 >> w;
#pragma unroll
        for (int i = 0; i < 16; i++) {
            if (i & st) continue;
            const int j = i + st;
            const float xr = sr[i], xi = si[i], yr = sr[j], yi = si[j];
            sr[i] = c * xr + s * yi;
            si[i] = c * xi - s * yr;
            sr[j] = c * yr + s * xi;
            si[j] = c * yi - s * xr;
        }
    }

    // Variational layers: Rot on each wire, then CNOT(0,1)
#pragma unroll
    for (int l = 0; l < 2; l++) {
#pragma unroll
        for (int w = 0; w < 4; w++) {
            const float phi = params[l * 12 + w * 3 + 0];
            const float th  = params[l * 12 + w * 3 + 1];
            const float om  = params[l * 12 + w * 3 + 2];
            float stt, ct;  sincosf(0.5f * th, &stt, &ct);
            float sap, cap; sincosf(0.5f * (phi + om), &sap, &cap);
            float sam, cam; sincosf(0.5f * (phi - om), &sam, &cam);
            // m00 = e^{-i(phi+om)/2} c ; m01 = -e^{+i(phi-om)/2} s
            // m10 = e^{-i(phi-om)/2} s ; m11 = e^{+i(phi+om)/2} c
            const float m00r =  cap * ct,  m00i = -sap * ct;
            const float m01r = -cam * stt, m01i = -sam * stt;
            const float m10r =  cam * stt, m10i = -sam * stt;
            const float m11r =  cap * ct,  m11i =  sap * ct;
            const int st = 8 >> w;
#pragma unroll
            for (int i = 0; i < 16; i++) {
                if (i & st) continue;
                const int j = i + st;
                const float xr = sr[i], xi = si[i], yr = sr[j], yi = si[j];
                sr[i] = m00r * xr - m00i * xi + m01r * yr - m01i * yi;
                si[i] = m00r * xi + m00i * xr + m01r * yi + m01i * yr;
                sr[j] = m10r * xr - m10i * xi + m11r * yr - m11i * yi;
                si[j] = m10r * xi + m10i * xr + m11r * yi + m11i * yr;
            }
        }
        // CNOT control wire0 (bit 8), target wire1 (bit 4): swap 8+r <-> 12+r
#pragma unroll
        for (int r = 0; r < 4; r++) {
            float tr = sr[8 + r], ti = si[8 + r];
            sr[8 + r] = sr[12 + r];  si[8 + r] = si[12 + r];
            sr[12 + r] = tr;         si[12 + r] = ti;
        }
    }

    float ev[4] = {0.f, 0.f, 0.f, 0.f};
#pragma unroll
    for (int i = 0; i < 16; i++) {
        const float pr = sr[i] * sr[i] + si[i] * si[i];
#pragma unroll
        for (int w = 0; w < 4; w++)
            ev[w] += ((i >> (3 - w)) & 1) ? -pr : pr;
    }
#pragma unroll
    for (int w = 0; w < 4; w++) vec[w] = ev[w];
}

// ---------------------------------------------------------------------------
// Flash-style attention (fp32). Grid: (S/64=32, B*H=32), 256 threads.
// Each block: 64 query rows of one (b,h); loops over key tiles of 32.
// Writes g_ao in [b][s][h*64+d] layout.
// ---------------------------------------------------------------------------
__global__ __launch_bounds__(256)
void attention_kernel()
{
    __shared__ float Qt[64][64];        // [d][r]   (transposed for vector LDS)
    __shared__ float Kt[64][BKT];       // [d][c]
    __shared__ float Vs[BKT][64];       // [c][d]
    __shared__ float Ps[64][BKT + 1];   // scores / probs, padded
    __shared__ float rowm[64], rowl[64], rowa[64];

    const int t  = threadIdx.x;
    const int bh = blockIdx.y;
    const int q0 = blockIdx.x * 64;

    const float* qb = g_q + (size_t)bh * 2048 * 64;
    const float* kb = g_k + (size_t)bh * 2048 * 64;
    const float* vb = g_v + (size_t)bh * 2048 * 64;

    // Load Q tile transposed: Qt[d][r]
#pragma unroll
    for (int rep = 0; rep < 4; rep++) {
        const int e = (rep * 256 + t) * 4;
        const int r = e >> 6, d = e & 63;
        float4 vq = *(const float4*)(qb + (size_t)(q0 + r) * 64 + d);
        Qt[d + 0][r] = vq.x; Qt[d + 1][r] = vq.y;
        Qt[d + 2][r] = vq.z; Qt[d + 3][r] = vq.w;
    }
    if (t < 64) { rowm[t] = -1e30f; rowl[t] = 0.f; }

    float acc[4][4] = {{0.f}};
    const int tx = t & 15;   // 16 cols of 4
    const int ty = t >> 4;   // 16 rows of 4

    for (int kt = 0; kt < 2048; kt += BKT) {
        __syncthreads();   // covers Q-load/init on first iter, Vs/Ps reuse after

        // Load K tile transposed + V tile natural
#pragma unroll
        for (int rep = 0; rep < 2; rep++) {
            const int e = (rep * 256 + t) * 4;
            const int c = e >> 6, d = e & 63;
            float4 vk = *(const float4*)(kb + (size_t)(kt + c) * 64 + d);
            Kt[d + 0][c] = vk.x; Kt[d + 1][c] = vk.y;
            Kt[d + 2][c] = vk.z; Kt[d + 3][c] = vk.w;
            *(float4*)(&Vs[0][0] + e) = *(const float4*)(vb + (size_t)kt * 64 + e);
        }
        __syncthreads();

        // Scores: S[4ty+i][2tx+j] = sum_d Q[r][d] K[c][d]
        float sc[4][2] = {{0.f}};
#pragma unroll
        for (int d = 0; d < 64; d++) {
            float4 a = *(const float4*)&Qt[d][ty * 4];
            float2 b = *(const float2*)&Kt[d][tx * 2];
            sc[0][0] += a.x * b.x;  sc[0][1] += a.x * b.y;
            sc[1][0] += a.y * b.x;  sc[1][1] += a.y * b.y;
            sc[2][0] += a.z * b.x;  sc[2][1] += a.z * b.y;
            sc[3][0] += a.w * b.x;  sc[3][1] += a.w * b.y;
        }
#pragma unroll
        for (int i = 0; i < 4; i++)
#pragma unroll
            for (int j = 0; j < 2; j++)
                Ps[ty * 4 + i][tx * 2 + j] = sc[i][j] * 0.125f;   // 1/sqrt(64)
        __syncthreads();

        // Online softmax: 4 threads per row, 8 cols each
        {
            const int r  = t >> 2;
            const int p4 = t & 3;
            float* row = &Ps[r][p4 * 8];
            float mloc = row[0];
#pragma unroll
            for (int c = 1; c < 8; c++) mloc = fmaxf(mloc, row[c]);
            mloc = fmaxf(mloc, __shfl_xor_sync(0xffffffffu, mloc, 1));
            mloc = fmaxf(mloc, __shfl_xor_sync(0xffffffffu, mloc, 2));
            const float mnew = fmaxf(rowm[r], mloc);
            float sum = 0.f;
#pragma unroll
            for (int c = 0; c < 8; c++) {
                const float e = __expf(row[c] - mnew);
                row[c] = e;
                sum += e;
            }
            sum += __shfl_xor_sync(0xffffffffu, sum, 1);
            sum += __shfl_xor_sync(0xffffffffu, sum, 2);
            if (p4 == 0) {
                const float al = __expf(rowm[r] - mnew);
                rowa[r] = al;
                rowl[r] = rowl[r] * al + sum;
                rowm[r] = mnew;
            }
        }
        __syncthreads();

        // Rescale + PV accumulate: O[4ty+i][4tx+j]
        float al[4];
#pragma unroll
        for (int i = 0; i < 4; i++) al[i] = rowa[ty * 4 + i];
#pragma unroll
        for (int i = 0; i < 4; i++)
#pragma unroll
            for (int j = 0; j < 4; j++) acc[i][j] *= al[i];

#pragma unroll
        for (int kk = 0; kk < BKT; kk++) {
            float4 vv = *(const float4*)&Vs[kk][tx * 4];
#pragma unroll
            for (int i = 0; i < 4; i++) {
                const float p = Ps[ty * 4 + i][kk];
                acc[i][0] += p * vv.x;  acc[i][1] += p * vv.y;
                acc[i][2] += p * vv.z;  acc[i][3] += p * vv.w;
            }
        }
    }

    // Normalize and write to g_ao [b][s][h*64+d]
    const int b = bh >> 4, h = bh & 15;
#pragma unroll
    for (int i = 0; i < 4; i++) {
        const int r   = ty * 4 + i;
        const float inv = 1.f / rowl[r];
        float4 o = make_float4(acc[i][0] * inv, acc[i][1] * inv,
                               acc[i][2] * inv, acc[i][3] * inv);
        *(float4*)(g_ao + ((size_t)(b * 2048 + q0 + r) * 1024) + h * 64 + tx * 4) = o;
    }
}

// ---------------------------------------------------------------------------
extern "C" void kernel_launch(void* const* d_in, const int* in_sizes, int n_in,
                              void* d_out, int out_size)
{
    const float* x      = (const float*)d_in[0];
    const float* params = (const float*)d_in[1];
    const float* wq     = (const float*)d_in[2];
    const float* wk     = (const float*)d_in[3];
    const float* wv     = (const float*)d_in[4];
    const float* wo     = (const float*)d_in[5];
    float* out = (float*)d_out;

    gemm_qkv_kernel<<<dim3(8, 32, 3), 256>>>(x, wq, wk, wv);
    quantum_kernel<<<768, 256>>>(params);
    attention_kernel<<<dim3(32, 32), 256>>>();
    gemm_out_kernel<<<dim3(8, 32), 256>>>(wo, out);
}

// round 3
// speedup vs baseline: 1.1978x; 1.1978x over previous
#include <cuda_runtime.h>
#include <cuda_bf16.h>
#include <cstdint>

// ---------------------------------------------------------------------------
// QuantumAttention  (B=2, S=2048, E=1024, H=16, dk=64, NQ=4, NL=2)
// Round 3: GEMMs via mma.sync bf16 (bf16x3 split, fp32 acc) — tcgen05 is not
// available through the harness's compute_103 virtual arch.
// ---------------------------------------------------------------------------

// ---------------- scratch (__device__ globals; no allocs allowed) ----------
__device__ float g_q [2*16*2048*64];   // [b][h][s][d]
__device__ float g_k [2*16*2048*64];
__device__ float g_v [2*16*2048*64];
__device__ float g_ao[2*2048*1024];    // attention out, [b][s][h*64+d]

__device__ __nv_bfloat16 g_xhi [4096*1024];
__device__ __nv_bfloat16 g_xlo [4096*1024];
__device__ __nv_bfloat16 g_whi [4*1024*1024];   // q,k,v,o packed
__device__ __nv_bfloat16 g_wlo [4*1024*1024];
__device__ __nv_bfloat16 g_aohi[4096*1024];
__device__ __nv_bfloat16 g_aolo[4096*1024];

// ---------------- helpers ---------------------------------------------------
__device__ __forceinline__ uint32_t smem_u32(const void* p) {
    uint32_t a;
    asm("{ .reg .u64 t; cvta.to.shared.u64 t, %1; cvt.u32.u64 %0, t; }" : "=r"(a) : "l"(p));
    return a;
}
#define CP_ASYNC16(dst, src) \
    asm volatile("cp.async.cg.shared.global [%0], [%1], 16;" :: "r"(dst), "l"(src) : "memory")
#define CP_COMMIT() asm volatile("cp.async.commit_group;" ::: "memory")
#define CP_WAIT(n)  asm volatile("cp.async.wait_group %0;" :: "n"(n) : "memory")

__device__ __forceinline__ void ldmatrix_x4(uint32_t (&r)[4], uint32_t addr) {
    asm volatile("ldmatrix.sync.aligned.m8n8.x4.shared.b16 {%0,%1,%2,%3}, [%4];"
                 : "=r"(r[0]), "=r"(r[1]), "=r"(r[2]), "=r"(r[3]) : "r"(addr));
}
__device__ __forceinline__ void ldmatrix_x2(uint32_t (&r)[2], uint32_t addr) {
    asm volatile("ldmatrix.sync.aligned.m8n8.x2.shared.b16 {%0,%1}, [%2];"
                 : "=r"(r[0]), "=r"(r[1]) : "r"(addr));
}
__device__ __forceinline__ void mma_bf16(float (&d)[4], const uint32_t (&a)[4],
                                         const uint32_t (&b)[2]) {
    asm volatile("mma.sync.aligned.m16n8k16.row.col.f32.bf16.bf16.f32 "
                 "{%0,%1,%2,%3}, {%4,%5,%6,%7}, {%8,%9}, {%0,%1,%2,%3};"
                 : "+f"(d[0]), "+f"(d[1]), "+f"(d[2]), "+f"(d[3])
                 : "r"(a[0]), "r"(a[1]), "r"(a[2]), "r"(a[3]), "r"(b[0]), "r"(b[1]));
}

// ---------------------------------------------------------------------------
// fp32 -> (bf16 hi, bf16 lo) split, vectorized by 4
// ---------------------------------------------------------------------------
__global__ void split_kernel(const float* __restrict__ src,
                             __nv_bfloat16* __restrict__ hi,
                             __nv_bfloat16* __restrict__ lo, int n4)
{
    const int i = blockIdx.x * 256 + threadIdx.x;
    if (i >= n4) return;
    float4 v = ((const float4*)src)[i];
    const float* a = &v.x;
    uint32_t hw[4], lw[4];
#pragma unroll
    for (int j = 0; j < 4; j++) {
        __nv_bfloat16 hb = __float2bfloat16(a[j]);
        float hf = __bfloat162float(hb);
        __nv_bfloat16 lb = __float2bfloat16(a[j] - hf);
        hw[j] = (uint32_t)__bfloat16_as_ushort(hb);
        lw[j] = (uint32_t)__bfloat16_as_ushort(lb);
    }
    ((uint2*)hi)[i] = make_uint2(hw[0] | (hw[1] << 16), hw[2] | (hw[3] << 16));
    ((uint2*)lo)[i] = make_uint2(lw[0] | (lw[1] << 16), lw[2] | (lw[3] << 16));
}

// ---------------------------------------------------------------------------
// mma.sync GEMM:  C[m][n] = sum_k A[m][k] * B[n][k],  M=4096, N=1024, K=1024
// CTA 128x128, K-chunk 32, double-buffered cp.async, bf16x3 split.
// 8 warps = 2(m) x 4(n); warp tile 64x32 = 16 m16n8k16 tiles.
// ---------------------------------------------------------------------------
#define PITCH   40                         // bf16 elems per smem row (32 + 8 pad)
#define MAT_B   (128 * PITCH * 2)          // 10240 B per matrix
#define STAGE_B (4 * MAT_B)                // Ahi, Alo, Bhi, Blo
#define GSMEM   (2 * STAGE_B)              // 81920 B

__global__ __launch_bounds__(256, 1)
void gemm_mma_kernel(const __nv_bfloat16* __restrict__ Ahi,
                     const __nv_bfloat16* __restrict__ Alo,
                     float* __restrict__ Cout, int is_proj)
{
    extern __shared__ char smem[];
    const uint32_t sb = smem_u32(smem);
    const int tid  = threadIdx.x;
    const int wid  = tid >> 5;
    const int lane = tid & 31;

    const int z  = blockIdx.z;
    const int m0 = blockIdx.y * 128;
    const int n0 = blockIdx.x * 128;
    const size_t woff = ((size_t)(is_proj ? z : 3)) << 20;

    // ---- load geometry: 4 matrices x 64 threads, 8x 16B chunks each --------
    const int mat = tid >> 6;       // 0=Ahi 1=Alo 2=Bhi 3=Blo
    const int tt  = tid & 63;
    const __nv_bfloat16* gbase;
    {
        const __nv_bfloat16* srcs[4] = { Ahi + (size_t)m0 * 1024,
                                         Alo + (size_t)m0 * 1024,
                                         g_whi + woff + (size_t)n0 * 1024,
                                         g_wlo + woff + (size_t)n0 * 1024 };
        gbase = srcs[mat];
    }
    const uint32_t sdst0 = sb + (uint32_t)mat * MAT_B;

    // ---- ldmatrix addresses (per warp) --------------------------------------
    const int wm = wid & 1;         // 0..1   (64 rows each)
    const int wn = wid >> 1;        // 0..3   (32 cols each)
    // A: lanes 0-15 -> row (lane&15), k+0 ; lanes 16-31 -> row (lane&15), k+8
    const uint32_t a_row = (uint32_t)(wm * 64 + (lane & 15));
    const uint32_t a_koff = (uint32_t)((lane >> 4) * 8);
    const uint32_t a_addr0 = a_row * (PITCH * 2) + a_koff * 2;
    // B: lanes 0-7 -> row, k+0 ; lanes 8-15 -> row, k+8 (lanes>=16 unused)
    const uint32_t b_row = (uint32_t)(wn * 32 + (lane & 7));
    const uint32_t b_koff = (uint32_t)(((lane >> 3) & 1) * 8);
    const uint32_t b_addr0 = b_row * (PITCH * 2) + b_koff * 2;

    float acc[4][4][4];             // [m-tile][n-tile][frag]
#pragma unroll
    for (int i = 0; i < 4; i++)
#pragma unroll
        for (int t = 0; t < 4; t++)
#pragma unroll
            for (int f = 0; f < 4; f++) acc[i][t][f] = 0.f;

    auto load_stage = [&](int ch, int buf) {
        const int k0 = ch * 32;
        const uint32_t dst = sdst0 + (uint32_t)buf * STAGE_B;
#pragma unroll
        for (int j = 0; j < 8; j++) {
            const int idx = tt * 8 + j;
            const int row = idx >> 2;
            const int c16 = idx & 3;
            CP_ASYNC16(dst + (uint32_t)row * (PITCH * 2) + (uint32_t)c16 * 16,
                       gbase + (size_t)row * 1024 + k0 + c16 * 8);
        }
        CP_COMMIT();
    };

    load_stage(0, 0);

    for (int ch = 0; ch < 32; ch++) {
        const int buf = ch & 1;
        if (ch < 31) load_stage(ch + 1, buf ^ 1);
        if (ch < 31) { CP_WAIT(1); } else { CP_WAIT(0); }
        __syncthreads();

        const uint32_t stg = sb + (uint32_t)buf * STAGE_B;
#pragma unroll
        for (int ks = 0; ks < 2; ks++) {
            const uint32_t kb = (uint32_t)(ks * 16 * 2);
            uint32_t ah[4][4], al[4][4];
#pragma unroll
            for (int i = 0; i < 4; i++) {
                const uint32_t ro = (uint32_t)(i * 16 * PITCH * 2);
                ldmatrix_x4(ah[i], stg + 0 * MAT_B + a_addr0 + ro + kb);
                ldmatrix_x4(al[i], stg + 1 * MAT_B + a_addr0 + ro + kb);
            }
            uint32_t bh[4][2], bl[4][2];
#pragma unroll
            for (int t = 0; t < 4; t++) {
                const uint32_t ro = (uint32_t)(t * 8 * PITCH * 2);
                ldmatrix_x2(bh[t], stg + 2 * MAT_B + b_addr0 + ro + kb);
                ldmatrix_x2(bl[t], stg + 3 * MAT_B + b_addr0 + ro + kb);
            }
#pragma unroll
            for (int i = 0; i < 4; i++)
#pragma unroll
                for (int t = 0; t < 4; t++) {
                    mma_bf16(acc[i][t], ah[i], bh[t]);
                    mma_bf16(acc[i][t], ah[i], bl[t]);
                    mma_bf16(acc[i][t], al[i], bh[t]);
                }
        }
        __syncthreads();
    }

    // ---- epilogue: registers -> global --------------------------------------
    const int r_in  = lane >> 2;          // 0..7
    const int c_in  = (lane & 3) * 2;     // 0,2,4,6
#pragma unroll
    for (int i = 0; i < 4; i++) {
#pragma unroll
        for (int half = 0; half < 2; half++) {
            const int m = m0 + wm * 64 + i * 16 + r_in + half * 8;
            const int b = m >> 11, s = m & 2047;
#pragma unroll
            for (int t = 0; t < 4; t++) {
                const int n = n0 + wn * 32 + t * 8 + c_in;
                float2 v = make_float2(acc[i][t][half * 2], acc[i][t][half * 2 + 1]);
                if (is_proj) {
                    float* O = (z == 0) ? g_q : (z == 1) ? g_k : g_v;
                    const int h = n >> 6, d = n & 63;
                    *(float2*)(O + (((size_t)((b << 4) + h) * 2048 + s) << 6) + d) = v;
                } else {
                    *(float2*)(Cout + (size_t)m * 1024 + n) = v;
                }
            }
        }
    }
}

// ---------------------------------------------------------------------------
// Quantum block (unchanged)
// ---------------------------------------------------------------------------
__global__ void quantum_kernel(const float* __restrict__ params)
{
    const int id = blockIdx.x * 256 + threadIdx.x;
    if (id >= 3 * 65536) return;
    float* base = (id < 65536) ? g_q : (id < 2 * 65536 ? g_k : g_v);
    float* vec  = base + (size_t)(id & 65535) * 64;

    float ax[4];
#pragma unroll
    for (int w = 0; w < 4; w++) ax[w] = vec[w];

    float sr[16], si[16];
#pragma unroll
    for (int i = 0; i < 16; i++) { sr[i] = 0.f; si[i] = 0.f; }
    sr[0] = 1.f;

#pragma unroll
    for (int w = 0; w < 4; w++) {
        const float a = 0.5f * ax[w];
        float s, c;
        sincosf(a, &s, &c);
        const int st = 8 >> w;
#pragma unroll
        for (int i = 0; i < 16; i++) {
            if (i & st) continue;
            const int j = i + st;
            const float xr = sr[i], xi = si[i], yr = sr[j], yi = si[j];
            sr[i] = c * xr + s * yi;  si[i] = c * xi - s * yr;
            sr[j] = c * yr + s * xi;  si[j] = c * yi - s * xr;
        }
    }
#pragma unroll
    for (int l = 0; l < 2; l++) {
#pragma unroll
        for (int w = 0; w < 4; w++) {
            const float phi = params[l * 12 + w * 3 + 0];
            const float th  = params[l * 12 + w * 3 + 1];
            const float om  = params[l * 12 + w * 3 + 2];
            float stt, ct;  sincosf(0.5f * th, &stt, &ct);
            float sap, cap; sincosf(0.5f * (phi + om), &sap, &cap);
            float sam, cam; sincosf(0.5f * (phi - om), &sam, &cam);
            const float m00r =  cap * ct,  m00i = -sap * ct;
            const float m01r = -cam * stt, m01i = -sam * stt;
            const float m10r =  cam * stt, m10i = -sam * stt;
            const float m11r =  cap * ct,  m11i =  sap * ct;
            const int st = 8 >> w;
#pragma unroll
            for (int i = 0; i < 16; i++) {
                if (i & st) continue;
                const int j = i + st;
                const float xr = sr[i], xi = si[i], yr = sr[j], yi = si[j];
                sr[i] = m00r * xr - m00i * xi + m01r * yr - m01i * yi;
                si[i] = m00r * xi + m00i * xr + m01r * yi + m01i * yr;
                sr[j] = m10r * xr - m10i * xi + m11r * yr - m11i * yi;
                si[j] = m10r * xi + m10i * xr + m11r * yi + m11i * yr;
            }
        }
#pragma unroll
        for (int r = 0; r < 4; r++) {
            float tr = sr[8 + r], ti = si[8 + r];
            sr[8 + r] = sr[12 + r];  si[8 + r] = si[12 + r];
            sr[12 + r] = tr;         si[12 + r] = ti;
        }
    }
    float ev[4] = {0.f, 0.f, 0.f, 0.f};
#pragma unroll
    for (int i = 0; i < 16; i++) {
        const float pr = sr[i] * sr[i] + si[i] * si[i];
#pragma unroll
        for (int w = 0; w < 4; w++)
            ev[w] += ((i >> (3 - w)) & 1) ? -pr : pr;
    }
#pragma unroll
    for (int w = 0; w < 4; w++) vec[w] = ev[w];
}

// ---------------------------------------------------------------------------
// Flash-style attention (fp32, unchanged)
// ---------------------------------------------------------------------------
#define BKT 32
__global__ __launch_bounds__(256)
void attention_kernel()
{
    __shared__ float Qt[64][64];
    __shared__ float Kt[64][BKT];
    __shared__ float Vs[BKT][64];
    __shared__ float Ps[64][BKT + 1];
    __shared__ float rowm[64], rowl[64], rowa[64];

    const int t  = threadIdx.x;
    const int bh = blockIdx.y;
    const int q0 = blockIdx.x * 64;

    const float* qb = g_q + (size_t)bh * 2048 * 64;
    const float* kb = g_k + (size_t)bh * 2048 * 64;
    const float* vb = g_v + (size_t)bh * 2048 * 64;

#pragma unroll
    for (int rep = 0; rep < 4; rep++) {
        const int e = (rep * 256 + t) * 4;
        const int r = e >> 6, d = e & 63;
        float4 vq = *(const float4*)(qb + (size_t)(q0 + r) * 64 + d);
        Qt[d + 0][r] = vq.x; Qt[d + 1][r] = vq.y;
        Qt[d + 2][r] = vq.z; Qt[d + 3][r] = vq.w;
    }
    if (t < 64) { rowm[t] = -1e30f; rowl[t] = 0.f; }

    float acc[4][4] = {{0.f}};
    const int tx = t & 15;
    const int ty = t >> 4;

    for (int kt = 0; kt < 2048; kt += BKT) {
        __syncthreads();
#pragma unroll
        for (int rep = 0; rep < 2; rep++) {
            const int e = (rep * 256 + t) * 4;
            const int c = e >> 6, d = e & 63;
            float4 vk = *(const float4*)(kb + (size_t)(kt + c) * 64 + d);
            Kt[d + 0][c] = vk.x; Kt[d + 1][c] = vk.y;
            Kt[d + 2][c] = vk.z; Kt[d + 3][c] = vk.w;
            *(float4*)(&Vs[0][0] + e) = *(const float4*)(vb + (size_t)kt * 64 + e);
        }
        __syncthreads();

        float sc[4][2] = {{0.f}};
#pragma unroll
        for (int d = 0; d < 64; d++) {
            float4 a = *(const float4*)&Qt[d][ty * 4];
            float2 b = *(const float2*)&Kt[d][tx * 2];
            sc[0][0] += a.x * b.x;  sc[0][1] += a.x * b.y;
            sc[1][0] += a.y * b.x;  sc[1][1] += a.y * b.y;
            sc[2][0] += a.z * b.x;  sc[2][1] += a.z * b.y;
            sc[3][0] += a.w * b.x;  sc[3][1] += a.w * b.y;
        }
#pragma unroll
        for (int i = 0; i < 4; i++)
#pragma unroll
            for (int j = 0; j < 2; j++)
                Ps[ty * 4 + i][tx * 2 + j] = sc[i][j] * 0.125f;
        __syncthreads();

        {
            const int r  = t >> 2;
            const int p4 = t & 3;
            float* row = &Ps[r][p4 * 8];
            float mloc = row[0];
#pragma unroll
            for (int c = 1; c < 8; c++) mloc = fmaxf(mloc, row[c]);
            mloc = fmaxf(mloc, __shfl_xor_sync(0xffffffffu, mloc, 1));
            mloc = fmaxf(mloc, __shfl_xor_sync(0xffffffffu, mloc, 2));
            const float mnew = fmaxf(rowm[r], mloc);
            float sum = 0.f;
#pragma unroll
            for (int c = 0; c < 8; c++) {
                const float e = __expf(row[c] - mnew);
                row[c] = e;
                sum += e;
            }
            sum += __shfl_xor_sync(0xffffffffu, sum, 1);
            sum += __shfl_xor_sync(0xffffffffu, sum, 2);
            if (p4 == 0) {
                const float al = __expf(rowm[r] - mnew);
                rowa[r] = al;
                rowl[r] = rowl[r] * al + sum;
                rowm[r] = mnew;
            }
        }
        __syncthreads();

        float al[4];
#pragma unroll
        for (int i = 0; i < 4; i++) al[i] = rowa[ty * 4 + i];
#pragma unroll
        for (int i = 0; i < 4; i++)
#pragma unroll
            for (int j = 0; j < 4; j++) acc[i][j] *= al[i];

#pragma unroll
        for (int kk = 0; kk < BKT; kk++) {
            float4 vv = *(const float4*)&Vs[kk][tx * 4];
#pragma unroll
            for (int i = 0; i < 4; i++) {
                const float p = Ps[ty * 4 + i][kk];
                acc[i][0] += p * vv.x;  acc[i][1] += p * vv.y;
                acc[i][2] += p * vv.z;  acc[i][3] += p * vv.w;
            }
        }
    }

    const int b = bh >> 4, h = bh & 15;
#pragma unroll
    for (int i = 0; i < 4; i++) {
        const int r = ty * 4 + i;
        const float inv = 1.f / rowl[r];
        float4 o = make_float4(acc[i][0] * inv, acc[i][1] * inv,
                               acc[i][2] * inv, acc[i][3] * inv);
        *(float4*)(g_ao + ((size_t)(b * 2048 + q0 + r) * 1024) + h * 64 + tx * 4) = o;
    }
}

// ---------------------------------------------------------------------------
extern "C" void kernel_launch(void* const* d_in, const int* in_sizes, int n_in,
                              void* d_out, int out_size)
{
    const float* x      = (const float*)d_in[0];
    const float* params = (const float*)d_in[1];
    const float* wq     = (const float*)d_in[2];
    const float* wk     = (const float*)d_in[3];
    const float* wv     = (const float*)d_in[4];
    const float* wo     = (const float*)d_in[5];
    float* out = (float*)d_out;

    cudaFuncSetAttribute(gemm_mma_kernel,
                         cudaFuncAttributeMaxDynamicSharedMemorySize, GSMEM);

    __nv_bfloat16 *whi, *wlo, *xhi, *xlo, *aohi, *aolo;
    cudaGetSymbolAddress((void**)&whi,  g_whi);
    cudaGetSymbolAddress((void**)&wlo,  g_wlo);
    cudaGetSymbolAddress((void**)&xhi,  g_xhi);
    cudaGetSymbolAddress((void**)&xlo,  g_xlo);
    cudaGetSymbolAddress((void**)&aohi, g_aohi);
    cudaGetSymbolAddress((void**)&aolo, g_aolo);

    split_kernel<<<4096, 256>>>(x,  xhi, xlo, 1048576);
    split_kernel<<<1024, 256>>>(wq, whi + 0 * 1048576, wlo + 0 * 1048576, 262144);
    split_kernel<<<1024, 256>>>(wk, whi + 1 * 1048576, wlo + 1 * 1048576, 262144);
    split_kernel<<<1024, 256>>>(wv, whi + 2 * 1048576, wlo + 2 * 1048576, 262144);
    split_kernel<<<1024, 256>>>(wo, whi + 3 * 1048576, wlo + 3 * 1048576, 262144);

    gemm_mma_kernel<<<dim3(8, 32, 3), 256, GSMEM>>>(xhi, xlo, nullptr, 1);
    quantum_kernel<<<768, 256>>>(params);
    attention_kernel<<<dim3(32, 32), 256>>>();

    float* ao;
    cudaGetSymbolAddress((void**)&ao, g_ao);
    split_kernel<<<4096, 256>>>(ao, aohi, aolo, 1048576);
    gemm_mma_kernel<<<dim3(8, 32, 1), 256, GSMEM>>>(aohi, aolo, out, 0);
}

// round 4
// speedup vs baseline: 2.3519x; 1.9635x over previous
#include <cuda_runtime.h>
#include <cuda_bf16.h>
#include <cstdint>

// ---------------------------------------------------------------------------
// QuantumAttention  (B=2, S=2048, E=1024, H=16, dk=64, NQ=4, NL=2)
// Round 4: attention moved to mma.sync bf16 (FA2-style, bf16x3 split both for
// QK^T and PV). GEMMs unchanged from R3. V stored transposed [b][h][d][s].
// ---------------------------------------------------------------------------

__device__ float g_q [2*16*2048*64];   // [b][h][s][d]
__device__ float g_k [2*16*2048*64];   // [b][h][s][d]
__device__ float g_v [2*16*2048*64];   // [b][h][d][s]   (transposed!)
__device__ float g_ao[2*2048*1024];    // [b][s][h*64+d]

__device__ __nv_bfloat16 g_xhi [4096*1024];
__device__ __nv_bfloat16 g_xlo [4096*1024];
__device__ __nv_bfloat16 g_whi [4*1024*1024];
__device__ __nv_bfloat16 g_wlo [4*1024*1024];
__device__ __nv_bfloat16 g_aohi[4096*1024];
__device__ __nv_bfloat16 g_aolo[4096*1024];

// ---------------- helpers ---------------------------------------------------
__device__ __forceinline__ uint32_t smem_u32(const void* p) {
    uint32_t a;
    asm("{ .reg .u64 t; cvta.to.shared.u64 t, %1; cvt.u32.u64 %0, t; }" : "=r"(a) : "l"(p));
    return a;
}
#define CP_ASYNC16(dst, src) \
    asm volatile("cp.async.cg.shared.global [%0], [%1], 16;" :: "r"(dst), "l"(src) : "memory")
#define CP_COMMIT() asm volatile("cp.async.commit_group;" ::: "memory")
#define CP_WAIT(n)  asm volatile("cp.async.wait_group %0;" :: "n"(n) : "memory")

__device__ __forceinline__ void ldmatrix_x4(uint32_t (&r)[4], uint32_t addr) {
    asm volatile("ldmatrix.sync.aligned.m8n8.x4.shared.b16 {%0,%1,%2,%3}, [%4];"
                 : "=r"(r[0]), "=r"(r[1]), "=r"(r[2]), "=r"(r[3]) : "r"(addr));
}
__device__ __forceinline__ void ldmatrix_x2(uint32_t (&r)[2], uint32_t addr) {
    asm volatile("ldmatrix.sync.aligned.m8n8.x2.shared.b16 {%0,%1}, [%2];"
                 : "=r"(r[0]), "=r"(r[1]) : "r"(addr));
}
__device__ __forceinline__ void mma_bf16(float (&d)[4], const uint32_t (&a)[4],
                                         const uint32_t (&b)[2]) {
    asm volatile("mma.sync.aligned.m16n8k16.row.col.f32.bf16.bf16.f32 "
                 "{%0,%1,%2,%3}, {%4,%5,%6,%7}, {%8,%9}, {%0,%1,%2,%3};"
                 : "+f"(d[0]), "+f"(d[1]), "+f"(d[2]), "+f"(d[3])
                 : "r"(a[0]), "r"(a[1]), "r"(a[2]), "r"(a[3]), "r"(b[0]), "r"(b[1]));
}
// pack two fp32 -> bf16x2 register (lo -> bits 0-15, hi -> bits 16-31)
__device__ __forceinline__ uint32_t pack_bf16x2(float lo, float hi) {
    uint32_t r;
    asm("cvt.rn.bf16x2.f32 %0, %1, %2;" : "=r"(r) : "f"(hi), "f"(lo));
    return r;
}
__device__ __forceinline__ uint2 cvt4_hi(const float4 v) {
    return make_uint2(pack_bf16x2(v.x, v.y), pack_bf16x2(v.z, v.w));
}
__device__ __forceinline__ uint2 cvt4_lo(const float4 v, const uint2 hi) {
    __nv_bfloat162 h0 = *reinterpret_cast<const __nv_bfloat162*>(&hi.x);
    __nv_bfloat162 h1 = *reinterpret_cast<const __nv_bfloat162*>(&hi.y);
    float2 f0 = __bfloat1622float2(h0);
    float2 f1 = __bfloat1622float2(h1);
    return make_uint2(pack_bf16x2(v.x - f0.x, v.y - f0.y),
                      pack_bf16x2(v.z - f1.x, v.w - f1.y));
}
#define STS64(ad, v) \
    asm volatile("st.shared.v2.b32 [%0], {%1, %2};" :: "r"(ad), "r"((v).x), "r"((v).y) : "memory")

// ---------------------------------------------------------------------------
// fp32 -> (bf16 hi, bf16 lo) split
// ---------------------------------------------------------------------------
__global__ void split_kernel(const float* __restrict__ src,
                             __nv_bfloat16* __restrict__ hi,
                             __nv_bfloat16* __restrict__ lo, int n4)
{
    const int i = blockIdx.x * 256 + threadIdx.x;
    if (i >= n4) return;
    float4 v = ((const float4*)src)[i];
    uint2 ph = cvt4_hi(v);
    uint2 pl = cvt4_lo(v, ph);
    ((uint2*)hi)[i] = ph;
    ((uint2*)lo)[i] = pl;
}

// ---------------------------------------------------------------------------
// mma.sync GEMM (as R3):  C[m][n] = sum_k A[m][k] * B[n][k]
// ---------------------------------------------------------------------------
#define PITCH   40
#define MAT_B   (128 * PITCH * 2)
#define STAGE_B (4 * MAT_B)
#define GSMEM   (2 * STAGE_B)

__global__ __launch_bounds__(256, 1)
void gemm_mma_kernel(const __nv_bfloat16* __restrict__ Ahi,
                     const __nv_bfloat16* __restrict__ Alo,
                     float* __restrict__ Cout, int is_proj)
{
    extern __shared__ char smem[];
    const uint32_t sb = smem_u32(smem);
    const int tid  = threadIdx.x;
    const int wid  = tid >> 5;
    const int lane = tid & 31;

    const int z  = blockIdx.z;
    const int m0 = blockIdx.y * 128;
    const int n0 = blockIdx.x * 128;
    const size_t woff = ((size_t)(is_proj ? z : 3)) << 20;

    const int mat = tid >> 6;
    const int tt  = tid & 63;
    const __nv_bfloat16* gbase;
    {
        const __nv_bfloat16* srcs[4] = { Ahi + (size_t)m0 * 1024,
                                         Alo + (size_t)m0 * 1024,
                                         g_whi + woff + (size_t)n0 * 1024,
                                         g_wlo + woff + (size_t)n0 * 1024 };
        gbase = srcs[mat];
    }
    const uint32_t sdst0 = sb + (uint32_t)mat * MAT_B;

    const int wm = wid & 1;
    const int wn = wid >> 1;
    const uint32_t a_addr0 = (uint32_t)(wm * 64 + (lane & 15)) * (PITCH * 2)
                           + (uint32_t)((lane >> 4) * 8) * 2;
    const uint32_t b_addr0 = (uint32_t)(wn * 32 + (lane & 7)) * (PITCH * 2)
                           + (uint32_t)(((lane >> 3) & 1) * 8) * 2;

    float acc[4][4][4];
#pragma unroll
    for (int i = 0; i < 4; i++)
#pragma unroll
        for (int t = 0; t < 4; t++)
#pragma unroll
            for (int f = 0; f < 4; f++) acc[i][t][f] = 0.f;

    auto load_stage = [&](int ch, int buf) {
        const int k0 = ch * 32;
        const uint32_t dst = sdst0 + (uint32_t)buf * STAGE_B;
#pragma unroll
        for (int j = 0; j < 8; j++) {
            const int idx = tt * 8 + j;
            const int row = idx >> 2;
            const int c16 = idx & 3;
            CP_ASYNC16(dst + (uint32_t)row * (PITCH * 2) + (uint32_t)c16 * 16,
                       gbase + (size_t)row * 1024 + k0 + c16 * 8);
        }
        CP_COMMIT();
    };

    load_stage(0, 0);

    for (int ch = 0; ch < 32; ch++) {
        const int buf = ch & 1;
        if (ch < 31) load_stage(ch + 1, buf ^ 1);
        if (ch < 31) { CP_WAIT(1); } else { CP_WAIT(0); }
        __syncthreads();

        const uint32_t stg = sb + (uint32_t)buf * STAGE_B;
#pragma unroll
        for (int ks = 0; ks < 2; ks++) {
            const uint32_t kb = (uint32_t)(ks * 16 * 2);
            uint32_t ah[4][4], al[4][4];
#pragma unroll
            for (int i = 0; i < 4; i++) {
                const uint32_t ro = (uint32_t)(i * 16 * PITCH * 2);
                ldmatrix_x4(ah[i], stg + 0 * MAT_B + a_addr0 + ro + kb);
                ldmatrix_x4(al[i], stg + 1 * MAT_B + a_addr0 + ro + kb);
            }
            uint32_t bh[4][2], bl[4][2];
#pragma unroll
            for (int t = 0; t < 4; t++) {
                const uint32_t ro = (uint32_t)(t * 8 * PITCH * 2);
                ldmatrix_x2(bh[t], stg + 2 * MAT_B + b_addr0 + ro + kb);
                ldmatrix_x2(bl[t], stg + 3 * MAT_B + b_addr0 + ro + kb);
            }
#pragma unroll
            for (int i = 0; i < 4; i++)
#pragma unroll
                for (int t = 0; t < 4; t++) {
                    mma_bf16(acc[i][t], ah[i], bh[t]);
                    mma_bf16(acc[i][t], ah[i], bl[t]);
                    mma_bf16(acc[i][t], al[i], bh[t]);
                }
        }
        __syncthreads();
    }

    const int r_in = lane >> 2;
    const int c_in = (lane & 3) * 2;
#pragma unroll
    for (int i = 0; i < 4; i++) {
#pragma unroll
        for (int half = 0; half < 2; half++) {
            const int m = m0 + wm * 64 + i * 16 + r_in + half * 8;
            const int b = m >> 11, s = m & 2047;
#pragma unroll
            for (int t = 0; t < 4; t++) {
                const int n = n0 + wn * 32 + t * 8 + c_in;
                const float v0 = acc[i][t][half * 2], v1 = acc[i][t][half * 2 + 1];
                if (is_proj) {
                    const int h = n >> 6, d = n & 63;
                    if (z == 2) {   // V: transposed [b][h][d][s]
                        float* dst = g_v + ((size_t)(((b << 4) + h) << 6) + d) * 2048 + s;
                        dst[0] = v0; dst[2048] = v1;
                    } else {
                        float* O = (z == 0) ? g_q : g_k;
                        *(float2*)(O + (((size_t)((b << 4) + h) * 2048 + s) << 6) + d)
                            = make_float2(v0, v1);
                    }
                } else {
                    *(float2*)(Cout + (size_t)m * 1024 + n) = make_float2(v0, v1);
                }
            }
        }
    }
}

// ---------------------------------------------------------------------------
// Quantum block (V uses transposed layout: stride 2048 between wires)
// ---------------------------------------------------------------------------
__global__ void quantum_kernel(const float* __restrict__ params)
{
    const int id = blockIdx.x * 256 + threadIdx.x;
    if (id >= 3 * 65536) return;
    const int tensor = id >> 16;
    const int idx = id & 65535;
    float* vec;
    int stride;
    if (tensor == 0)      { vec = g_q + (size_t)idx * 64; stride = 1; }
    else if (tensor == 1) { vec = g_k + (size_t)idx * 64; stride = 1; }
    else {
        const int bh = idx >> 11, s = idx & 2047;
        vec = g_v + ((size_t)bh << 6) * 2048 + s; stride = 2048;
    }

    float ax[4];
#pragma unroll
    for (int w = 0; w < 4; w++) ax[w] = vec[w * stride];

    float sr[16], si[16];
#pragma unroll
    for (int i = 0; i < 16; i++) { sr[i] = 0.f; si[i] = 0.f; }
    sr[0] = 1.f;

#pragma unroll
    for (int w = 0; w < 4; w++) {
        const float a = 0.5f * ax[w];
        float s, c;
        sincosf(a, &s, &c);
        const int st = 8 >> w;
#pragma unroll
        for (int i = 0; i < 16; i++) {
            if (i & st) continue;
            const int j = i + st;
            const float xr = sr[i], xi = si[i], yr = sr[j], yi = si[j];
            sr[i] = c * xr + s * yi;  si[i] = c * xi - s * yr;
            sr[j] = c * yr + s * xi;  si[j] = c * yi - s * xr;
        }
    }
#pragma unroll
    for (int l = 0; l < 2; l++) {
#pragma unroll
        for (int w = 0; w < 4; w++) {
            const float phi = params[l * 12 + w * 3 + 0];
            const float th  = params[l * 12 + w * 3 + 1];
            const float om  = params[l * 12 + w * 3 + 2];
            float stt, ct;  sincosf(0.5f * th, &stt, &ct);
            float sap, cap; sincosf(0.5f * (phi + om), &sap, &cap);
            float sam, cam; sincosf(0.5f * (phi - om), &sam, &cam);
            const float m00r =  cap * ct,  m00i = -sap * ct;
            const float m01r = -cam * stt, m01i = -sam * stt;
            const float m10r =  cam * stt, m10i = -sam * stt;
            const float m11r =  cap * ct,  m11i =  sap * ct;
            const int st = 8 >> w;
#pragma unroll
            for (int i = 0; i < 16; i++) {
                if (i & st) continue;
                const int j = i + st;
                const float xr = sr[i], xi = si[i], yr = sr[j], yi = si[j];
                sr[i] = m00r * xr - m00i * xi + m01r * yr - m01i * yi;
                si[i] = m00r * xi + m00i * xr + m01r * yi + m01i * yr;
                sr[j] = m10r * xr - m10i * xi + m11r * yr - m11i * yi;
                si[j] = m10r * xi + m10i * xr + m11r * yi + m11i * yr;
            }
        }
#pragma unroll
        for (int r = 0; r < 4; r++) {
            float tr = sr[8 + r], ti = si[8 + r];
            sr[8 + r] = sr[12 + r];  si[8 + r] = si[12 + r];
            sr[12 + r] = tr;         si[12 + r] = ti;
        }
    }
    float ev[4] = {0.f, 0.f, 0.f, 0.f};
#pragma unroll
    for (int i = 0; i < 16; i++) {
        const float pr = sr[i] * sr[i] + si[i] * si[i];
#pragma unroll
        for (int w = 0; w < 4; w++)
            ev[w] += ((i >> (3 - w)) & 1) ? -pr : pr;
    }
#pragma unroll
    for (int w = 0; w < 4; w++) vec[w * stride] = ev[w];
}

// ---------------------------------------------------------------------------
// FA2-style attention on mma.sync bf16 (split x3 both phases).
// Grid: (S/128=16, B*H=32), 256 threads (8 warps x 16 q-rows).
// Key tile = 64. smem: double-buffered K/V hi/lo tiles, pitch 72 bf16.
// ---------------------------------------------------------------------------
#define AP      72                      // smem pitch in bf16
#define APB     (AP * 2)                // 144 bytes
#define KHI_O   0
#define KLO_O   (64 * APB)              // 9216
#define VHI_O   (2 * 64 * APB)          // 18432
#define VLO_O   (3 * 64 * APB)          // 27648
#define ABUF_B  (4 * 64 * APB)          // 36864
#define ASMEM   (2 * ABUF_B)            // 73728

__global__ __launch_bounds__(256, 1)
void attention_mma_kernel()
{
    extern __shared__ char smem[];
    const uint32_t sb = smem_u32(smem);
    const int tid  = threadIdx.x;
    const int wid  = tid >> 5;
    const int lane = tid & 31;

    const int bh = blockIdx.y;
    const int q0 = blockIdx.x * 128;

    const float* qb = g_q + (size_t)bh * 2048 * 64;
    const float* kb = g_k + (size_t)bh * 2048 * 64;
    const float* vb = g_v + (size_t)bh * 64 * 2048;   // [d][s]

    // ---- stage Q into buf0 area (hi at 0, lo at 18432), convert, ldmatrix ----
    {
#pragma unroll
        for (int j = 0; j < 8; j++) {
            const int idx = j * 256 + tid;          // 2048 float4 = 128x64
            const int r = idx >> 4, c4 = idx & 15;
            float4 v = *(const float4*)(qb + (size_t)(q0 + r) * 64 + c4 * 4);
            uint2 h = cvt4_hi(v);
            uint2 l = cvt4_lo(v, h);
            const uint32_t ad = sb + (uint32_t)r * APB + (uint32_t)c4 * 8;
            STS64(ad, h);
            STS64(ad + 18432, l);
        }
    }
    __syncthreads();

    uint32_t qh[4][4], ql[4][4];
    {
        const uint32_t a0 = sb + (uint32_t)(wid * 16 + (lane & 15)) * APB
                          + (uint32_t)((lane >> 4) * 8) * 2;
#pragma unroll
        for (int j = 0; j < 4; j++) {
            ldmatrix_x4(qh[j], a0 + (uint32_t)(j * 16) * 2);
            ldmatrix_x4(ql[j], a0 + 18432 + (uint32_t)(j * 16) * 2);
        }
    }
    __syncthreads();

    // ---- softmax state ----
    float m0r = -1e30f, m1r = -1e30f, l0 = 0.f, l1 = 0.f;
    float o[8][4];
#pragma unroll
    for (int t = 0; t < 8; t++)
#pragma unroll
        for (int f = 0; f < 4; f++) o[t][f] = 0.f;

    // B-frag smem addr offsets (same for K and V regions)
    const uint32_t brow = (uint32_t)(lane & 7) * APB + (uint32_t)(((lane >> 3) & 1) * 8) * 2;

    // ---- prefetch tile 0 ----
    float4 pf[8];
    auto load_tile = [&](int kt) {
#pragma unroll
        for (int j = 0; j < 4; j++) {               // K: 1024 float4
            const int idx = j * 256 + tid;
            const int key = idx >> 4, c4 = idx & 15;
            pf[j] = *(const float4*)(kb + (size_t)(kt + key) * 64 + c4 * 4);
        }
#pragma unroll
        for (int j = 0; j < 4; j++) {               // V: rows d, cols keys
            const int idx = j * 256 + tid;
            const int d = idx >> 4, c4 = idx & 15;
            pf[4 + j] = *(const float4*)(vb + (size_t)d * 2048 + kt + c4 * 4);
        }
    };
    auto store_tile = [&](int buf) {
        const uint32_t bp = sb + (uint32_t)buf * ABUF_B;
#pragma unroll
        for (int j = 0; j < 4; j++) {
            const int idx = j * 256 + tid;
            const int key = idx >> 4, c4 = idx & 15;
            uint2 h = cvt4_hi(pf[j]);
            uint2 l = cvt4_lo(pf[j], h);
            const uint32_t ad = bp + (uint32_t)key * APB + (uint32_t)c4 * 8;
            STS64(ad + KHI_O, h);
            STS64(ad + KLO_O, l);
        }
#pragma unroll
        for (int j = 0; j < 4; j++) {
            const int idx = j * 256 + tid;
            const int d = idx >> 4, c4 = idx & 15;
            uint2 h = cvt4_hi(pf[4 + j]);
            uint2 l = cvt4_lo(pf[4 + j], h);
            const uint32_t ad = bp + (uint32_t)d * APB + (uint32_t)c4 * 8;
            STS64(ad + VHI_O, h);
            STS64(ad + VLO_O, l);
        }
    };

    load_tile(0);
    store_tile(0);
    __syncthreads();

    for (int kt = 0; kt < 32; kt++) {
        const int buf = kt & 1;
        if (kt < 31) load_tile((kt + 1) * 64);

        const uint32_t bp = sb + (uint32_t)buf * ABUF_B;

        // ---- scores: s[8 ntiles][4] ----
        float s[8][4];
#pragma unroll
        for (int n = 0; n < 8; n++)
#pragma unroll
            for (int f = 0; f < 4; f++) s[n][f] = 0.f;

#pragma unroll
        for (int j = 0; j < 4; j++) {
            const uint32_t kb2 = (uint32_t)(j * 16) * 2;
            uint32_t kh[8][2], kl[8][2];
#pragma unroll
            for (int n = 0; n < 8; n++) {
                const uint32_t ro = (uint32_t)(n * 8) * APB;
                ldmatrix_x2(kh[n], bp + KHI_O + brow + ro + kb2);
                ldmatrix_x2(kl[n], bp + KLO_O + brow + ro + kb2);
            }
#pragma unroll
            for (int n = 0; n < 8; n++) {
                mma_bf16(s[n], qh[j], kh[n]);
                mma_bf16(s[n], qh[j], kl[n]);
                mma_bf16(s[n], ql[j], kh[n]);
            }
        }

        // ---- online softmax ----
        float tm0 = -1e30f, tm1 = -1e30f;
#pragma unroll
        for (int n = 0; n < 8; n++) {
#pragma unroll
            for (int f = 0; f < 4; f++) s[n][f] *= 0.125f;
            tm0 = fmaxf(tm0, fmaxf(s[n][0], s[n][1]));
            tm1 = fmaxf(tm1, fmaxf(s[n][2], s[n][3]));
        }
        tm0 = fmaxf(tm0, __shfl_xor_sync(0xffffffffu, tm0, 1));
        tm0 = fmaxf(tm0, __shfl_xor_sync(0xffffffffu, tm0, 2));
        tm1 = fmaxf(tm1, __shfl_xor_sync(0xffffffffu, tm1, 1));
        tm1 = fmaxf(tm1, __shfl_xor_sync(0xffffffffu, tm1, 2));
        const float mn0 = fmaxf(m0r, tm0), mn1 = fmaxf(m1r, tm1);
        const float a0 = __expf(m0r - mn0), a1 = __expf(m1r - mn1);
        m0r = mn0; m1r = mn1;

        float rs0 = 0.f, rs1 = 0.f;
#pragma unroll
        for (int n = 0; n < 8; n++) {
            s[n][0] = __expf(s[n][0] - mn0);
            s[n][1] = __expf(s[n][1] - mn0);
            s[n][2] = __expf(s[n][2] - mn1);
            s[n][3] = __expf(s[n][3] - mn1);
            rs0 += s[n][0] + s[n][1];
            rs1 += s[n][2] + s[n][3];
        }
        rs0 += __shfl_xor_sync(0xffffffffu, rs0, 1);
        rs0 += __shfl_xor_sync(0xffffffffu, rs0, 2);
        rs1 += __shfl_xor_sync(0xffffffffu, rs1, 1);
        rs1 += __shfl_xor_sync(0xffffffffu, rs1, 2);
        l0 = l0 * a0 + rs0;
        l1 = l1 * a1 + rs1;

#pragma unroll
        for (int t = 0; t < 8; t++) {
            o[t][0] *= a0; o[t][1] *= a0; o[t][2] *= a1; o[t][3] *= a1;
        }

        // ---- PV: P frags from score regs, V B-frags from smem ----
#pragma unroll
        for (int j = 0; j < 4; j++) {
            uint32_t ph[4], pl[4];
            ph[0] = pack_bf16x2(s[2 * j][0],     s[2 * j][1]);
            ph[1] = pack_bf16x2(s[2 * j][2],     s[2 * j][3]);
            ph[2] = pack_bf16x2(s[2 * j + 1][0], s[2 * j + 1][1]);
            ph[3] = pack_bf16x2(s[2 * j + 1][2], s[2 * j + 1][3]);
            {
                __nv_bfloat162 b0 = *reinterpret_cast<__nv_bfloat162*>(&ph[0]);
                __nv_bfloat162 b1 = *reinterpret_cast<__nv_bfloat162*>(&ph[1]);
                __nv_bfloat162 b2 = *reinterpret_cast<__nv_bfloat162*>(&ph[2]);
                __nv_bfloat162 b3 = *reinterpret_cast<__nv_bfloat162*>(&ph[3]);
                float2 f0 = __bfloat1622float2(b0), f1 = __bfloat1622float2(b1);
                float2 f2 = __bfloat1622float2(b2), f3 = __bfloat1622float2(b3);
                pl[0] = pack_bf16x2(s[2 * j][0] - f0.x,     s[2 * j][1] - f0.y);
                pl[1] = pack_bf16x2(s[2 * j][2] - f1.x,     s[2 * j][3] - f1.y);
                pl[2] = pack_bf16x2(s[2 * j + 1][0] - f2.x, s[2 * j + 1][1] - f2.y);
                pl[3] = pack_bf16x2(s[2 * j + 1][2] - f3.x, s[2 * j + 1][3] - f3.y);
            }
            const uint32_t kb2 = (uint32_t)(j * 16) * 2;
#pragma unroll
            for (int t = 0; t < 8; t++) {
                const uint32_t ro = (uint32_t)(t * 8) * APB;
                uint32_t vh[2], vl[2];
                ldmatrix_x2(vh, bp + VHI_O + brow + ro + kb2);
                ldmatrix_x2(vl, bp + VLO_O + brow + ro + kb2);
                mma_bf16(o[t], ph, vh);
                mma_bf16(o[t], ph, vl);
                mma_bf16(o[t], pl, vh);
            }
        }

        if (kt < 31) {
            store_tile(buf ^ 1);
            __syncthreads();
        }
    }

    // ---- epilogue: normalize, write g_ao [b][s][h*64+d] ----
    const int b = bh >> 4, h = bh & 15;
    const int r0 = q0 + wid * 16 + (lane >> 2);
    const int c0 = h * 64 + (lane & 3) * 2;
    const float il0 = 1.f / l0, il1 = 1.f / l1;
#pragma unroll
    for (int t = 0; t < 8; t++) {
        float* base0 = g_ao + (size_t)(b * 2048 + r0) * 1024 + c0 + t * 8;
        float* base1 = g_ao + (size_t)(b * 2048 + r0 + 8) * 1024 + c0 + t * 8;
        *(float2*)base0 = make_float2(o[t][0] * il0, o[t][1] * il0);
        *(float2*)base1 = make_float2(o[t][2] * il1, o[t][3] * il1);
    }
}

// ---------------------------------------------------------------------------
extern "C" void kernel_launch(void* const* d_in, const int* in_sizes, int n_in,
                              void* d_out, int out_size)
{
    const float* x      = (const float*)d_in[0];
    const float* params = (const float*)d_in[1];
    const float* wq     = (const float*)d_in[2];
    const float* wk     = (const float*)d_in[3];
    const float* wv     = (const float*)d_in[4];
    const float* wo     = (const float*)d_in[5];
    float* out = (float*)d_out;

    cudaFuncSetAttribute(gemm_mma_kernel,
                         cudaFuncAttributeMaxDynamicSharedMemorySize, GSMEM);
    cudaFuncSetAttribute(attention_mma_kernel,
                         cudaFuncAttributeMaxDynamicSharedMemorySize, ASMEM);

    __nv_bfloat16 *whi, *wlo, *xhi, *xlo, *aohi, *aolo;
    cudaGetSymbolAddress((void**)&whi,  g_whi);
    cudaGetSymbolAddress((void**)&wlo,  g_wlo);
    cudaGetSymbolAddress((void**)&xhi,  g_xhi);
    cudaGetSymbolAddress((void**)&xlo,  g_xlo);
    cudaGetSymbolAddress((void**)&aohi, g_aohi);
    cudaGetSymbolAddress((void**)&aolo, g_aolo);

    split_kernel<<<4096, 256>>>(x,  xhi, xlo, 1048576);
    split_kernel<<<1024, 256>>>(wq, whi + 0 * 1048576, wlo + 0 * 1048576, 262144);
    split_kernel<<<1024, 256>>>(wk, whi + 1 * 1048576, wlo + 1 * 1048576, 262144);
    split_kernel<<<1024, 256>>>(wv, whi + 2 * 1048576, wlo + 2 * 1048576, 262144);
    split_kernel<<<1024, 256>>>(wo, whi + 3 * 1048576, wlo + 3 * 1048576, 262144);

    gemm_mma_kernel<<<dim3(8, 32, 3), 256, GSMEM>>>(xhi, xlo, nullptr, 1);
    quantum_kernel<<<768, 256>>>(params);
    attention_mma_kernel<<<dim3(16, 32), 256, ASMEM>>>();

    float* ao;
    cudaGetSymbolAddress((void**)&ao, g_ao);
    split_kernel<<<4096, 256>>>(ao, aohi, aolo, 1048576);
    gemm_mma_kernel<<<dim3(8, 32, 1), 256, GSMEM>>>(aohi, aolo, out, 0);
}

// round 5
// speedup vs baseline: 2.3895x; 1.0160x over previous
#include <cuda_runtime.h>
#include <cuda_bf16.h>
#include <cstdint>

// ---------------------------------------------------------------------------
// QuantumAttention  (B=2, S=2048, E=1024, H=16, dk=64, NQ=4, NL=2)
// Round 5: GEMM mainloop rework — 3-stage cp.async ring (1 sync/chunk),
// paired ldmatrix.x4 for B, term-major MMA ordering. Attention as R4.
// ---------------------------------------------------------------------------

__device__ float g_q [2*16*2048*64];   // [b][h][s][d]
__device__ float g_k [2*16*2048*64];   // [b][h][s][d]
__device__ float g_v [2*16*2048*64];   // [b][h][d][s]   (transposed!)
__device__ float g_ao[2*2048*1024];    // [b][s][h*64+d]

__device__ __nv_bfloat16 g_xhi [4096*1024];
__device__ __nv_bfloat16 g_xlo [4096*1024];
__device__ __nv_bfloat16 g_whi [4*1024*1024];
__device__ __nv_bfloat16 g_wlo [4*1024*1024];
__device__ __nv_bfloat16 g_aohi[4096*1024];
__device__ __nv_bfloat16 g_aolo[4096*1024];

// ---------------- helpers ---------------------------------------------------
__device__ __forceinline__ uint32_t smem_u32(const void* p) {
    uint32_t a;
    asm("{ .reg .u64 t; cvta.to.shared.u64 t, %1; cvt.u32.u64 %0, t; }" : "=r"(a) : "l"(p));
    return a;
}
#define CP_ASYNC16(dst, src) \
    asm volatile("cp.async.cg.shared.global [%0], [%1], 16;" :: "r"(dst), "l"(src) : "memory")
#define CP_COMMIT() asm volatile("cp.async.commit_group;" ::: "memory")
#define CP_WAIT(n)  asm volatile("cp.async.wait_group %0;" :: "n"(n) : "memory")

__device__ __forceinline__ void ldmatrix_x4(uint32_t (&r)[4], uint32_t addr) {
    asm volatile("ldmatrix.sync.aligned.m8n8.x4.shared.b16 {%0,%1,%2,%3}, [%4];"
                 : "=r"(r[0]), "=r"(r[1]), "=r"(r[2]), "=r"(r[3]) : "r"(addr));
}
__device__ __forceinline__ void ldmatrix_x2(uint32_t (&r)[2], uint32_t addr) {
    asm volatile("ldmatrix.sync.aligned.m8n8.x2.shared.b16 {%0,%1}, [%2];"
                 : "=r"(r[0]), "=r"(r[1]) : "r"(addr));
}
__device__ __forceinline__ void mma_bf16(float (&d)[4], const uint32_t (&a)[4],
                                         const uint32_t (&b)[2]) {
    asm volatile("mma.sync.aligned.m16n8k16.row.col.f32.bf16.bf16.f32 "
                 "{%0,%1,%2,%3}, {%4,%5,%6,%7}, {%8,%9}, {%0,%1,%2,%3};"
                 : "+f"(d[0]), "+f"(d[1]), "+f"(d[2]), "+f"(d[3])
                 : "r"(a[0]), "r"(a[1]), "r"(a[2]), "r"(a[3]), "r"(b[0]), "r"(b[1]));
}
__device__ __forceinline__ uint32_t pack_bf16x2(float lo, float hi) {
    uint32_t r;
    asm("cvt.rn.bf16x2.f32 %0, %1, %2;" : "=r"(r) : "f"(hi), "f"(lo));
    return r;
}
__device__ __forceinline__ uint2 cvt4_hi(const float4 v) {
    return make_uint2(pack_bf16x2(v.x, v.y), pack_bf16x2(v.z, v.w));
}
__device__ __forceinline__ uint2 cvt4_lo(const float4 v, const uint2 hi) {
    __nv_bfloat162 h0 = *reinterpret_cast<const __nv_bfloat162*>(&hi.x);
    __nv_bfloat162 h1 = *reinterpret_cast<const __nv_bfloat162*>(&hi.y);
    float2 f0 = __bfloat1622float2(h0);
    float2 f1 = __bfloat1622float2(h1);
    return make_uint2(pack_bf16x2(v.x - f0.x, v.y - f0.y),
                      pack_bf16x2(v.z - f1.x, v.w - f1.y));
}
#define STS64(ad, v) \
    asm volatile("st.shared.v2.b32 [%0], {%1, %2};" :: "r"(ad), "r"((v).x), "r"((v).y) : "memory")

// ---------------------------------------------------------------------------
// fp32 -> (bf16 hi, bf16 lo) split
// ---------------------------------------------------------------------------
__global__ void split_kernel(const float* __restrict__ src,
                             __nv_bfloat16* __restrict__ hi,
                             __nv_bfloat16* __restrict__ lo, int n4)
{
    const int i = blockIdx.x * 256 + threadIdx.x;
    if (i >= n4) return;
    float4 v = ((const float4*)src)[i];
    uint2 ph = cvt4_hi(v);
    uint2 pl = cvt4_lo(v, ph);
    ((uint2*)hi)[i] = ph;
    ((uint2*)lo)[i] = pl;
}

// ---------------------------------------------------------------------------
// mma.sync GEMM:  C[m][n] = sum_k A[m][k] * B[n][k]
// CTA 128x128, K-chunk 32, 3-stage cp.async ring, bf16x3 split.
// ---------------------------------------------------------------------------
#define PITCH   40
#define PITCHB  (PITCH * 2)               // 80 bytes/row
#define MAT_B   (128 * PITCHB)            // 10240
#define STAGE_B (4 * MAT_B)               // 40960
#define NSTG    3
#define GSMEM   (NSTG * STAGE_B)          // 122880

__global__ __launch_bounds__(256, 1)
void gemm_mma_kernel(const __nv_bfloat16* __restrict__ Ahi,
                     const __nv_bfloat16* __restrict__ Alo,
                     float* __restrict__ Cout, int is_proj)
{
    extern __shared__ char smem[];
    const uint32_t sb = smem_u32(smem);
    const int tid  = threadIdx.x;
    const int wid  = tid >> 5;
    const int lane = tid & 31;

    const int z  = blockIdx.z;
    const int m0 = blockIdx.y * 128;
    const int n0 = blockIdx.x * 128;
    const size_t woff = ((size_t)(is_proj ? z : 3)) << 20;

    const int mat = tid >> 6;       // 0=Ahi 1=Alo 2=Bhi 3=Blo
    const int tt  = tid & 63;
    const __nv_bfloat16* gbase;
    {
        const __nv_bfloat16* srcs[4] = { Ahi + (size_t)m0 * 1024,
                                         Alo + (size_t)m0 * 1024,
                                         g_whi + woff + (size_t)n0 * 1024,
                                         g_wlo + woff + (size_t)n0 * 1024 };
        gbase = srcs[mat];
    }
    const uint32_t sdst0 = sb + (uint32_t)mat * MAT_B;

    const int wm = wid & 1;
    const int wn = wid >> 1;
    // A ldmatrix.x4: lanes 0-15 rows, lanes 16-31 rows at k+8
    const uint32_t a_addr0 = (uint32_t)(wm * 64 + (lane & 15)) * PITCHB
                           + (uint32_t)((lane >> 4) * 8) * 2;
    // B paired ldmatrix.x4: lanes 0-7 rows(t), 8-15 rows(t) k+8,
    //                       16-23 rows(t+1),   24-31 rows(t+1) k+8
    const uint32_t b_addr0 = (uint32_t)(wn * 32 + (lane & 7) + ((lane >> 4) << 3)) * PITCHB
                           + (uint32_t)(((lane >> 3) & 1) * 16);

    float acc[4][4][4];
#pragma unroll
    for (int i = 0; i < 4; i++)
#pragma unroll
        for (int t = 0; t < 4; t++)
#pragma unroll
            for (int f = 0; f < 4; f++) acc[i][t][f] = 0.f;

    auto load_stage = [&](int ch, int stg) {
        const int k0 = ch * 32;
        const uint32_t dst = sdst0 + (uint32_t)stg * STAGE_B;
#pragma unroll
        for (int j = 0; j < 8; j++) {
            const int idx = tt * 8 + j;
            const int row = idx >> 2;
            const int c16 = idx & 3;
            CP_ASYNC16(dst + (uint32_t)row * PITCHB + (uint32_t)c16 * 16,
                       gbase + (size_t)row * 1024 + k0 + c16 * 8);
        }
        CP_COMMIT();
    };

    load_stage(0, 0);
    load_stage(1, 1);

    for (int ch = 0; ch < 32; ch++) {
        CP_WAIT(1);
        __syncthreads();
        if (ch + 2 < 32) load_stage(ch + 2, (ch + 2) % NSTG);

        const uint32_t stg = sb + (uint32_t)(ch % NSTG) * STAGE_B;
#pragma unroll
        for (int ks = 0; ks < 2; ks++) {
            const uint32_t kb = (uint32_t)(ks * 32);   // 16 elems = 32 bytes
            uint32_t ah[4][4], al[4][4];
#pragma unroll
            for (int i = 0; i < 4; i++) {
                const uint32_t ro = (uint32_t)(i * 16) * PITCHB;
                ldmatrix_x4(ah[i], stg + 0 * MAT_B + a_addr0 + ro + kb);
                ldmatrix_x4(al[i], stg + 1 * MAT_B + a_addr0 + ro + kb);
            }
            uint32_t bh[4][2], bl[4][2];
#pragma unroll
            for (int p = 0; p < 2; p++) {
                const uint32_t ro = (uint32_t)(p * 16) * PITCHB;
                uint32_t t4[4];
                ldmatrix_x4(t4, stg + 2 * MAT_B + b_addr0 + ro + kb);
                bh[2 * p][0] = t4[0]; bh[2 * p][1] = t4[1];
                bh[2 * p + 1][0] = t4[2]; bh[2 * p + 1][1] = t4[3];
                ldmatrix_x4(t4, stg + 3 * MAT_B + b_addr0 + ro + kb);
                bl[2 * p][0] = t4[0]; bl[2 * p][1] = t4[1];
                bl[2 * p + 1][0] = t4[2]; bl[2 * p + 1][1] = t4[3];
            }
            // term-major: 16 independent accumulator chains per pass
#pragma unroll
            for (int i = 0; i < 4; i++)
#pragma unroll
                for (int t = 0; t < 4; t++) mma_bf16(acc[i][t], ah[i], bh[t]);
#pragma unroll
            for (int i = 0; i < 4; i++)
#pragma unroll
                for (int t = 0; t < 4; t++) mma_bf16(acc[i][t], ah[i], bl[t]);
#pragma unroll
            for (int i = 0; i < 4; i++)
#pragma unroll
                for (int t = 0; t < 4; t++) mma_bf16(acc[i][t], al[i], bh[t]);
        }
    }

    const int r_in = lane >> 2;
    const int c_in = (lane & 3) * 2;
#pragma unroll
    for (int i = 0; i < 4; i++) {
#pragma unroll
        for (int half = 0; half < 2; half++) {
            const int m = m0 + wm * 64 + i * 16 + r_in + half * 8;
            const int b = m >> 11, s = m & 2047;
#pragma unroll
            for (int t = 0; t < 4; t++) {
                const int n = n0 + wn * 32 + t * 8 + c_in;
                const float v0 = acc[i][t][half * 2], v1 = acc[i][t][half * 2 + 1];
                if (is_proj) {
                    const int h = n >> 6, d = n & 63;
                    if (z == 2) {   // V: transposed [b][h][d][s]
                        float* dst = g_v + ((size_t)(((b << 4) + h) << 6) + d) * 2048 + s;
                        dst[0] = v0; dst[2048] = v1;
                    } else {
                        float* O = (z == 0) ? g_q : g_k;
                        *(float2*)(O + (((size_t)((b << 4) + h) * 2048 + s) << 6) + d)
                            = make_float2(v0, v1);
                    }
                } else {
                    *(float2*)(Cout + (size_t)m * 1024 + n) = make_float2(v0, v1);
                }
            }
        }
    }
}

// ---------------------------------------------------------------------------
// Quantum block (V uses transposed layout: stride 2048 between wires)
// ---------------------------------------------------------------------------
__global__ void quantum_kernel(const float* __restrict__ params)
{
    const int id = blockIdx.x * 256 + threadIdx.x;
    if (id >= 3 * 65536) return;
    const int tensor = id >> 16;
    const int idx = id & 65535;
    float* vec;
    int stride;
    if (tensor == 0)      { vec = g_q + (size_t)idx * 64; stride = 1; }
    else if (tensor == 1) { vec = g_k + (size_t)idx * 64; stride = 1; }
    else {
        const int bh = idx >> 11, s = idx & 2047;
        vec = g_v + ((size_t)bh << 6) * 2048 + s; stride = 2048;
    }

    float ax[4];
#pragma unroll
    for (int w = 0; w < 4; w++) ax[w] = vec[w * stride];

    float sr[16], si[16];
#pragma unroll
    for (int i = 0; i < 16; i++) { sr[i] = 0.f; si[i] = 0.f; }
    sr[0] = 1.f;

#pragma unroll
    for (int w = 0; w < 4; w++) {
        const float a = 0.5f * ax[w];
        float s, c;
        sincosf(a, &s, &c);
        const int st = 8 >> w;
#pragma unroll
        for (int i = 0; i < 16; i++) {
            if (i & st) continue;
            const int j = i + st;
            const float xr = sr[i], xi = si[i], yr = sr[j], yi = si[j];
            sr[i] = c * xr + s * yi;  si[i] = c * xi - s * yr;
            sr[j] = c * yr + s * xi;  si[j] = c * yi - s * xr;
        }
    }
#pragma unroll
    for (int l = 0; l < 2; l++) {
#pragma unroll
        for (int w = 0; w < 4; w++) {
            const float phi = params[l * 12 + w * 3 + 0];
            const float th  = params[l * 12 + w * 3 + 1];
            const float om  = params[l * 12 + w * 3 + 2];
            float stt, ct;  sincosf(0.5f * th, &stt, &ct);
            float sap, cap; sincosf(0.5f * (phi + om), &sap, &cap);
            float sam, cam; sincosf(0.5f * (phi - om), &sam, &cam);
            const float m00r =  cap * ct,  m00i = -sap * ct;
            const float m01r = -cam * stt, m01i = -sam * stt;
            const float m10r =  cam * stt, m10i = -sam * stt;
            const float m11r =  cap * ct,  m11i =  sap * ct;
            const int st = 8 >> w;
#pragma unroll
            for (int i = 0; i < 16; i++) {
                if (i & st) continue;
                const int j = i + st;
                const float xr = sr[i], xi = si[i], yr = sr[j], yi = si[j];
                sr[i] = m00r * xr - m00i * xi + m01r * yr - m01i * yi;
                si[i] = m00r * xi + m00i * xr + m01r * yi + m01i * yr;
                sr[j] = m10r * xr - m10i * xi + m11r * yr - m11i * yi;
                si[j] = m10r * xi + m10i * xr + m11r * yi + m11i * yr;
            }
        }
#pragma unroll
        for (int r = 0; r < 4; r++) {
            float tr = sr[8 + r], ti = si[8 + r];
            sr[8 + r] = sr[12 + r];  si[8 + r] = si[12 + r];
            sr[12 + r] = tr;         si[12 + r] = ti;
        }
    }
    float ev[4] = {0.f, 0.f, 0.f, 0.f};
#pragma unroll
    for (int i = 0; i < 16; i++) {
        const float pr = sr[i] * sr[i] + si[i] * si[i];
#pragma unroll
        for (int w = 0; w < 4; w++)
            ev[w] += ((i >> (3 - w)) & 1) ? -pr : pr;
    }
#pragma unroll
    for (int w = 0; w < 4; w++) vec[w * stride] = ev[w];
}

// ---------------------------------------------------------------------------
// FA2-style attention on mma.sync bf16 (split x3 both phases). (as R4)
// ---------------------------------------------------------------------------
#define AP      72
#define APB     (AP * 2)
#define KHI_O   0
#define KLO_O   (64 * APB)
#define VHI_O   (2 * 64 * APB)
#define VLO_O   (3 * 64 * APB)
#define ABUF_B  (4 * 64 * APB)
#define ASMEM   (2 * ABUF_B)

__global__ __launch_bounds__(256, 1)
void attention_mma_kernel()
{
    extern __shared__ char smem[];
    const uint32_t sb = smem_u32(smem);
    const int tid  = threadIdx.x;
    const int wid  = tid >> 5;
    const int lane = tid & 31;

    const int bh = blockIdx.y;
    const int q0 = blockIdx.x * 128;

    const float* qb = g_q + (size_t)bh * 2048 * 64;
    const float* kb = g_k + (size_t)bh * 2048 * 64;
    const float* vb = g_v + (size_t)bh * 64 * 2048;

    {
#pragma unroll
        for (int j = 0; j < 8; j++) {
            const int idx = j * 256 + tid;
            const int r = idx >> 4, c4 = idx & 15;
            float4 v = *(const float4*)(qb + (size_t)(q0 + r) * 64 + c4 * 4);
            uint2 h = cvt4_hi(v);
            uint2 l = cvt4_lo(v, h);
            const uint32_t ad = sb + (uint32_t)r * APB + (uint32_t)c4 * 8;
            STS64(ad, h);
            STS64(ad + 18432, l);
        }
    }
    __syncthreads();

    uint32_t qh[4][4], ql[4][4];
    {
        const uint32_t a0 = sb + (uint32_t)(wid * 16 + (lane & 15)) * APB
                          + (uint32_t)((lane >> 4) * 8) * 2;
#pragma unroll
        for (int j = 0; j < 4; j++) {
            ldmatrix_x4(qh[j], a0 + (uint32_t)(j * 16) * 2);
            ldmatrix_x4(ql[j], a0 + 18432 + (uint32_t)(j * 16) * 2);
        }
    }
    __syncthreads();

    float m0r = -1e30f, m1r = -1e30f, l0 = 0.f, l1 = 0.f;
    float o[8][4];
#pragma unroll
    for (int t = 0; t < 8; t++)
#pragma unroll
        for (int f = 0; f < 4; f++) o[t][f] = 0.f;

    const uint32_t brow = (uint32_t)(lane & 7) * APB + (uint32_t)(((lane >> 3) & 1) * 8) * 2;

    float4 pf[8];
    auto load_tile = [&](int kt) {
#pragma unroll
        for (int j = 0; j < 4; j++) {
            const int idx = j * 256 + tid;
            const int key = idx >> 4, c4 = idx & 15;
            pf[j] = *(const float4*)(kb + (size_t)(kt + key) * 64 + c4 * 4);
        }
#pragma unroll
        for (int j = 0; j < 4; j++) {
            const int idx = j * 256 + tid;
            const int d = idx >> 4, c4 = idx & 15;
            pf[4 + j] = *(const float4*)(vb + (size_t)d * 2048 + kt + c4 * 4);
        }
    };
    auto store_tile = [&](int buf) {
        const uint32_t bp = sb + (uint32_t)buf * ABUF_B;
#pragma unroll
        for (int j = 0; j < 4; j++) {
            const int idx = j * 256 + tid;
            const int key = idx >> 4, c4 = idx & 15;
            uint2 h = cvt4_hi(pf[j]);
            uint2 l = cvt4_lo(pf[j], h);
            const uint32_t ad = bp + (uint32_t)key * APB + (uint32_t)c4 * 8;
            STS64(ad + KHI_O, h);
            STS64(ad + KLO_O, l);
        }
#pragma unroll
        for (int j = 0; j < 4; j++) {
            const int idx = j * 256 + tid;
            const int d = idx >> 4, c4 = idx & 15;
            uint2 h = cvt4_hi(pf[4 + j]);
            uint2 l = cvt4_lo(pf[4 + j], h);
            const uint32_t ad = bp + (uint32_t)d * APB + (uint32_t)c4 * 8;
            STS64(ad + VHI_O, h);
            STS64(ad + VLO_O, l);
        }
    };

    load_tile(0);
    store_tile(0);
    __syncthreads();

    for (int kt = 0; kt < 32; kt++) {
        const int buf = kt & 1;
        if (kt < 31) load_tile((kt + 1) * 64);

        const uint32_t bp = sb + (uint32_t)buf * ABUF_B;

        float s[8][4];
#pragma unroll
        for (int n = 0; n < 8; n++)
#pragma unroll
            for (int f = 0; f < 4; f++) s[n][f] = 0.f;

#pragma unroll
        for (int j = 0; j < 4; j++) {
            const uint32_t kb2 = (uint32_t)(j * 16) * 2;
            uint32_t kh[8][2], kl[8][2];
#pragma unroll
            for (int n = 0; n < 8; n++) {
                const uint32_t ro = (uint32_t)(n * 8) * APB;
                ldmatrix_x2(kh[n], bp + KHI_O + brow + ro + kb2);
                ldmatrix_x2(kl[n], bp + KLO_O + brow + ro + kb2);
            }
#pragma unroll
            for (int n = 0; n < 8; n++) mma_bf16(s[n], qh[j], kh[n]);
#pragma unroll
            for (int n = 0; n < 8; n++) mma_bf16(s[n], qh[j], kl[n]);
#pragma unroll
            for (int n = 0; n < 8; n++) mma_bf16(s[n], ql[j], kh[n]);
        }

        float tm0 = -1e30f, tm1 = -1e30f;
#pragma unroll
        for (int n = 0; n < 8; n++) {
#pragma unroll
            for (int f = 0; f < 4; f++) s[n][f] *= 0.125f;
            tm0 = fmaxf(tm0, fmaxf(s[n][0], s[n][1]));
            tm1 = fmaxf(tm1, fmaxf(s[n][2], s[n][3]));
        }
        tm0 = fmaxf(tm0, __shfl_xor_sync(0xffffffffu, tm0, 1));
        tm0 = fmaxf(tm0, __shfl_xor_sync(0xffffffffu, tm0, 2));
        tm1 = fmaxf(tm1, __shfl_xor_sync(0xffffffffu, tm1, 1));
        tm1 = fmaxf(tm1, __shfl_xor_sync(0xffffffffu, tm1, 2));
        const float mn0 = fmaxf(m0r, tm0), mn1 = fmaxf(m1r, tm1);
        const float a0 = __expf(m0r - mn0), a1 = __expf(m1r - mn1);
        m0r = mn0; m1r = mn1;

        float rs0 = 0.f, rs1 = 0.f;
#pragma unroll
        for (int n = 0; n < 8; n++) {
            s[n][0] = __expf(s[n][0] - mn0);
            s[n][1] = __expf(s[n][1] - mn0);
            s[n][2] = __expf(s[n][2] - mn1);
            s[n][3] = __expf(s[n][3] - mn1);
            rs0 += s[n][0] + s[n][1];
            rs1 += s[n][2] + s[n][3];
        }
        rs0 += __shfl_xor_sync(0xffffffffu, rs0, 1);
        rs0 += __shfl_xor_sync(0xffffffffu, rs0, 2);
        rs1 += __shfl_xor_sync(0xffffffffu, rs1, 1);
        rs1 += __shfl_xor_sync(0xffffffffu, rs1, 2);
        l0 = l0 * a0 + rs0;
        l1 = l1 * a1 + rs1;

#pragma unroll
        for (int t = 0; t < 8; t++) {
            o[t][0] *= a0; o[t][1] *= a0; o[t][2] *= a1; o[t][3] *= a1;
        }

#pragma unroll
        for (int j = 0; j < 4; j++) {
            uint32_t ph[4], pl[4];
            ph[0] = pack_bf16x2(s[2 * j][0],     s[2 * j][1]);
            ph[1] = pack_bf16x2(s[2 * j][2],     s[2 * j][3]);
            ph[2] = pack_bf16x2(s[2 * j + 1][0], s[2 * j + 1][1]);
            ph[3] = pack_bf16x2(s[2 * j + 1][2], s[2 * j + 1][3]);
            {
                __nv_bfloat162 b0 = *reinterpret_cast<__nv_bfloat162*>(&ph[0]);
                __nv_bfloat162 b1 = *reinterpret_cast<__nv_bfloat162*>(&ph[1]);
                __nv_bfloat162 b2 = *reinterpret_cast<__nv_bfloat162*>(&ph[2]);
                __nv_bfloat162 b3 = *reinterpret_cast<__nv_bfloat162*>(&ph[3]);
                float2 f0 = __bfloat1622float2(b0), f1 = __bfloat1622float2(b1);
                float2 f2 = __bfloat1622float2(b2), f3 = __bfloat1622float2(b3);
                pl[0] = pack_bf16x2(s[2 * j][0] - f0.x,     s[2 * j][1] - f0.y);
                pl[1] = pack_bf16x2(s[2 * j][2] - f1.x,     s[2 * j][3] - f1.y);
                pl[2] = pack_bf16x2(s[2 * j + 1][0] - f2.x, s[2 * j + 1][1] - f2.y);
                pl[3] = pack_bf16x2(s[2 * j + 1][2] - f3.x, s[2 * j + 1][3] - f3.y);
            }
            const uint32_t kb2 = (uint32_t)(j * 16) * 2;
#pragma unroll
            for (int t = 0; t < 8; t++) {
                const uint32_t ro = (uint32_t)(t * 8) * APB;
                uint32_t vh[2], vl[2];
                ldmatrix_x2(vh, bp + VHI_O + brow + ro + kb2);
                ldmatrix_x2(vl, bp + VLO_O + brow + ro + kb2);
                mma_bf16(o[t], ph, vh);
                mma_bf16(o[t], ph, vl);
                mma_bf16(o[t], pl, vh);
            }
        }

        if (kt < 31) {
            store_tile(buf ^ 1);
            __syncthreads();
        }
    }

    const int b = bh >> 4, h = bh & 15;
    const int r0 = q0 + wid * 16 + (lane >> 2);
    const int c0 = h * 64 + (lane & 3) * 2;
    const float il0 = 1.f / l0, il1 = 1.f / l1;
#pragma unroll
    for (int t = 0; t < 8; t++) {
        float* base0 = g_ao + (size_t)(b * 2048 + r0) * 1024 + c0 + t * 8;
        float* base1 = g_ao + (size_t)(b * 2048 + r0 + 8) * 1024 + c0 + t * 8;
        *(float2*)base0 = make_float2(o[t][0] * il0, o[t][1] * il0);
        *(float2*)base1 = make_float2(o[t][2] * il1, o[t][3] * il1);
    }
}

// ---------------------------------------------------------------------------
extern "C" void kernel_launch(void* const* d_in, const int* in_sizes, int n_in,
                              void* d_out, int out_size)
{
    const float* x      = (const float*)d_in[0];
    const float* params = (const float*)d_in[1];
    const float* wq     = (const float*)d_in[2];
    const float* wk     = (const float*)d_in[3];
    const float* wv     = (const float*)d_in[4];
    const float* wo     = (const float*)d_in[5];
    float* out = (float*)d_out;

    cudaFuncSetAttribute(gemm_mma_kernel,
                         cudaFuncAttributeMaxDynamicSharedMemorySize, GSMEM);
    cudaFuncSetAttribute(attention_mma_kernel,
                         cudaFuncAttributeMaxDynamicSharedMemorySize, ASMEM);

    __nv_bfloat16 *whi, *wlo, *xhi, *xlo, *aohi, *aolo;
    cudaGetSymbolAddress((void**)&whi,  g_whi);
    cudaGetSymbolAddress((void**)&wlo,  g_wlo);
    cudaGetSymbolAddress((void**)&xhi,  g_xhi);
    cudaGetSymbolAddress((void**)&xlo,  g_xlo);
    cudaGetSymbolAddress((void**)&aohi, g_aohi);
    cudaGetSymbolAddress((void**)&aolo, g_aolo);

    split_kernel<<<4096, 256>>>(x,  xhi, xlo, 1048576);
    split_kernel<<<1024, 256>>>(wq, whi + 0 * 1048576, wlo + 0 * 1048576, 262144);
    split_kernel<<<1024, 256>>>(wk, whi + 1 * 1048576, wlo + 1 * 1048576, 262144);
    split_kernel<<<1024, 256>>>(wv, whi + 2 * 1048576, wlo + 2 * 1048576, 262144);
    split_kernel<<<1024, 256>>>(wo, whi + 3 * 1048576, wlo + 3 * 1048576, 262144);

    gemm_mma_kernel<<<dim3(8, 32, 3), 256, GSMEM>>>(xhi, xlo, nullptr, 1);
    quantum_kernel<<<768, 256>>>(params);
    attention_mma_kernel<<<dim3(16, 32), 256, ASMEM>>>();

    float* ao;
    cudaGetSymbolAddress((void**)&ao, g_ao);
    split_kernel<<<4096, 256>>>(ao, aohi, aolo, 1048576);
    gemm_mma_kernel<<<dim3(8, 32, 1), 256, GSMEM>>>(aohi, aolo, out, 0);
}

// round 6
// speedup vs baseline: 3.7939x; 1.5878x over previous
#include <cuda_runtime.h>
#include <cuda_fp16.h>
#include <cstdint>

// ---------------------------------------------------------------------------
// QuantumAttention  (B=2, S=2048, E=1024, H=16, dk=64, NQ=4, NL=2)
// Round 6: fp16 2-term splits (A split, B single) for GEMMs and PV;
// 3-term fp16 for scores. Legacy HMMA pipe is the bound -> cut FLOPs.
// ---------------------------------------------------------------------------

__device__ float g_q [2*16*2048*64];   // [b][h][s][d]
__device__ float g_k [2*16*2048*64];   // [b][h][s][d]
__device__ float g_v [2*16*2048*64];   // [b][h][d][s]   (transposed!)
__device__ float g_ao[2*2048*1024];    // [b][s][h*64+d]

__device__ __half g_xhi [4096*1024];
__device__ __half g_xlo [4096*1024];
__device__ __half g_wh  [4*1024*1024];   // q,k,v,o packed, single-rounded
__device__ __half g_aohi[4096*1024];
__device__ __half g_aolo[4096*1024];

// ---------------- helpers ---------------------------------------------------
__device__ __forceinline__ uint32_t smem_u32(const void* p) {
    uint32_t a;
    asm("{ .reg .u64 t; cvta.to.shared.u64 t, %1; cvt.u32.u64 %0, t; }" : "=r"(a) : "l"(p));
    return a;
}
#define CP_ASYNC16(dst, src) \
    asm volatile("cp.async.cg.shared.global [%0], [%1], 16;" :: "r"(dst), "l"(src) : "memory")
#define CP_COMMIT() asm volatile("cp.async.commit_group;" ::: "memory")
#define CP_WAIT(n)  asm volatile("cp.async.wait_group %0;" :: "n"(n) : "memory")

__device__ __forceinline__ void ldmatrix_x4(uint32_t (&r)[4], uint32_t addr) {
    asm volatile("ldmatrix.sync.aligned.m8n8.x4.shared.b16 {%0,%1,%2,%3}, [%4];"
                 : "=r"(r[0]), "=r"(r[1]), "=r"(r[2]), "=r"(r[3]) : "r"(addr));
}
__device__ __forceinline__ void ldmatrix_x2(uint32_t (&r)[2], uint32_t addr) {
    asm volatile("ldmatrix.sync.aligned.m8n8.x2.shared.b16 {%0,%1}, [%2];"
                 : "=r"(r[0]), "=r"(r[1]) : "r"(addr));
}
__device__ __forceinline__ void mma_f16(float (&d)[4], const uint32_t (&a)[4],
                                        const uint32_t (&b)[2]) {
    asm volatile("mma.sync.aligned.m16n8k16.row.col.f32.f16.f16.f32 "
                 "{%0,%1,%2,%3}, {%4,%5,%6,%7}, {%8,%9}, {%0,%1,%2,%3};"
                 : "+f"(d[0]), "+f"(d[1]), "+f"(d[2]), "+f"(d[3])
                 : "r"(a[0]), "r"(a[1]), "r"(a[2]), "r"(a[3]), "r"(b[0]), "r"(b[1]));
}
// pack two fp32 -> f16x2 register (first arg -> bits 0-15)
__device__ __forceinline__ uint32_t pack_f16x2(float lo, float hi) {
    uint32_t r;
    asm("cvt.rn.f16x2.f32 %0, %1, %2;" : "=r"(r) : "f"(hi), "f"(lo));
    return r;
}
__device__ __forceinline__ uint2 cvt4_hi(const float4 v) {
    return make_uint2(pack_f16x2(v.x, v.y), pack_f16x2(v.z, v.w));
}
__device__ __forceinline__ uint2 cvt4_lo(const float4 v, const uint2 hi) {
    __half2 h0 = *reinterpret_cast<const __half2*>(&hi.x);
    __half2 h1 = *reinterpret_cast<const __half2*>(&hi.y);
    float2 f0 = __half22float2(h0);
    float2 f1 = __half22float2(h1);
    return make_uint2(pack_f16x2(v.x - f0.x, v.y - f0.y),
                      pack_f16x2(v.z - f1.x, v.w - f1.y));
}
#define STS64(ad, v) \
    asm volatile("st.shared.v2.b32 [%0], {%1, %2};" :: "r"(ad), "r"((v).x), "r"((v).y) : "memory")

// ---------------------------------------------------------------------------
// fp32 -> (f16 hi, f16 lo) split  |  fp32 -> f16 single
// ---------------------------------------------------------------------------
__global__ void split2_kernel(const float* __restrict__ src,
                              __half* __restrict__ hi,
                              __half* __restrict__ lo, int n4)
{
    const int i = blockIdx.x * 256 + threadIdx.x;
    if (i >= n4) return;
    float4 v = ((const float4*)src)[i];
    uint2 ph = cvt4_hi(v);
    uint2 pl = cvt4_lo(v, ph);
    ((uint2*)hi)[i] = ph;
    ((uint2*)lo)[i] = pl;
}
__global__ void cvt1_kernel(const float* __restrict__ src,
                            __half* __restrict__ dst, int n4)
{
    const int i = blockIdx.x * 256 + threadIdx.x;
    if (i >= n4) return;
    float4 v = ((const float4*)src)[i];
    ((uint2*)dst)[i] = cvt4_hi(v);
}

// ---------------------------------------------------------------------------
// mma.sync GEMM:  C[m][n] = sum_k A[m][k] * B[n][k]
// CTA 128x128, K-chunk 32, 3-stage ring, fp16 2-term (Ahi,Alo split; B single).
// ---------------------------------------------------------------------------
#define PITCH   40
#define PITCHB  (PITCH * 2)               // 80 bytes/row
#define MAT_B   (128 * PITCHB)            // 10240
#define STAGE_B (3 * MAT_B)               // 30720  (Ahi, Alo, B)
#define NSTG    3
#define GSMEM   (NSTG * STAGE_B)          // 92160

__global__ __launch_bounds__(256, 2)
void gemm_mma_kernel(const __half* __restrict__ Ahi,
                     const __half* __restrict__ Alo,
                     float* __restrict__ Cout, int is_proj)
{
    extern __shared__ char smem[];
    const uint32_t sb = smem_u32(smem);
    const int tid  = threadIdx.x;
    const int wid  = tid >> 5;
    const int lane = tid & 31;

    const int z  = blockIdx.z;
    const int m0 = blockIdx.y * 128;
    const int n0 = blockIdx.x * 128;
    const size_t woff = ((size_t)(is_proj ? z : 3)) << 20;

    const __half* gsrc[3] = { Ahi + (size_t)m0 * 1024,
                              Alo + (size_t)m0 * 1024,
                              g_wh + woff + (size_t)n0 * 1024 };

    const int wm = wid & 1;
    const int wn = wid >> 1;
    const uint32_t a_addr0 = (uint32_t)(wm * 64 + (lane & 15)) * PITCHB
                           + (uint32_t)((lane >> 4) * 8) * 2;
    // paired x4 B: lanes 0-7 t, 8-15 t k+8, 16-23 t+1, 24-31 t+1 k+8
    const uint32_t b_addr0 = (uint32_t)(wn * 32 + (lane & 7) + ((lane >> 4) << 3)) * PITCHB
                           + (uint32_t)(((lane >> 3) & 1) * 16);

    float acc[4][4][4];
#pragma unroll
    for (int i = 0; i < 4; i++)
#pragma unroll
        for (int t = 0; t < 4; t++)
#pragma unroll
            for (int f = 0; f < 4; f++) acc[i][t][f] = 0.f;

    auto load_stage = [&](int ch, int stg) {
        const int k0 = ch * 32;
        const uint32_t dst = sb + (uint32_t)stg * STAGE_B;
#pragma unroll
        for (int j = 0; j < 6; j++) {
            const int idx = j * 256 + tid;          // 0..1535
            const int mat = idx >> 9;               // 0..2
            const int w   = idx & 511;
            const int row = w >> 2;
            const int c16 = w & 3;
            CP_ASYNC16(dst + (uint32_t)mat * MAT_B + (uint32_t)row * PITCHB
                           + (uint32_t)c16 * 16,
                       gsrc[mat] + (size_t)row * 1024 + k0 + c16 * 8);
        }
        CP_COMMIT();
    };

    load_stage(0, 0);
    load_stage(1, 1);

    for (int ch = 0; ch < 32; ch++) {
        CP_WAIT(1);
        __syncthreads();
        if (ch + 2 < 32) load_stage(ch + 2, (ch + 2) % NSTG);

        const uint32_t stg = sb + (uint32_t)(ch % NSTG) * STAGE_B;
#pragma unroll
        for (int ks = 0; ks < 2; ks++) {
            const uint32_t kb = (uint32_t)(ks * 32);
            uint32_t ah[4][4], al[4][4];
#pragma unroll
            for (int i = 0; i < 4; i++) {
                const uint32_t ro = (uint32_t)(i * 16) * PITCHB;
                ldmatrix_x4(ah[i], stg + 0 * MAT_B + a_addr0 + ro + kb);
                ldmatrix_x4(al[i], stg + 1 * MAT_B + a_addr0 + ro + kb);
            }
            uint32_t bh[4][2];
#pragma unroll
            for (int p = 0; p < 2; p++) {
                const uint32_t ro = (uint32_t)(p * 16) * PITCHB;
                uint32_t t4[4];
                ldmatrix_x4(t4, stg + 2 * MAT_B + b_addr0 + ro + kb);
                bh[2 * p][0] = t4[0];     bh[2 * p][1] = t4[1];
                bh[2 * p + 1][0] = t4[2]; bh[2 * p + 1][1] = t4[3];
            }
#pragma unroll
            for (int i = 0; i < 4; i++)
#pragma unroll
                for (int t = 0; t < 4; t++) mma_f16(acc[i][t], ah[i], bh[t]);
#pragma unroll
            for (int i = 0; i < 4; i++)
#pragma unroll
                for (int t = 0; t < 4; t++) mma_f16(acc[i][t], al[i], bh[t]);
        }
    }

    const int r_in = lane >> 2;
    const int c_in = (lane & 3) * 2;
#pragma unroll
    for (int i = 0; i < 4; i++) {
#pragma unroll
        for (int half = 0; half < 2; half++) {
            const int m = m0 + wm * 64 + i * 16 + r_in + half * 8;
            const int b = m >> 11, s = m & 2047;
#pragma unroll
            for (int t = 0; t < 4; t++) {
                const int n = n0 + wn * 32 + t * 8 + c_in;
                const float v0 = acc[i][t][half * 2], v1 = acc[i][t][half * 2 + 1];
                if (is_proj) {
                    const int h = n >> 6, d = n & 63;
                    if (z == 2) {   // V transposed [b][h][d][s]
                        float* dst = g_v + ((size_t)(((b << 4) + h) << 6) + d) * 2048 + s;
                        dst[0] = v0; dst[2048] = v1;
                    } else {
                        float* O = (z == 0) ? g_q : g_k;
                        *(float2*)(O + (((size_t)((b << 4) + h) * 2048 + s) << 6) + d)
                            = make_float2(v0, v1);
                    }
                } else {
                    *(float2*)(Cout + (size_t)m * 1024 + n) = make_float2(v0, v1);
                }
            }
        }
    }
}

// ---------------------------------------------------------------------------
// Quantum block (V transposed: stride 2048 between wires)
// ---------------------------------------------------------------------------
__global__ void quantum_kernel(const float* __restrict__ params)
{
    const int id = blockIdx.x * 256 + threadIdx.x;
    if (id >= 3 * 65536) return;
    const int tensor = id >> 16;
    const int idx = id & 65535;
    float* vec;
    int stride;
    if (tensor == 0)      { vec = g_q + (size_t)idx * 64; stride = 1; }
    else if (tensor == 1) { vec = g_k + (size_t)idx * 64; stride = 1; }
    else {
        const int bh = idx >> 11, s = idx & 2047;
        vec = g_v + ((size_t)bh << 6) * 2048 + s; stride = 2048;
    }

    float ax[4];
#pragma unroll
    for (int w = 0; w < 4; w++) ax[w] = vec[w * stride];

    float sr[16], si[16];
#pragma unroll
    for (int i = 0; i < 16; i++) { sr[i] = 0.f; si[i] = 0.f; }
    sr[0] = 1.f;

#pragma unroll
    for (int w = 0; w < 4; w++) {
        const float a = 0.5f * ax[w];
        float s, c;
        sincosf(a, &s, &c);
        const int st = 8 >> w;
#pragma unroll
        for (int i = 0; i < 16; i++) {
            if (i & st) continue;
            const int j = i + st;
            const float xr = sr[i], xi = si[i], yr = sr[j], yi = si[j];
            sr[i] = c * xr + s * yi;  si[i] = c * xi - s * yr;
            sr[j] = c * yr + s * xi;  si[j] = c * yi - s * xr;
        }
    }
#pragma unroll
    for (int l = 0; l < 2; l++) {
#pragma unroll
        for (int w = 0; w < 4; w++) {
            const float phi = params[l * 12 + w * 3 + 0];
            const float th  = params[l * 12 + w * 3 + 1];
            const float om  = params[l * 12 + w * 3 + 2];
            float stt, ct;  sincosf(0.5f * th, &stt, &ct);
            float sap, cap; sincosf(0.5f * (phi + om), &sap, &cap);
            float sam, cam; sincosf(0.5f * (phi - om), &sam, &cam);
            const float m00r =  cap * ct,  m00i = -sap * ct;
            const float m01r = -cam * stt, m01i = -sam * stt;
            const float m10r =  cam * stt, m10i = -sam * stt;
            const float m11r =  cap * ct,  m11i =  sap * ct;
            const int st = 8 >> w;
#pragma unroll
            for (int i = 0; i < 16; i++) {
                if (i & st) continue;
                const int j = i + st;
                const float xr = sr[i], xi = si[i], yr = sr[j], yi = si[j];
                sr[i] = m00r * xr - m00i * xi + m01r * yr - m01i * yi;
                si[i] = m00r * xi + m00i * xr + m01r * yi + m01i * yr;
                sr[j] = m10r * xr - m10i * xi + m11r * yr - m11i * yi;
                si[j] = m10r * xi + m10i * xr + m11r * yi + m11i * yr;
            }
        }
#pragma unroll
        for (int r = 0; r < 4; r++) {
            float tr = sr[8 + r], ti = si[8 + r];
            sr[8 + r] = sr[12 + r];  si[8 + r] = si[12 + r];
            sr[12 + r] = tr;         si[12 + r] = ti;
        }
    }
    float ev[4] = {0.f, 0.f, 0.f, 0.f};
#pragma unroll
    for (int i = 0; i < 16; i++) {
        const float pr = sr[i] * sr[i] + si[i] * si[i];
#pragma unroll
        for (int w = 0; w < 4; w++)
            ev[w] += ((i >> (3 - w)) & 1) ? -pr : pr;
    }
#pragma unroll
    for (int w = 0; w < 4; w++) vec[w * stride] = ev[w];
}

// ---------------------------------------------------------------------------
// FA2 attention, fp16: scores 3-term (Q split x K split), PV 2-term
// (P single x V split). Grid: (16, 32), 256 threads.
// ---------------------------------------------------------------------------
#define AP      72
#define APB     (AP * 2)
#define KHI_O   0
#define KLO_O   (64 * APB)
#define VHI_O   (2 * 64 * APB)
#define VLO_O   (3 * 64 * APB)
#define ABUF_B  (4 * 64 * APB)
#define ASMEM   (2 * ABUF_B)

__global__ __launch_bounds__(256, 1)
void attention_mma_kernel()
{
    extern __shared__ char smem[];
    const uint32_t sb = smem_u32(smem);
    const int tid  = threadIdx.x;
    const int wid  = tid >> 5;
    const int lane = tid & 31;

    const int bh = blockIdx.y;
    const int q0 = blockIdx.x * 128;

    const float* qb = g_q + (size_t)bh * 2048 * 64;
    const float* kb = g_k + (size_t)bh * 2048 * 64;
    const float* vb = g_v + (size_t)bh * 64 * 2048;

    {
#pragma unroll
        for (int j = 0; j < 8; j++) {
            const int idx = j * 256 + tid;
            const int r = idx >> 4, c4 = idx & 15;
            float4 v = *(const float4*)(qb + (size_t)(q0 + r) * 64 + c4 * 4);
            uint2 h = cvt4_hi(v);
            uint2 l = cvt4_lo(v, h);
            const uint32_t ad = sb + (uint32_t)r * APB + (uint32_t)c4 * 8;
            STS64(ad, h);
            STS64(ad + 18432, l);
        }
    }
    __syncthreads();

    uint32_t qh[4][4], ql[4][4];
    {
        const uint32_t a0 = sb + (uint32_t)(wid * 16 + (lane & 15)) * APB
                          + (uint32_t)((lane >> 4) * 8) * 2;
#pragma unroll
        for (int j = 0; j < 4; j++) {
            ldmatrix_x4(qh[j], a0 + (uint32_t)(j * 16) * 2);
            ldmatrix_x4(ql[j], a0 + 18432 + (uint32_t)(j * 16) * 2);
        }
    }
    __syncthreads();

    float m0r = -1e30f, m1r = -1e30f, l0 = 0.f, l1 = 0.f;
    float o[8][4];
#pragma unroll
    for (int t = 0; t < 8; t++)
#pragma unroll
        for (int f = 0; f < 4; f++) o[t][f] = 0.f;

    const uint32_t brow = (uint32_t)(lane & 7) * APB + (uint32_t)(((lane >> 3) & 1) * 8) * 2;

    float4 pf[8];
    auto load_tile = [&](int kt) {
#pragma unroll
        for (int j = 0; j < 4; j++) {
            const int idx = j * 256 + tid;
            const int key = idx >> 4, c4 = idx & 15;
            pf[j] = *(const float4*)(kb + (size_t)(kt + key) * 64 + c4 * 4);
        }
#pragma unroll
        for (int j = 0; j < 4; j++) {
            const int idx = j * 256 + tid;
            const int d = idx >> 4, c4 = idx & 15;
            pf[4 + j] = *(const float4*)(vb + (size_t)d * 2048 + kt + c4 * 4);
        }
    };
    auto store_tile = [&](int buf) {
        const uint32_t bp = sb + (uint32_t)buf * ABUF_B;
#pragma unroll
        for (int j = 0; j < 4; j++) {
            const int idx = j * 256 + tid;
            const int key = idx >> 4, c4 = idx & 15;
            uint2 h = cvt4_hi(pf[j]);
            uint2 l = cvt4_lo(pf[j], h);
            const uint32_t ad = bp + (uint32_t)key * APB + (uint32_t)c4 * 8;
            STS64(ad + KHI_O, h);
            STS64(ad + KLO_O, l);
        }
#pragma unroll
        for (int j = 0; j < 4; j++) {
            const int idx = j * 256 + tid;
            const int d = idx >> 4, c4 = idx & 15;
            uint2 h = cvt4_hi(pf[4 + j]);
            uint2 l = cvt4_lo(pf[4 + j], h);
            const uint32_t ad = bp + (uint32_t)d * APB + (uint32_t)c4 * 8;
            STS64(ad + VHI_O, h);
            STS64(ad + VLO_O, l);
        }
    };

    load_tile(0);
    store_tile(0);
    __syncthreads();

    for (int kt = 0; kt < 32; kt++) {
        const int buf = kt & 1;
        if (kt < 31) load_tile((kt + 1) * 64);

        const uint32_t bp = sb + (uint32_t)buf * ABUF_B;

        float s[8][4];
#pragma unroll
        for (int n = 0; n < 8; n++)
#pragma unroll
            for (int f = 0; f < 4; f++) s[n][f] = 0.f;

#pragma unroll
        for (int j = 0; j < 4; j++) {
            const uint32_t kb2 = (uint32_t)(j * 16) * 2;
            uint32_t kh[8][2], kl[8][2];
#pragma unroll
            for (int n = 0; n < 8; n++) {
                const uint32_t ro = (uint32_t)(n * 8) * APB;
                ldmatrix_x2(kh[n], bp + KHI_O + brow + ro + kb2);
                ldmatrix_x2(kl[n], bp + KLO_O + brow + ro + kb2);
            }
#pragma unroll
            for (int n = 0; n < 8; n++) mma_f16(s[n], qh[j], kh[n]);
#pragma unroll
            for (int n = 0; n < 8; n++) mma_f16(s[n], qh[j], kl[n]);
#pragma unroll
            for (int n = 0; n < 8; n++) mma_f16(s[n], ql[j], kh[n]);
        }

        float tm0 = -1e30f, tm1 = -1e30f;
#pragma unroll
        for (int n = 0; n < 8; n++) {
#pragma unroll
            for (int f = 0; f < 4; f++) s[n][f] *= 0.125f;
            tm0 = fmaxf(tm0, fmaxf(s[n][0], s[n][1]));
            tm1 = fmaxf(tm1, fmaxf(s[n][2], s[n][3]));
        }
        tm0 = fmaxf(tm0, __shfl_xor_sync(0xffffffffu, tm0, 1));
        tm0 = fmaxf(tm0, __shfl_xor_sync(0xffffffffu, tm0, 2));
        tm1 = fmaxf(tm1, __shfl_xor_sync(0xffffffffu, tm1, 1));
        tm1 = fmaxf(tm1, __shfl_xor_sync(0xffffffffu, tm1, 2));
        const float mn0 = fmaxf(m0r, tm0), mn1 = fmaxf(m1r, tm1);
        const float a0 = __expf(m0r - mn0), a1 = __expf(m1r - mn1);
        m0r = mn0; m1r = mn1;

        float rs0 = 0.f, rs1 = 0.f;
#pragma unroll
        for (int n = 0; n < 8; n++) {
            s[n][0] = __expf(s[n][0] - mn0);
            s[n][1] = __expf(s[n][1] - mn0);
            s[n][2] = __expf(s[n][2] - mn1);
            s[n][3] = __expf(s[n][3] - mn1);
            rs0 += s[n][0] + s[n][1];
            rs1 += s[n][2] + s[n][3];
        }
        rs0 += __shfl_xor_sync(0xffffffffu, rs0, 1);
        rs0 += __shfl_xor_sync(0xffffffffu, rs0, 2);
        rs1 += __shfl_xor_sync(0xffffffffu, rs1, 1);
        rs1 += __shfl_xor_sync(0xffffffffu, rs1, 2);
        l0 = l0 * a0 + rs0;
        l1 = l1 * a1 + rs1;

#pragma unroll
        for (int t = 0; t < 8; t++) {
            o[t][0] *= a0; o[t][1] *= a0; o[t][2] *= a1; o[t][3] *= a1;
        }

        // PV: P single fp16, V split (2 MMAs)
#pragma unroll
        for (int j = 0; j < 4; j++) {
            uint32_t ph[4];
            ph[0] = pack_f16x2(s[2 * j][0],     s[2 * j][1]);
            ph[1] = pack_f16x2(s[2 * j][2],     s[2 * j][3]);
            ph[2] = pack_f16x2(s[2 * j + 1][0], s[2 * j + 1][1]);
            ph[3] = pack_f16x2(s[2 * j + 1][2], s[2 * j + 1][3]);
            const uint32_t kb2 = (uint32_t)(j * 16) * 2;
#pragma unroll
            for (int t = 0; t < 8; t++) {
                const uint32_t ro = (uint32_t)(t * 8) * APB;
                uint32_t vh[2], vl[2];
                ldmatrix_x2(vh, bp + VHI_O + brow + ro + kb2);
                ldmatrix_x2(vl, bp + VLO_O + brow + ro + kb2);
                mma_f16(o[t], ph, vh);
                mma_f16(o[t], ph, vl);
            }
        }

        if (kt < 31) {
            store_tile(buf ^ 1);
            __syncthreads();
        }
    }

    const int b = bh >> 4, h = bh & 15;
    const int r0 = q0 + wid * 16 + (lane >> 2);
    const int c0 = h * 64 + (lane & 3) * 2;
    const float il0 = 1.f / l0, il1 = 1.f / l1;
#pragma unroll
    for (int t = 0; t < 8; t++) {
        float* base0 = g_ao + (size_t)(b * 2048 + r0) * 1024 + c0 + t * 8;
        float* base1 = g_ao + (size_t)(b * 2048 + r0 + 8) * 1024 + c0 + t * 8;
        *(float2*)base0 = make_float2(o[t][0] * il0, o[t][1] * il0);
        *(float2*)base1 = make_float2(o[t][2] * il1, o[t][3] * il1);
    }
}

// ---------------------------------------------------------------------------
extern "C" void kernel_launch(void* const* d_in, const int* in_sizes, int n_in,
                              void* d_out, int out_size)
{
    const float* x      = (const float*)d_in[0];
    const float* params = (const float*)d_in[1];
    const float* wq     = (const float*)d_in[2];
    const float* wk     = (const float*)d_in[3];
    const float* wv     = (const float*)d_in[4];
    const float* wo     = (const float*)d_in[5];
    float* out = (float*)d_out;

    cudaFuncSetAttribute(gemm_mma_kernel,
                         cudaFuncAttributeMaxDynamicSharedMemorySize, GSMEM);
    cudaFuncSetAttribute(attention_mma_kernel,
                         cudaFuncAttributeMaxDynamicSharedMemorySize, ASMEM);

    __half *wh, *xhi, *xlo, *aohi, *aolo;
    cudaGetSymbolAddress((void**)&wh,   g_wh);
    cudaGetSymbolAddress((void**)&xhi,  g_xhi);
    cudaGetSymbolAddress((void**)&xlo,  g_xlo);
    cudaGetSymbolAddress((void**)&aohi, g_aohi);
    cudaGetSymbolAddress((void**)&aolo, g_aolo);

    split2_kernel<<<4096, 256>>>(x, xhi, xlo, 1048576);
    cvt1_kernel<<<1024, 256>>>(wq, wh + 0 * 1048576, 262144);
    cvt1_kernel<<<1024, 256>>>(wk, wh + 1 * 1048576, 262144);
    cvt1_kernel<<<1024, 256>>>(wv, wh + 2 * 1048576, 262144);
    cvt1_kernel<<<1024, 256>>>(wo, wh + 3 * 1048576, 262144);

    gemm_mma_kernel<<<dim3(8, 32, 3), 256, GSMEM>>>(xhi, xlo, nullptr, 1);
    quantum_kernel<<<768, 256>>>(params);
    attention_mma_kernel<<<dim3(16, 32), 256, ASMEM>>>();

    float* ao;
    cudaGetSymbolAddress((void**)&ao, g_ao);
    split2_kernel<<<4096, 256>>>(ao, aohi, aolo, 1048576);
    gemm_mma_kernel<<<dim3(8, 32, 1), 256, GSMEM>>>(aohi, aolo, out, 0);
}

// round 7
// speedup vs baseline: 4.2191x; 1.1121x over previous
#include <cuda_runtime.h>
#include <cuda_fp16.h>
#include <cstdint>

// ---------------------------------------------------------------------------
// QuantumAttention  (B=2, S=2048, E=1024, H=16, dk=64, NQ=4, NL=2)
// Round 7: scores 2-term (Q split x K single). K-lo tile removed from the
// attention loop; paired ldmatrix.x4 for K/V fragments. GEMMs as R6.
// ---------------------------------------------------------------------------

__device__ float g_q [2*16*2048*64];   // [b][h][s][d]
__device__ float g_k [2*16*2048*64];   // [b][h][s][d]
__device__ float g_v [2*16*2048*64];   // [b][h][d][s]   (transposed!)
__device__ float g_ao[2*2048*1024];    // [b][s][h*64+d]

__device__ __half g_xhi [4096*1024];
__device__ __half g_xlo [4096*1024];
__device__ __half g_wh  [4*1024*1024];   // q,k,v,o packed, single-rounded
__device__ __half g_aohi[4096*1024];
__device__ __half g_aolo[4096*1024];

// ---------------- helpers ---------------------------------------------------
__device__ __forceinline__ uint32_t smem_u32(const void* p) {
    uint32_t a;
    asm("{ .reg .u64 t; cvta.to.shared.u64 t, %1; cvt.u32.u64 %0, t; }" : "=r"(a) : "l"(p));
    return a;
}
#define CP_ASYNC16(dst, src) \
    asm volatile("cp.async.cg.shared.global [%0], [%1], 16;" :: "r"(dst), "l"(src) : "memory")
#define CP_COMMIT() asm volatile("cp.async.commit_group;" ::: "memory")
#define CP_WAIT(n)  asm volatile("cp.async.wait_group %0;" :: "n"(n) : "memory")

__device__ __forceinline__ void ldmatrix_x4(uint32_t (&r)[4], uint32_t addr) {
    asm volatile("ldmatrix.sync.aligned.m8n8.x4.shared.b16 {%0,%1,%2,%3}, [%4];"
                 : "=r"(r[0]), "=r"(r[1]), "=r"(r[2]), "=r"(r[3]) : "r"(addr));
}
__device__ __forceinline__ void mma_f16(float (&d)[4], const uint32_t (&a)[4],
                                        const uint32_t (&b)[2]) {
    asm volatile("mma.sync.aligned.m16n8k16.row.col.f32.f16.f16.f32 "
                 "{%0,%1,%2,%3}, {%4,%5,%6,%7}, {%8,%9}, {%0,%1,%2,%3};"
                 : "+f"(d[0]), "+f"(d[1]), "+f"(d[2]), "+f"(d[3])
                 : "r"(a[0]), "r"(a[1]), "r"(a[2]), "r"(a[3]), "r"(b[0]), "r"(b[1]));
}
__device__ __forceinline__ uint32_t pack_f16x2(float lo, float hi) {
    uint32_t r;
    asm("cvt.rn.f16x2.f32 %0, %1, %2;" : "=r"(r) : "f"(hi), "f"(lo));
    return r;
}
__device__ __forceinline__ uint2 cvt4_hi(const float4 v) {
    return make_uint2(pack_f16x2(v.x, v.y), pack_f16x2(v.z, v.w));
}
__device__ __forceinline__ uint2 cvt4_lo(const float4 v, const uint2 hi) {
    __half2 h0 = *reinterpret_cast<const __half2*>(&hi.x);
    __half2 h1 = *reinterpret_cast<const __half2*>(&hi.y);
    float2 f0 = __half22float2(h0);
    float2 f1 = __half22float2(h1);
    return make_uint2(pack_f16x2(v.x - f0.x, v.y - f0.y),
                      pack_f16x2(v.z - f1.x, v.w - f1.y));
}
#define STS64(ad, v) \
    asm volatile("st.shared.v2.b32 [%0], {%1, %2};" :: "r"(ad), "r"((v).x), "r"((v).y) : "memory")

// ---------------------------------------------------------------------------
// fp32 -> (f16 hi, f16 lo) split  |  fp32 -> f16 single
// ---------------------------------------------------------------------------
__global__ void split2_kernel(const float* __restrict__ src,
                              __half* __restrict__ hi,
                              __half* __restrict__ lo, int n4)
{
    const int i = blockIdx.x * 256 + threadIdx.x;
    if (i >= n4) return;
    float4 v = ((const float4*)src)[i];
    uint2 ph = cvt4_hi(v);
    uint2 pl = cvt4_lo(v, ph);
    ((uint2*)hi)[i] = ph;
    ((uint2*)lo)[i] = pl;
}
__global__ void cvt1_kernel(const float* __restrict__ src,
                            __half* __restrict__ dst, int n4)
{
    const int i = blockIdx.x * 256 + threadIdx.x;
    if (i >= n4) return;
    float4 v = ((const float4*)src)[i];
    ((uint2*)dst)[i] = cvt4_hi(v);
}

// ---------------------------------------------------------------------------
// mma.sync GEMM (as R6):  C[m][n] = sum_k A[m][k] * B[n][k]
// ---------------------------------------------------------------------------
#define PITCH   40
#define PITCHB  (PITCH * 2)
#define MAT_B   (128 * PITCHB)
#define STAGE_B (3 * MAT_B)
#define NSTG    3
#define GSMEM   (NSTG * STAGE_B)

__global__ __launch_bounds__(256, 2)
void gemm_mma_kernel(const __half* __restrict__ Ahi,
                     const __half* __restrict__ Alo,
                     float* __restrict__ Cout, int is_proj)
{
    extern __shared__ char smem[];
    const uint32_t sb = smem_u32(smem);
    const int tid  = threadIdx.x;
    const int wid  = tid >> 5;
    const int lane = tid & 31;

    const int z  = blockIdx.z;
    const int m0 = blockIdx.y * 128;
    const int n0 = blockIdx.x * 128;
    const size_t woff = ((size_t)(is_proj ? z : 3)) << 20;

    const __half* gsrc[3] = { Ahi + (size_t)m0 * 1024,
                              Alo + (size_t)m0 * 1024,
                              g_wh + woff + (size_t)n0 * 1024 };

    const int wm = wid & 1;
    const int wn = wid >> 1;
    const uint32_t a_addr0 = (uint32_t)(wm * 64 + (lane & 15)) * PITCHB
                           + (uint32_t)((lane >> 4) * 8) * 2;
    const uint32_t b_addr0 = (uint32_t)(wn * 32 + (lane & 7) + ((lane >> 4) << 3)) * PITCHB
                           + (uint32_t)(((lane >> 3) & 1) * 16);

    float acc[4][4][4];
#pragma unroll
    for (int i = 0; i < 4; i++)
#pragma unroll
        for (int t = 0; t < 4; t++)
#pragma unroll
            for (int f = 0; f < 4; f++) acc[i][t][f] = 0.f;

    auto load_stage = [&](int ch, int stg) {
        const int k0 = ch * 32;
        const uint32_t dst = sb + (uint32_t)stg * STAGE_B;
#pragma unroll
        for (int j = 0; j < 6; j++) {
            const int idx = j * 256 + tid;
            const int mat = idx >> 9;
            const int w   = idx & 511;
            const int row = w >> 2;
            const int c16 = w & 3;
            CP_ASYNC16(dst + (uint32_t)mat * MAT_B + (uint32_t)row * PITCHB
                           + (uint32_t)c16 * 16,
                       gsrc[mat] + (size_t)row * 1024 + k0 + c16 * 8);
        }
        CP_COMMIT();
    };

    load_stage(0, 0);
    load_stage(1, 1);

    for (int ch = 0; ch < 32; ch++) {
        CP_WAIT(1);
        __syncthreads();
        if (ch + 2 < 32) load_stage(ch + 2, (ch + 2) % NSTG);

        const uint32_t stg = sb + (uint32_t)(ch % NSTG) * STAGE_B;
#pragma unroll
        for (int ks = 0; ks < 2; ks++) {
            const uint32_t kb = (uint32_t)(ks * 32);
            uint32_t ah[4][4], al[4][4];
#pragma unroll
            for (int i = 0; i < 4; i++) {
                const uint32_t ro = (uint32_t)(i * 16) * PITCHB;
                ldmatrix_x4(ah[i], stg + 0 * MAT_B + a_addr0 + ro + kb);
                ldmatrix_x4(al[i], stg + 1 * MAT_B + a_addr0 + ro + kb);
            }
            uint32_t bh[4][2];
#pragma unroll
            for (int p = 0; p < 2; p++) {
                const uint32_t ro = (uint32_t)(p * 16) * PITCHB;
                uint32_t t4[4];
                ldmatrix_x4(t4, stg + 2 * MAT_B + b_addr0 + ro + kb);
                bh[2 * p][0] = t4[0];     bh[2 * p][1] = t4[1];
                bh[2 * p + 1][0] = t4[2]; bh[2 * p + 1][1] = t4[3];
            }
#pragma unroll
            for (int i = 0; i < 4; i++)
#pragma unroll
                for (int t = 0; t < 4; t++) mma_f16(acc[i][t], ah[i], bh[t]);
#pragma unroll
            for (int i = 0; i < 4; i++)
#pragma unroll
                for (int t = 0; t < 4; t++) mma_f16(acc[i][t], al[i], bh[t]);
        }
    }

    const int r_in = lane >> 2;
    const int c_in = (lane & 3) * 2;
#pragma unroll
    for (int i = 0; i < 4; i++) {
#pragma unroll
        for (int half = 0; half < 2; half++) {
            const int m = m0 + wm * 64 + i * 16 + r_in + half * 8;
            const int b = m >> 11, s = m & 2047;
#pragma unroll
            for (int t = 0; t < 4; t++) {
                const int n = n0 + wn * 32 + t * 8 + c_in;
                const float v0 = acc[i][t][half * 2], v1 = acc[i][t][half * 2 + 1];
                if (is_proj) {
                    const int h = n >> 6, d = n & 63;
                    if (z == 2) {
                        float* dst = g_v + ((size_t)(((b << 4) + h) << 6) + d) * 2048 + s;
                        dst[0] = v0; dst[2048] = v1;
                    } else {
                        float* O = (z == 0) ? g_q : g_k;
                        *(float2*)(O + (((size_t)((b << 4) + h) * 2048 + s) << 6) + d)
                            = make_float2(v0, v1);
                    }
                } else {
                    *(float2*)(Cout + (size_t)m * 1024 + n) = make_float2(v0, v1);
                }
            }
        }
    }
}

// ---------------------------------------------------------------------------
// Quantum block (V transposed: stride 2048 between wires)
// ---------------------------------------------------------------------------
__global__ void quantum_kernel(const float* __restrict__ params)
{
    const int id = blockIdx.x * 256 + threadIdx.x;
    if (id >= 3 * 65536) return;
    const int tensor = id >> 16;
    const int idx = id & 65535;
    float* vec;
    int stride;
    if (tensor == 0)      { vec = g_q + (size_t)idx * 64; stride = 1; }
    else if (tensor == 1) { vec = g_k + (size_t)idx * 64; stride = 1; }
    else {
        const int bh = idx >> 11, s = idx & 2047;
        vec = g_v + ((size_t)bh << 6) * 2048 + s; stride = 2048;
    }

    float ax[4];
#pragma unroll
    for (int w = 0; w < 4; w++) ax[w] = vec[w * stride];

    float sr[16], si[16];
#pragma unroll
    for (int i = 0; i < 16; i++) { sr[i] = 0.f; si[i] = 0.f; }
    sr[0] = 1.f;

#pragma unroll
    for (int w = 0; w < 4; w++) {
        const float a = 0.5f * ax[w];
        float s, c;
        sincosf(a, &s, &c);
        const int st = 8 >> w;
#pragma unroll
        for (int i = 0; i < 16; i++) {
            if (i & st) continue;
            const int j = i + st;
            const float xr = sr[i], xi = si[i], yr = sr[j], yi = si[j];
            sr[i] = c * xr + s * yi;  si[i] = c * xi - s * yr;
            sr[j] = c * yr + s * xi;  si[j] = c * yi - s * xr;
        }
    }
#pragma unroll
    for (int l = 0; l < 2; l++) {
#pragma unroll
        for (int w = 0; w < 4; w++) {
            const float phi = params[l * 12 + w * 3 + 0];
            const float th  = params[l * 12 + w * 3 + 1];
            const float om  = params[l * 12 + w * 3 + 2];
            float stt, ct;  sincosf(0.5f * th, &stt, &ct);
            float sap, cap; sincosf(0.5f * (phi + om), &sap, &cap);
            float sam, cam; sincosf(0.5f * (phi - om), &sam, &cam);
            const float m00r =  cap * ct,  m00i = -sap * ct;
            const float m01r = -cam * stt, m01i = -sam * stt;
            const float m10r =  cam * stt, m10i = -sam * stt;
            const float m11r =  cap * ct,  m11i =  sap * ct;
            const int st = 8 >> w;
#pragma unroll
            for (int i = 0; i < 16; i++) {
                if (i & st) continue;
                const int j = i + st;
                const float xr = sr[i], xi = si[i], yr = sr[j], yi = si[j];
                sr[i] = m00r * xr - m00i * xi + m01r * yr - m01i * yi;
                si[i] = m00r * xi + m00i * xr + m01r * yi + m01i * yr;
                sr[j] = m10r * xr - m10i * xi + m11r * yr - m11i * yi;
                si[j] = m10r * xi + m10i * xr + m11r * yi + m11i * yr;
            }
        }
#pragma unroll
        for (int r = 0; r < 4; r++) {
            float tr = sr[8 + r], ti = si[8 + r];
            sr[8 + r] = sr[12 + r];  si[8 + r] = si[12 + r];
            sr[12 + r] = tr;         si[12 + r] = ti;
        }
    }
    float ev[4] = {0.f, 0.f, 0.f, 0.f};
#pragma unroll
    for (int i = 0; i < 16; i++) {
        const float pr = sr[i] * sr[i] + si[i] * si[i];
#pragma unroll
        for (int w = 0; w < 4; w++)
            ev[w] += ((i >> (3 - w)) & 1) ? -pr : pr;
    }
#pragma unroll
    for (int w = 0; w < 4; w++) vec[w * stride] = ev[w];
}

// ---------------------------------------------------------------------------
// FA2 attention, fp16: scores 2-term (Q split x K single), PV 2-term
// (P single x V split). Paired x4 B-frag loads. Grid: (16, 32), 256 thr.
// smem buffer: Khi | Vhi | Vlo  (3 x 64 rows x 144B)
// ---------------------------------------------------------------------------
#define AP      72
#define APB     (AP * 2)
#define KHI_O   0
#define VHI_O   (64 * APB)
#define VLO_O   (2 * 64 * APB)
#define ABUF_B  (3 * 64 * APB)         // 27648
#define ASMEM   (2 * ABUF_B)           // 55296

__global__ __launch_bounds__(256, 1)
void attention_mma_kernel()
{
    extern __shared__ char smem[];
    const uint32_t sb = smem_u32(smem);
    const int tid  = threadIdx.x;
    const int wid  = tid >> 5;
    const int lane = tid & 31;

    const int bh = blockIdx.y;
    const int q0 = blockIdx.x * 128;

    const float* qb = g_q + (size_t)bh * 2048 * 64;
    const float* kb = g_k + (size_t)bh * 2048 * 64;
    const float* vb = g_v + (size_t)bh * 64 * 2048;

    // Q staging: hi at sb+0, lo at sb+18432 (both fit in 2*18432 < ASMEM)
    {
#pragma unroll
        for (int j = 0; j < 8; j++) {
            const int idx = j * 256 + tid;
            const int r = idx >> 4, c4 = idx & 15;
            float4 v = *(const float4*)(qb + (size_t)(q0 + r) * 64 + c4 * 4);
            uint2 h = cvt4_hi(v);
            uint2 l = cvt4_lo(v, h);
            const uint32_t ad = sb + (uint32_t)r * APB + (uint32_t)c4 * 8;
            STS64(ad, h);
            STS64(ad + 18432, l);
        }
    }
    __syncthreads();

    uint32_t qh[4][4], ql[4][4];
    {
        const uint32_t a0 = sb + (uint32_t)(wid * 16 + (lane & 15)) * APB
                          + (uint32_t)((lane >> 4) * 8) * 2;
#pragma unroll
        for (int j = 0; j < 4; j++) {
            ldmatrix_x4(qh[j], a0 + (uint32_t)(j * 16) * 2);
            ldmatrix_x4(ql[j], a0 + 18432 + (uint32_t)(j * 16) * 2);
        }
    }
    __syncthreads();

    float m0r = -1e30f, m1r = -1e30f, l0 = 0.f, l1 = 0.f;
    float o[8][4];
#pragma unroll
    for (int t = 0; t < 8; t++)
#pragma unroll
        for (int f = 0; f < 4; f++) o[t][f] = 0.f;

    // paired-x4 B-frag base: lanes 0-7 row, 8-15 row k+8, 16-23 row+8, 24-31 row+8 k+8
    const uint32_t brow4 = (uint32_t)((lane & 7) + ((lane >> 4) << 3)) * APB
                         + (uint32_t)(((lane >> 3) & 1) * 16);

    float4 pf[8];
    auto load_tile = [&](int kt) {
#pragma unroll
        for (int j = 0; j < 4; j++) {
            const int idx = j * 256 + tid;
            const int key = idx >> 4, c4 = idx & 15;
            pf[j] = *(const float4*)(kb + (size_t)(kt + key) * 64 + c4 * 4);
        }
#pragma unroll
        for (int j = 0; j < 4; j++) {
            const int idx = j * 256 + tid;
            const int d = idx >> 4, c4 = idx & 15;
            pf[4 + j] = *(const float4*)(vb + (size_t)d * 2048 + kt + c4 * 4);
        }
    };
    auto store_tile = [&](int buf) {
        const uint32_t bp = sb + (uint32_t)buf * ABUF_B;
#pragma unroll
        for (int j = 0; j < 4; j++) {      // K: hi only
            const int idx = j * 256 + tid;
            const int key = idx >> 4, c4 = idx & 15;
            uint2 h = cvt4_hi(pf[j]);
            STS64(bp + KHI_O + (uint32_t)key * APB + (uint32_t)c4 * 8, h);
        }
#pragma unroll
        for (int j = 0; j < 4; j++) {      // V: hi + lo
            const int idx = j * 256 + tid;
            const int d = idx >> 4, c4 = idx & 15;
            uint2 h = cvt4_hi(pf[4 + j]);
            uint2 l = cvt4_lo(pf[4 + j], h);
            const uint32_t ad = bp + (uint32_t)d * APB + (uint32_t)c4 * 8;
            STS64(ad + VHI_O, h);
            STS64(ad + VLO_O, l);
        }
    };

    load_tile(0);
    store_tile(0);
    __syncthreads();

    for (int kt = 0; kt < 32; kt++) {
        const int buf = kt & 1;
        if (kt < 31) load_tile((kt + 1) * 64);

        const uint32_t bp = sb + (uint32_t)buf * ABUF_B;

        float s[8][4];
#pragma unroll
        for (int n = 0; n < 8; n++)
#pragma unroll
            for (int f = 0; f < 4; f++) s[n][f] = 0.f;

        // ---- scores: 2-term, paired-x4 K frags ----
#pragma unroll
        for (int j = 0; j < 4; j++) {
            const uint32_t kb2 = (uint32_t)(j * 32);
            uint32_t kh[8][2];
#pragma unroll
            for (int p = 0; p < 4; p++) {
                const uint32_t ro = (uint32_t)(p * 16) * APB;
                uint32_t t4[4];
                ldmatrix_x4(t4, bp + KHI_O + brow4 + ro + kb2);
                kh[2 * p][0] = t4[0];     kh[2 * p][1] = t4[1];
                kh[2 * p + 1][0] = t4[2]; kh[2 * p + 1][1] = t4[3];
            }
#pragma unroll
            for (int n = 0; n < 8; n++) mma_f16(s[n], qh[j], kh[n]);
#pragma unroll
            for (int n = 0; n < 8; n++) mma_f16(s[n], ql[j], kh[n]);
        }

        // ---- online softmax ----
        float tm0 = -1e30f, tm1 = -1e30f;
#pragma unroll
        for (int n = 0; n < 8; n++) {
#pragma unroll
            for (int f = 0; f < 4; f++) s[n][f] *= 0.125f;
            tm0 = fmaxf(tm0, fmaxf(s[n][0], s[n][1]));
            tm1 = fmaxf(tm1, fmaxf(s[n][2], s[n][3]));
        }
        tm0 = fmaxf(tm0, __shfl_xor_sync(0xffffffffu, tm0, 1));
        tm0 = fmaxf(tm0, __shfl_xor_sync(0xffffffffu, tm0, 2));
        tm1 = fmaxf(tm1, __shfl_xor_sync(0xffffffffu, tm1, 1));
        tm1 = fmaxf(tm1, __shfl_xor_sync(0xffffffffu, tm1, 2));
        const float mn0 = fmaxf(m0r, tm0), mn1 = fmaxf(m1r, tm1);
        const float a0 = __expf(m0r - mn0), a1 = __expf(m1r - mn1);
        m0r = mn0; m1r = mn1;

        float rs0 = 0.f, rs1 = 0.f;
#pragma unroll
        for (int n = 0; n < 8; n++) {
            s[n][0] = __expf(s[n][0] - mn0);
            s[n][1] = __expf(s[n][1] - mn0);
            s[n][2] = __expf(s[n][2] - mn1);
            s[n][3] = __expf(s[n][3] - mn1);
            rs0 += s[n][0] + s[n][1];
            rs1 += s[n][2] + s[n][3];
        }
        rs0 += __shfl_xor_sync(0xffffffffu, rs0, 1);
        rs0 += __shfl_xor_sync(0xffffffffu, rs0, 2);
        rs1 += __shfl_xor_sync(0xffffffffu, rs1, 1);
        rs1 += __shfl_xor_sync(0xffffffffu, rs1, 2);
        l0 = l0 * a0 + rs0;
        l1 = l1 * a1 + rs1;

#pragma unroll
        for (int t = 0; t < 8; t++) {
            o[t][0] *= a0; o[t][1] *= a0; o[t][2] *= a1; o[t][3] *= a1;
        }

        // ---- PV: P single fp16, V split; paired-x4 V frags ----
#pragma unroll
        for (int j = 0; j < 4; j++) {
            uint32_t ph[4];
            ph[0] = pack_f16x2(s[2 * j][0],     s[2 * j][1]);
            ph[1] = pack_f16x2(s[2 * j][2],     s[2 * j][3]);
            ph[2] = pack_f16x2(s[2 * j + 1][0], s[2 * j + 1][1]);
            ph[3] = pack_f16x2(s[2 * j + 1][2], s[2 * j + 1][3]);
            const uint32_t kb2 = (uint32_t)(j * 32);
            uint32_t vh[8][2], vl[8][2];
#pragma unroll
            for (int p = 0; p < 4; p++) {
                const uint32_t ro = (uint32_t)(p * 16) * APB;
                uint32_t t4[4];
                ldmatrix_x4(t4, bp + VHI_O + brow4 + ro + kb2);
                vh[2 * p][0] = t4[0];     vh[2 * p][1] = t4[1];
                vh[2 * p + 1][0] = t4[2]; vh[2 * p + 1][1] = t4[3];
                ldmatrix_x4(t4, bp + VLO_O + brow4 + ro + kb2);
                vl[2 * p][0] = t4[0];     vl[2 * p][1] = t4[1];
                vl[2 * p + 1][0] = t4[2]; vl[2 * p + 1][1] = t4[3];
            }
#pragma unroll
            for (int t = 0; t < 8; t++) mma_f16(o[t], ph, vh[t]);
#pragma unroll
            for (int t = 0; t < 8; t++) mma_f16(o[t], ph, vl[t]);
        }

        if (kt < 31) {
            store_tile(buf ^ 1);
            __syncthreads();
        }
    }

    const int b = bh >> 4, h = bh & 15;
    const int r0 = q0 + wid * 16 + (lane >> 2);
    const int c0 = h * 64 + (lane & 3) * 2;
    const float il0 = 1.f / l0, il1 = 1.f / l1;
#pragma unroll
    for (int t = 0; t < 8; t++) {
        float* base0 = g_ao + (size_t)(b * 2048 + r0) * 1024 + c0 + t * 8;
        float* base1 = g_ao + (size_t)(b * 2048 + r0 + 8) * 1024 + c0 + t * 8;
        *(float2*)base0 = make_float2(o[t][0] * il0, o[t][1] * il0);
        *(float2*)base1 = make_float2(o[t][2] * il1, o[t][3] * il1);
    }
}

// ---------------------------------------------------------------------------
extern "C" void kernel_launch(void* const* d_in, const int* in_sizes, int n_in,
                              void* d_out, int out_size)
{
    const float* x      = (const float*)d_in[0];
    const float* params = (const float*)d_in[1];
    const float* wq     = (const float*)d_in[2];
    const float* wk     = (const float*)d_in[3];
    const float* wv     = (const float*)d_in[4];
    const float* wo     = (const float*)d_in[5];
    float* out = (float*)d_out;

    cudaFuncSetAttribute(gemm_mma_kernel,
                         cudaFuncAttributeMaxDynamicSharedMemorySize, GSMEM);
    cudaFuncSetAttribute(attention_mma_kernel,
                         cudaFuncAttributeMaxDynamicSharedMemorySize, ASMEM);

    __half *wh, *xhi, *xlo, *aohi, *aolo;
    cudaGetSymbolAddress((void**)&wh,   g_wh);
    cudaGetSymbolAddress((void**)&xhi,  g_xhi);
    cudaGetSymbolAddress((void**)&xlo,  g_xlo);
    cudaGetSymbolAddress((void**)&aohi, g_aohi);
    cudaGetSymbolAddress((void**)&aolo, g_aolo);

    split2_kernel<<<4096, 256>>>(x, xhi, xlo, 1048576);
    cvt1_kernel<<<1024, 256>>>(wq, wh + 0 * 1048576, 262144);
    cvt1_kernel<<<1024, 256>>>(wk, wh + 1 * 1048576, 262144);
    cvt1_kernel<<<1024, 256>>>(wv, wh + 2 * 1048576, 262144);
    cvt1_kernel<<<1024, 256>>>(wo, wh + 3 * 1048576, 262144);

    gemm_mma_kernel<<<dim3(8, 32, 3), 256, GSMEM>>>(xhi, xlo, nullptr, 1);
    quantum_kernel<<<768, 256>>>(params);
    attention_mma_kernel<<<dim3(16, 32), 256, ASMEM>>>();

    float* ao;
    cudaGetSymbolAddress((void**)&ao, g_ao);
    split2_kernel<<<4096, 256>>>(ao, aohi, aolo, 1048576);
    gemm_mma_kernel<<<dim3(8, 32, 1), 256, GSMEM>>>(aohi, aolo, out, 0);
}

// round 8
// speedup vs baseline: 4.7402x; 1.1235x over previous
#include <cuda_runtime.h>
#include <cuda_fp16.h>
#include <cstdint>

// ---------------------------------------------------------------------------
// QuantumAttention  (B=2, S=2048, E=1024, H=16, dk=64, NQ=4, NL=2)
// Round 8: PV 1-term (P,V single fp16); out-proj 1-term A; attention epilogue
// writes fp16 directly (ao split kernel removed). Scores/QKV stay 2-term.
// ---------------------------------------------------------------------------

__device__ float g_q [2*16*2048*64];   // [b][h][s][d]
__device__ float g_k [2*16*2048*64];   // [b][h][s][d]
__device__ float g_v [2*16*2048*64];   // [b][h][d][s]   (transposed!)

__device__ __half g_aoh [4096*1024];   // attention out, fp16, [b][s][h*64+d]
__device__ __half g_xhi [4096*1024];
__device__ __half g_xlo [4096*1024];
__device__ __half g_wh  [4*1024*1024]; // q,k,v,o packed, single-rounded

// ---------------- helpers ---------------------------------------------------
__device__ __forceinline__ uint32_t smem_u32(const void* p) {
    uint32_t a;
    asm("{ .reg .u64 t; cvta.to.shared.u64 t, %1; cvt.u32.u64 %0, t; }" : "=r"(a) : "l"(p));
    return a;
}
#define CP_ASYNC16(dst, src) \
    asm volatile("cp.async.cg.shared.global [%0], [%1], 16;" :: "r"(dst), "l"(src) : "memory")
#define CP_COMMIT() asm volatile("cp.async.commit_group;" ::: "memory")
#define CP_WAIT(n)  asm volatile("cp.async.wait_group %0;" :: "n"(n) : "memory")

__device__ __forceinline__ void ldmatrix_x4(uint32_t (&r)[4], uint32_t addr) {
    asm volatile("ldmatrix.sync.aligned.m8n8.x4.shared.b16 {%0,%1,%2,%3}, [%4];"
                 : "=r"(r[0]), "=r"(r[1]), "=r"(r[2]), "=r"(r[3]) : "r"(addr));
}
__device__ __forceinline__ void mma_f16(float (&d)[4], const uint32_t (&a)[4],
                                        const uint32_t (&b)[2]) {
    asm volatile("mma.sync.aligned.m16n8k16.row.col.f32.f16.f16.f32 "
                 "{%0,%1,%2,%3}, {%4,%5,%6,%7}, {%8,%9}, {%0,%1,%2,%3};"
                 : "+f"(d[0]), "+f"(d[1]), "+f"(d[2]), "+f"(d[3])
                 : "r"(a[0]), "r"(a[1]), "r"(a[2]), "r"(a[3]), "r"(b[0]), "r"(b[1]));
}
__device__ __forceinline__ uint32_t pack_f16x2(float lo, float hi) {
    uint32_t r;
    asm("cvt.rn.f16x2.f32 %0, %1, %2;" : "=r"(r) : "f"(hi), "f"(lo));
    return r;
}
__device__ __forceinline__ uint2 cvt4_hi(const float4 v) {
    return make_uint2(pack_f16x2(v.x, v.y), pack_f16x2(v.z, v.w));
}
__device__ __forceinline__ uint2 cvt4_lo(const float4 v, const uint2 hi) {
    __half2 h0 = *reinterpret_cast<const __half2*>(&hi.x);
    __half2 h1 = *reinterpret_cast<const __half2*>(&hi.y);
    float2 f0 = __half22float2(h0);
    float2 f1 = __half22float2(h1);
    return make_uint2(pack_f16x2(v.x - f0.x, v.y - f0.y),
                      pack_f16x2(v.z - f1.x, v.w - f1.y));
}
#define STS64(ad, v) \
    asm volatile("st.shared.v2.b32 [%0], {%1, %2};" :: "r"(ad), "r"((v).x), "r"((v).y) : "memory")

// ---------------------------------------------------------------------------
// fp32 -> (f16 hi, f16 lo) split  |  fp32 -> f16 single
// ---------------------------------------------------------------------------
__global__ void split2_kernel(const float* __restrict__ src,
                              __half* __restrict__ hi,
                              __half* __restrict__ lo, int n4)
{
    const int i = blockIdx.x * 256 + threadIdx.x;
    if (i >= n4) return;
    float4 v = ((const float4*)src)[i];
    uint2 ph = cvt4_hi(v);
    uint2 pl = cvt4_lo(v, ph);
    ((uint2*)hi)[i] = ph;
    ((uint2*)lo)[i] = pl;
}
__global__ void cvt1_kernel(const float* __restrict__ src,
                            __half* __restrict__ dst, int n4)
{
    const int i = blockIdx.x * 256 + threadIdx.x;
    if (i >= n4) return;
    float4 v = ((const float4*)src)[i];
    ((uint2*)dst)[i] = cvt4_hi(v);
}

// ---------------------------------------------------------------------------
// mma.sync GEMM:  C[m][n] = sum_k A[m][k] * B[n][k]
// two_term (is_proj=1): A = Ahi+Alo split. is_proj=0: A single (Ahi only).
// ---------------------------------------------------------------------------
#define PITCH   40
#define PITCHB  (PITCH * 2)
#define MAT_B   (128 * PITCHB)
#define STAGE_B (3 * MAT_B)
#define NSTG    3
#define GSMEM   (NSTG * STAGE_B)

__global__ __launch_bounds__(256, 2)
void gemm_mma_kernel(const __half* __restrict__ Ahi,
                     const __half* __restrict__ Alo,
                     float* __restrict__ Cout, int is_proj)
{
    extern __shared__ char smem[];
    const uint32_t sb = smem_u32(smem);
    const int tid  = threadIdx.x;
    const int wid  = tid >> 5;
    const int lane = tid & 31;

    const int z  = blockIdx.z;
    const int m0 = blockIdx.y * 128;
    const int n0 = blockIdx.x * 128;
    const size_t woff = ((size_t)(is_proj ? z : 3)) << 20;
    const int two_term = is_proj;

    const __half* gsrc[3] = { Ahi + (size_t)m0 * 1024,
                              two_term ? (Alo + (size_t)m0 * 1024)
                                       : (Ahi + (size_t)m0 * 1024),
                              g_wh + woff + (size_t)n0 * 1024 };

    const int wm = wid & 1;
    const int wn = wid >> 1;
    const uint32_t a_addr0 = (uint32_t)(wm * 64 + (lane & 15)) * PITCHB
                           + (uint32_t)((lane >> 4) * 8) * 2;
    const uint32_t b_addr0 = (uint32_t)(wn * 32 + (lane & 7) + ((lane >> 4) << 3)) * PITCHB
                           + (uint32_t)(((lane >> 3) & 1) * 16);

    float acc[4][4][4];
#pragma unroll
    for (int i = 0; i < 4; i++)
#pragma unroll
        for (int t = 0; t < 4; t++)
#pragma unroll
            for (int f = 0; f < 4; f++) acc[i][t][f] = 0.f;

    auto load_stage = [&](int ch, int stg) {
        const int k0 = ch * 32;
        const uint32_t dst = sb + (uint32_t)stg * STAGE_B;
#pragma unroll
        for (int j = 0; j < 6; j++) {
            const int idx = j * 256 + tid;
            const int mat = idx >> 9;
            if (!two_term && mat == 1) continue;
            const int w   = idx & 511;
            const int row = w >> 2;
            const int c16 = w & 3;
            CP_ASYNC16(dst + (uint32_t)mat * MAT_B + (uint32_t)row * PITCHB
                           + (uint32_t)c16 * 16,
                       gsrc[mat] + (size_t)row * 1024 + k0 + c16 * 8);
        }
        CP_COMMIT();
    };

    load_stage(0, 0);
    load_stage(1, 1);

    for (int ch = 0; ch < 32; ch++) {
        CP_WAIT(1);
        __syncthreads();
        if (ch + 2 < 32) load_stage(ch + 2, (ch + 2) % NSTG);

        const uint32_t stg = sb + (uint32_t)(ch % NSTG) * STAGE_B;
#pragma unroll
        for (int ks = 0; ks < 2; ks++) {
            const uint32_t kb = (uint32_t)(ks * 32);
            uint32_t ah[4][4];
#pragma unroll
            for (int i = 0; i < 4; i++) {
                const uint32_t ro = (uint32_t)(i * 16) * PITCHB;
                ldmatrix_x4(ah[i], stg + 0 * MAT_B + a_addr0 + ro + kb);
            }
            uint32_t bh[4][2];
#pragma unroll
            for (int p = 0; p < 2; p++) {
                const uint32_t ro = (uint32_t)(p * 16) * PITCHB;
                uint32_t t4[4];
                ldmatrix_x4(t4, stg + 2 * MAT_B + b_addr0 + ro + kb);
                bh[2 * p][0] = t4[0];     bh[2 * p][1] = t4[1];
                bh[2 * p + 1][0] = t4[2]; bh[2 * p + 1][1] = t4[3];
            }
#pragma unroll
            for (int i = 0; i < 4; i++)
#pragma unroll
                for (int t = 0; t < 4; t++) mma_f16(acc[i][t], ah[i], bh[t]);

            if (two_term) {
                uint32_t al[4][4];
#pragma unroll
                for (int i = 0; i < 4; i++) {
                    const uint32_t ro = (uint32_t)(i * 16) * PITCHB;
                    ldmatrix_x4(al[i], stg + 1 * MAT_B + a_addr0 + ro + kb);
                }
#pragma unroll
                for (int i = 0; i < 4; i++)
#pragma unroll
                    for (int t = 0; t < 4; t++) mma_f16(acc[i][t], al[i], bh[t]);
            }
        }
    }

    const int r_in = lane >> 2;
    const int c_in = (lane & 3) * 2;
#pragma unroll
    for (int i = 0; i < 4; i++) {
#pragma unroll
        for (int half = 0; half < 2; half++) {
            const int m = m0 + wm * 64 + i * 16 + r_in + half * 8;
            const int b = m >> 11, s = m & 2047;
#pragma unroll
            for (int t = 0; t < 4; t++) {
                const int n = n0 + wn * 32 + t * 8 + c_in;
                const float v0 = acc[i][t][half * 2], v1 = acc[i][t][half * 2 + 1];
                if (is_proj) {
                    const int h = n >> 6, d = n & 63;
                    if (z == 2) {
                        float* dst = g_v + ((size_t)(((b << 4) + h) << 6) + d) * 2048 + s;
                        dst[0] = v0; dst[2048] = v1;
                    } else {
                        float* O = (z == 0) ? g_q : g_k;
                        *(float2*)(O + (((size_t)((b << 4) + h) * 2048 + s) << 6) + d)
                            = make_float2(v0, v1);
                    }
                } else {
                    *(float2*)(Cout + (size_t)m * 1024 + n) = make_float2(v0, v1);
                }
            }
        }
    }
}

// ---------------------------------------------------------------------------
// Quantum block (V transposed: stride 2048 between wires)
// ---------------------------------------------------------------------------
__global__ void quantum_kernel(const float* __restrict__ params)
{
    const int id = blockIdx.x * 256 + threadIdx.x;
    if (id >= 3 * 65536) return;
    const int tensor = id >> 16;
    const int idx = id & 65535;
    float* vec;
    int stride;
    if (tensor == 0)      { vec = g_q + (size_t)idx * 64; stride = 1; }
    else if (tensor == 1) { vec = g_k + (size_t)idx * 64; stride = 1; }
    else {
        const int bh = idx >> 11, s = idx & 2047;
        vec = g_v + ((size_t)bh << 6) * 2048 + s; stride = 2048;
    }

    float ax[4];
#pragma unroll
    for (int w = 0; w < 4; w++) ax[w] = vec[w * stride];

    float sr[16], si[16];
#pragma unroll
    for (int i = 0; i < 16; i++) { sr[i] = 0.f; si[i] = 0.f; }
    sr[0] = 1.f;

#pragma unroll
    for (int w = 0; w < 4; w++) {
        const float a = 0.5f * ax[w];
        float s, c;
        sincosf(a, &s, &c);
        const int st = 8 >> w;
#pragma unroll
        for (int i = 0; i < 16; i++) {
            if (i & st) continue;
            const int j = i + st;
            const float xr = sr[i], xi = si[i], yr = sr[j], yi = si[j];
            sr[i] = c * xr + s * yi;  si[i] = c * xi - s * yr;
            sr[j] = c * yr + s * xi;  si[j] = c * yi - s * xr;
        }
    }
#pragma unroll
    for (int l = 0; l < 2; l++) {
#pragma unroll
        for (int w = 0; w < 4; w++) {
            const float phi = params[l * 12 + w * 3 + 0];
            const float th  = params[l * 12 + w * 3 + 1];
            const float om  = params[l * 12 + w * 3 + 2];
            float stt, ct;  sincosf(0.5f * th, &stt, &ct);
            float sap, cap; sincosf(0.5f * (phi + om), &sap, &cap);
            float sam, cam; sincosf(0.5f * (phi - om), &sam, &cam);
            const float m00r =  cap * ct,  m00i = -sap * ct;
            const float m01r = -cam * stt, m01i = -sam * stt;
            const float m10r =  cam * stt, m10i = -sam * stt;
            const float m11r =  cap * ct,  m11i =  sap * ct;
            const int st = 8 >> w;
#pragma unroll
            for (int i = 0; i < 16; i++) {
                if (i & st) continue;
                const int j = i + st;
                const float xr = sr[i], xi = si[i], yr = sr[j], yi = si[j];
                sr[i] = m00r * xr - m00i * xi + m01r * yr - m01i * yi;
                si[i] = m00r * xi + m00i * xr + m01r * yi + m01i * yr;
                sr[j] = m10r * xr - m10i * xi + m11r * yr - m11i * yi;
                si[j] = m10r * xi + m10i * xr + m11r * yi + m11i * yr;
            }
        }
#pragma unroll
        for (int r = 0; r < 4; r++) {
            float tr = sr[8 + r], ti = si[8 + r];
            sr[8 + r] = sr[12 + r];  si[8 + r] = si[12 + r];
            sr[12 + r] = tr;         si[12 + r] = ti;
        }
    }
    float ev[4] = {0.f, 0.f, 0.f, 0.f};
#pragma unroll
    for (int i = 0; i < 16; i++) {
        const float pr = sr[i] * sr[i] + si[i] * si[i];
#pragma unroll
        for (int w = 0; w < 4; w++)
            ev[w] += ((i >> (3 - w)) & 1) ? -pr : pr;
    }
#pragma unroll
    for (int w = 0; w < 4; w++) vec[w * stride] = ev[w];
}

// ---------------------------------------------------------------------------
// FA2 attention, fp16: scores 2-term (Q split x K single), PV 1-term
// (P single x V single). fp16 epilogue into g_aoh. Grid: (16, 32), 256 thr.
// smem buffer: Khi | Vhi  (2 x 64 rows x 144B)
// ---------------------------------------------------------------------------
#define AP      72
#define APB     (AP * 2)
#define KHI_O   0
#define VHI_O   (64 * APB)
#define ABUF_B  (2 * 64 * APB)         // 18432
#define ASMEM   (2 * ABUF_B)           // 36864

__global__ __launch_bounds__(256, 1)
void attention_mma_kernel()
{
    extern __shared__ char smem[];
    const uint32_t sb = smem_u32(smem);
    const int tid  = threadIdx.x;
    const int wid  = tid >> 5;
    const int lane = tid & 31;

    const int bh = blockIdx.y;
    const int q0 = blockIdx.x * 128;

    const float* qb = g_q + (size_t)bh * 2048 * 64;
    const float* kb = g_k + (size_t)bh * 2048 * 64;
    const float* vb = g_v + (size_t)bh * 64 * 2048;

    // Q staging: hi at sb+0 (18432 B), lo at sb+18432
    {
#pragma unroll
        for (int j = 0; j < 8; j++) {
            const int idx = j * 256 + tid;
            const int r = idx >> 4, c4 = idx & 15;
            float4 v = *(const float4*)(qb + (size_t)(q0 + r) * 64 + c4 * 4);
            uint2 h = cvt4_hi(v);
            uint2 l = cvt4_lo(v, h);
            const uint32_t ad = sb + (uint32_t)r * APB + (uint32_t)c4 * 8;
            STS64(ad, h);
            STS64(ad + 18432, l);
        }
    }
    __syncthreads();

    uint32_t qh[4][4], ql[4][4];
    {
        const uint32_t a0 = sb + (uint32_t)(wid * 16 + (lane & 15)) * APB
                          + (uint32_t)((lane >> 4) * 8) * 2;
#pragma unroll
        for (int j = 0; j < 4; j++) {
            ldmatrix_x4(qh[j], a0 + (uint32_t)(j * 16) * 2);
            ldmatrix_x4(ql[j], a0 + 18432 + (uint32_t)(j * 16) * 2);
        }
    }
    __syncthreads();

    float m0r = -1e30f, m1r = -1e30f, l0 = 0.f, l1 = 0.f;
    float o[8][4];
#pragma unroll
    for (int t = 0; t < 8; t++)
#pragma unroll
        for (int f = 0; f < 4; f++) o[t][f] = 0.f;

    const uint32_t brow4 = (uint32_t)((lane & 7) + ((lane >> 4) << 3)) * APB
                         + (uint32_t)(((lane >> 3) & 1) * 16);

    float4 pf[8];
    auto load_tile = [&](int kt) {
#pragma unroll
        for (int j = 0; j < 4; j++) {
            const int idx = j * 256 + tid;
            const int key = idx >> 4, c4 = idx & 15;
            pf[j] = *(const float4*)(kb + (size_t)(kt + key) * 64 + c4 * 4);
        }
#pragma unroll
        for (int j = 0; j < 4; j++) {
            const int idx = j * 256 + tid;
            const int d = idx >> 4, c4 = idx & 15;
            pf[4 + j] = *(const float4*)(vb + (size_t)d * 2048 + kt + c4 * 4);
        }
    };
    auto store_tile = [&](int buf) {
        const uint32_t bp = sb + (uint32_t)buf * ABUF_B;
#pragma unroll
        for (int j = 0; j < 4; j++) {      // K hi
            const int idx = j * 256 + tid;
            const int key = idx >> 4, c4 = idx & 15;
            uint2 h = cvt4_hi(pf[j]);
            STS64(bp + KHI_O + (uint32_t)key * APB + (uint32_t)c4 * 8, h);
        }
#pragma unroll
        for (int j = 0; j < 4; j++) {      // V hi
            const int idx = j * 256 + tid;
            const int d = idx >> 4, c4 = idx & 15;
            uint2 h = cvt4_hi(pf[4 + j]);
            STS64(bp + VHI_O + (uint32_t)d * APB + (uint32_t)c4 * 8, h);
        }
    };

    load_tile(0);
    store_tile(0);
    __syncthreads();

    for (int kt = 0; kt < 32; kt++) {
        const int buf = kt & 1;
        if (kt < 31) load_tile((kt + 1) * 64);

        const uint32_t bp = sb + (uint32_t)buf * ABUF_B;

        float s[8][4];
#pragma unroll
        for (int n = 0; n < 8; n++)
#pragma unroll
            for (int f = 0; f < 4; f++) s[n][f] = 0.f;

        // ---- scores: 2-term, paired-x4 K frags ----
#pragma unroll
        for (int j = 0; j < 4; j++) {
            const uint32_t kb2 = (uint32_t)(j * 32);
            uint32_t kh[8][2];
#pragma unroll
            for (int p = 0; p < 4; p++) {
                const uint32_t ro = (uint32_t)(p * 16) * APB;
                uint32_t t4[4];
                ldmatrix_x4(t4, bp + KHI_O + brow4 + ro + kb2);
                kh[2 * p][0] = t4[0];     kh[2 * p][1] = t4[1];
                kh[2 * p + 1][0] = t4[2]; kh[2 * p + 1][1] = t4[3];
            }
#pragma unroll
            for (int n = 0; n < 8; n++) mma_f16(s[n], qh[j], kh[n]);
#pragma unroll
            for (int n = 0; n < 8; n++) mma_f16(s[n], ql[j], kh[n]);
        }

        // ---- online softmax ----
        float tm0 = -1e30f, tm1 = -1e30f;
#pragma unroll
        for (int n = 0; n < 8; n++) {
#pragma unroll
            for (int f = 0; f < 4; f++) s[n][f] *= 0.125f;
            tm0 = fmaxf(tm0, fmaxf(s[n][0], s[n][1]));
            tm1 = fmaxf(tm1, fmaxf(s[n][2], s[n][3]));
        }
        tm0 = fmaxf(tm0, __shfl_xor_sync(0xffffffffu, tm0, 1));
        tm0 = fmaxf(tm0, __shfl_xor_sync(0xffffffffu, tm0, 2));
        tm1 = fmaxf(tm1, __shfl_xor_sync(0xffffffffu, tm1, 1));
        tm1 = fmaxf(tm1, __shfl_xor_sync(0xffffffffu, tm1, 2));
        const float mn0 = fmaxf(m0r, tm0), mn1 = fmaxf(m1r, tm1);
        const float a0 = __expf(m0r - mn0), a1 = __expf(m1r - mn1);
        m0r = mn0; m1r = mn1;

        float rs0 = 0.f, rs1 = 0.f;
#pragma unroll
        for (int n = 0; n < 8; n++) {
            s[n][0] = __expf(s[n][0] - mn0);
            s[n][1] = __expf(s[n][1] - mn0);
            s[n][2] = __expf(s[n][2] - mn1);
            s[n][3] = __expf(s[n][3] - mn1);
            rs0 += s[n][0] + s[n][1];
            rs1 += s[n][2] + s[n][3];
        }
        rs0 += __shfl_xor_sync(0xffffffffu, rs0, 1);
        rs0 += __shfl_xor_sync(0xffffffffu, rs0, 2);
        rs1 += __shfl_xor_sync(0xffffffffu, rs1, 1);
        rs1 += __shfl_xor_sync(0xffffffffu, rs1, 2);
        l0 = l0 * a0 + rs0;
        l1 = l1 * a1 + rs1;

#pragma unroll
        for (int t = 0; t < 8; t++) {
            o[t][0] *= a0; o[t][1] *= a0; o[t][2] *= a1; o[t][3] *= a1;
        }

        // ---- PV: 1-term (P single x V single), paired-x4 V frags ----
#pragma unroll
        for (int j = 0; j < 4; j++) {
            uint32_t ph[4];
            ph[0] = pack_f16x2(s[2 * j][0],     s[2 * j][1]);
            ph[1] = pack_f16x2(s[2 * j][2],     s[2 * j][3]);
            ph[2] = pack_f16x2(s[2 * j + 1][0], s[2 * j + 1][1]);
            ph[3] = pack_f16x2(s[2 * j + 1][2], s[2 * j + 1][3]);
            const uint32_t kb2 = (uint32_t)(j * 32);
            uint32_t vh[8][2];
#pragma unroll
            for (int p = 0; p < 4; p++) {
                const uint32_t ro = (uint32_t)(p * 16) * APB;
                uint32_t t4[4];
                ldmatrix_x4(t4, bp + VHI_O + brow4 + ro + kb2);
                vh[2 * p][0] = t4[0];     vh[2 * p][1] = t4[1];
                vh[2 * p + 1][0] = t4[2]; vh[2 * p + 1][1] = t4[3];
            }
#pragma unroll
            for (int t = 0; t < 8; t++) mma_f16(o[t], ph, vh[t]);
        }

        if (kt < 31) {
            store_tile(buf ^ 1);
            __syncthreads();
        }
    }

    // ---- fp16 epilogue into g_aoh [b][s][h*64+d] ----
    const int b = bh >> 4, h = bh & 15;
    const int r0 = q0 + wid * 16 + (lane >> 2);
    const int c0 = h * 64 + (lane & 3) * 2;
    const float il0 = 1.f / l0, il1 = 1.f / l1;
    uint32_t* aoh = (uint32_t*)g_aoh;
#pragma unroll
    for (int t = 0; t < 8; t++) {
        const uint32_t p0 = pack_f16x2(o[t][0] * il0, o[t][1] * il0);
        const uint32_t p1 = pack_f16x2(o[t][2] * il1, o[t][3] * il1);
        aoh[((size_t)(b * 2048 + r0) * 1024 + c0 + t * 8) >> 1]       = p0;
        aoh[((size_t)(b * 2048 + r0 + 8) * 1024 + c0 + t * 8) >> 1]   = p1;
    }
}

// ---------------------------------------------------------------------------
extern "C" void kernel_launch(void* const* d_in, const int* in_sizes, int n_in,
                              void* d_out, int out_size)
{
    const float* x      = (const float*)d_in[0];
    const float* params = (const float*)d_in[1];
    const float* wq     = (const float*)d_in[2];
    const float* wk     = (const float*)d_in[3];
    const float* wv     = (const float*)d_in[4];
    const float* wo     = (const float*)d_in[5];
    float* out = (float*)d_out;

    cudaFuncSetAttribute(gemm_mma_kernel,
                         cudaFuncAttributeMaxDynamicSharedMemorySize, GSMEM);
    cudaFuncSetAttribute(attention_mma_kernel,
                         cudaFuncAttributeMaxDynamicSharedMemorySize, ASMEM);

    __half *wh, *xhi, *xlo, *aoh;
    cudaGetSymbolAddress((void**)&wh,  g_wh);
    cudaGetSymbolAddress((void**)&xhi, g_xhi);
    cudaGetSymbolAddress((void**)&xlo, g_xlo);
    cudaGetSymbolAddress((void**)&aoh, g_aoh);

    split2_kernel<<<4096, 256>>>(x, xhi, xlo, 1048576);
    cvt1_kernel<<<1024, 256>>>(wq, wh + 0 * 1048576, 262144);
    cvt1_kernel<<<1024, 256>>>(wk, wh + 1 * 1048576, 262144);
    cvt1_kernel<<<1024, 256>>>(wv, wh + 2 * 1048576, 262144);
    cvt1_kernel<<<1024, 256>>>(wo, wh + 3 * 1048576, 262144);

    gemm_mma_kernel<<<dim3(8, 32, 3), 256, GSMEM>>>(xhi, xlo, nullptr, 1);
    quantum_kernel<<<768, 256>>>(params);
    attention_mma_kernel<<<dim3(16, 32), 256, ASMEM>>>();
    gemm_mma_kernel<<<dim3(8, 32, 1), 256, GSMEM>>>(aoh, nullptr, out, 0);
}

// round 9
// speedup vs baseline: 5.6684x; 1.1958x over previous
#include <cuda_runtime.h>
#include <cuda_fp16.h>
#include <cstdint>

// ---------------------------------------------------------------------------
// QuantumAttention  (B=2, S=2048, E=1024, H=16, dk=64, NQ=4, NL=2)
// Round 9: QKV A-side 1-term (x single-rounded fp16). All GEMMs now 1-term
// (A single x B single). Attention: scores 2-term, PV 1-term (as R8).
// ---------------------------------------------------------------------------

__device__ float g_q [2*16*2048*64];   // [b][h][s][d]
__device__ float g_k [2*16*2048*64];   // [b][h][s][d]
__device__ float g_v [2*16*2048*64];   // [b][h][d][s]   (transposed!)

__device__ __half g_aoh [4096*1024];   // attention out, fp16, [b][s][h*64+d]
__device__ __half g_xh  [4096*1024];   // x, single-rounded fp16
__device__ __half g_wh  [4*1024*1024]; // q,k,v,o packed, single-rounded

// ---------------- helpers ---------------------------------------------------
__device__ __forceinline__ uint32_t smem_u32(const void* p) {
    uint32_t a;
    asm("{ .reg .u64 t; cvta.to.shared.u64 t, %1; cvt.u32.u64 %0, t; }" : "=r"(a) : "l"(p));
    return a;
}
#define CP_ASYNC16(dst, src) \
    asm volatile("cp.async.cg.shared.global [%0], [%1], 16;" :: "r"(dst), "l"(src) : "memory")
#define CP_COMMIT() asm volatile("cp.async.commit_group;" ::: "memory")
#define CP_WAIT(n)  asm volatile("cp.async.wait_group %0;" :: "n"(n) : "memory")

__device__ __forceinline__ void ldmatrix_x4(uint32_t (&r)[4], uint32_t addr) {
    asm volatile("ldmatrix.sync.aligned.m8n8.x4.shared.b16 {%0,%1,%2,%3}, [%4];"
                 : "=r"(r[0]), "=r"(r[1]), "=r"(r[2]), "=r"(r[3]) : "r"(addr));
}
__device__ __forceinline__ void mma_f16(float (&d)[4], const uint32_t (&a)[4],
                                        const uint32_t (&b)[2]) {
    asm volatile("mma.sync.aligned.m16n8k16.row.col.f32.f16.f16.f32 "
                 "{%0,%1,%2,%3}, {%4,%5,%6,%7}, {%8,%9}, {%0,%1,%2,%3};"
                 : "+f"(d[0]), "+f"(d[1]), "+f"(d[2]), "+f"(d[3])
                 : "r"(a[0]), "r"(a[1]), "r"(a[2]), "r"(a[3]), "r"(b[0]), "r"(b[1]));
}
__device__ __forceinline__ uint32_t pack_f16x2(float lo, float hi) {
    uint32_t r;
    asm("cvt.rn.f16x2.f32 %0, %1, %2;" : "=r"(r) : "f"(hi), "f"(lo));
    return r;
}
__device__ __forceinline__ uint2 cvt4_hi(const float4 v) {
    return make_uint2(pack_f16x2(v.x, v.y), pack_f16x2(v.z, v.w));
}
__device__ __forceinline__ uint2 cvt4_lo(const float4 v, const uint2 hi) {
    __half2 h0 = *reinterpret_cast<const __half2*>(&hi.x);
    __half2 h1 = *reinterpret_cast<const __half2*>(&hi.y);
    float2 f0 = __half22float2(h0);
    float2 f1 = __half22float2(h1);
    return make_uint2(pack_f16x2(v.x - f0.x, v.y - f0.y),
                      pack_f16x2(v.z - f1.x, v.w - f1.y));
}
#define STS64(ad, v) \
    asm volatile("st.shared.v2.b32 [%0], {%1, %2};" :: "r"(ad), "r"((v).x), "r"((v).y) : "memory")

// ---------------------------------------------------------------------------
// fp32 -> f16 single
// ---------------------------------------------------------------------------
__global__ void cvt1_kernel(const float* __restrict__ src,
                            __half* __restrict__ dst, int n4)
{
    const int i = blockIdx.x * 256 + threadIdx.x;
    if (i >= n4) return;
    float4 v = ((const float4*)src)[i];
    ((uint2*)dst)[i] = cvt4_hi(v);
}

// ---------------------------------------------------------------------------
// mma.sync GEMM, 1-term:  C[m][n] = sum_k A[m][k] * B[n][k]
// CTA 128x128, K-chunk 32, 3-stage ring. Smem: A | B per stage.
// ---------------------------------------------------------------------------
#define PITCH   40
#define PITCHB  (PITCH * 2)
#define MAT_B   (128 * PITCHB)          // 10240
#define STAGE_B (2 * MAT_B)             // 20480 (A, B)
#define NSTG    3
#define GSMEM   (NSTG * STAGE_B)        // 61440

__global__ __launch_bounds__(256, 2)
void gemm_mma_kernel(const __half* __restrict__ A,
                     float* __restrict__ Cout, int is_proj)
{
    extern __shared__ char smem[];
    const uint32_t sb = smem_u32(smem);
    const int tid  = threadIdx.x;
    const int wid  = tid >> 5;
    const int lane = tid & 31;

    const int z  = blockIdx.z;
    const int m0 = blockIdx.y * 128;
    const int n0 = blockIdx.x * 128;
    const size_t woff = ((size_t)(is_proj ? z : 3)) << 20;

    const __half* gsrc[2] = { A + (size_t)m0 * 1024,
                              g_wh + woff + (size_t)n0 * 1024 };

    const int wm = wid & 1;
    const int wn = wid >> 1;
    const uint32_t a_addr0 = (uint32_t)(wm * 64 + (lane & 15)) * PITCHB
                           + (uint32_t)((lane >> 4) * 8) * 2;
    const uint32_t b_addr0 = (uint32_t)(wn * 32 + (lane & 7) + ((lane >> 4) << 3)) * PITCHB
                           + (uint32_t)(((lane >> 3) & 1) * 16);

    float acc[4][4][4];
#pragma unroll
    for (int i = 0; i < 4; i++)
#pragma unroll
        for (int t = 0; t < 4; t++)
#pragma unroll
            for (int f = 0; f < 4; f++) acc[i][t][f] = 0.f;

    auto load_stage = [&](int ch, int stg) {
        const int k0 = ch * 32;
        const uint32_t dst = sb + (uint32_t)stg * STAGE_B;
#pragma unroll
        for (int j = 0; j < 4; j++) {
            const int idx = j * 256 + tid;          // 0..1023
            const int mat = idx >> 9;               // 0..1
            const int w   = idx & 511;
            const int row = w >> 2;
            const int c16 = w & 3;
            CP_ASYNC16(dst + (uint32_t)mat * MAT_B + (uint32_t)row * PITCHB
                           + (uint32_t)c16 * 16,
                       gsrc[mat] + (size_t)row * 1024 + k0 + c16 * 8);
        }
        CP_COMMIT();
    };

    load_stage(0, 0);
    load_stage(1, 1);

    for (int ch = 0; ch < 32; ch++) {
        CP_WAIT(1);
        __syncthreads();
        if (ch + 2 < 32) load_stage(ch + 2, (ch + 2) % NSTG);

        const uint32_t stg = sb + (uint32_t)(ch % NSTG) * STAGE_B;
#pragma unroll
        for (int ks = 0; ks < 2; ks++) {
            const uint32_t kb = (uint32_t)(ks * 32);
            uint32_t ah[4][4];
#pragma unroll
            for (int i = 0; i < 4; i++) {
                const uint32_t ro = (uint32_t)(i * 16) * PITCHB;
                ldmatrix_x4(ah[i], stg + 0 * MAT_B + a_addr0 + ro + kb);
            }
            uint32_t bh[4][2];
#pragma unroll
            for (int p = 0; p < 2; p++) {
                const uint32_t ro = (uint32_t)(p * 16) * PITCHB;
                uint32_t t4[4];
                ldmatrix_x4(t4, stg + 1 * MAT_B + b_addr0 + ro + kb);
                bh[2 * p][0] = t4[0];     bh[2 * p][1] = t4[1];
                bh[2 * p + 1][0] = t4[2]; bh[2 * p + 1][1] = t4[3];
            }
#pragma unroll
            for (int i = 0; i < 4; i++)
#pragma unroll
                for (int t = 0; t < 4; t++) mma_f16(acc[i][t], ah[i], bh[t]);
        }
    }

    const int r_in = lane >> 2;
    const int c_in = (lane & 3) * 2;
#pragma unroll
    for (int i = 0; i < 4; i++) {
#pragma unroll
        for (int half = 0; half < 2; half++) {
            const int m = m0 + wm * 64 + i * 16 + r_in + half * 8;
            const int b = m >> 11, s = m & 2047;
#pragma unroll
            for (int t = 0; t < 4; t++) {
                const int n = n0 + wn * 32 + t * 8 + c_in;
                const float v0 = acc[i][t][half * 2], v1 = acc[i][t][half * 2 + 1];
                if (is_proj) {
                    const int h = n >> 6, d = n & 63;
                    if (z == 2) {
                        float* dst = g_v + ((size_t)(((b << 4) + h) << 6) + d) * 2048 + s;
                        dst[0] = v0; dst[2048] = v1;
                    } else {
                        float* O = (z == 0) ? g_q : g_k;
                        *(float2*)(O + (((size_t)((b << 4) + h) * 2048 + s) << 6) + d)
                            = make_float2(v0, v1);
                    }
                } else {
                    *(float2*)(Cout + (size_t)m * 1024 + n) = make_float2(v0, v1);
                }
            }
        }
    }
}

// ---------------------------------------------------------------------------
// Quantum block (V transposed: stride 2048 between wires)
// ---------------------------------------------------------------------------
__global__ void quantum_kernel(const float* __restrict__ params)
{
    const int id = blockIdx.x * 256 + threadIdx.x;
    if (id >= 3 * 65536) return;
    const int tensor = id >> 16;
    const int idx = id & 65535;
    float* vec;
    int stride;
    if (tensor == 0)      { vec = g_q + (size_t)idx * 64; stride = 1; }
    else if (tensor == 1) { vec = g_k + (size_t)idx * 64; stride = 1; }
    else {
        const int bh = idx >> 11, s = idx & 2047;
        vec = g_v + ((size_t)bh << 6) * 2048 + s; stride = 2048;
    }

    float ax[4];
#pragma unroll
    for (int w = 0; w < 4; w++) ax[w] = vec[w * stride];

    float sr[16], si[16];
#pragma unroll
    for (int i = 0; i < 16; i++) { sr[i] = 0.f; si[i] = 0.f; }
    sr[0] = 1.f;

#pragma unroll
    for (int w = 0; w < 4; w++) {
        const float a = 0.5f * ax[w];
        float s, c;
        sincosf(a, &s, &c);
        const int st = 8 >> w;
#pragma unroll
        for (int i = 0; i < 16; i++) {
            if (i & st) continue;
            const int j = i + st;
            const float xr = sr[i], xi = si[i], yr = sr[j], yi = si[j];
            sr[i] = c * xr + s * yi;  si[i] = c * xi - s * yr;
            sr[j] = c * yr + s * xi;  si[j] = c * yi - s * xr;
        }
    }
#pragma unroll
    for (int l = 0; l < 2; l++) {
#pragma unroll
        for (int w = 0; w < 4; w++) {
            const float phi = params[l * 12 + w * 3 + 0];
            const float th  = params[l * 12 + w * 3 + 1];
            const float om  = params[l * 12 + w * 3 + 2];
            float stt, ct;  sincosf(0.5f * th, &stt, &ct);
            float sap, cap; sincosf(0.5f * (phi + om), &sap, &cap);
            float sam, cam; sincosf(0.5f * (phi - om), &sam, &cam);
            const float m00r =  cap * ct,  m00i = -sap * ct;
            const float m01r = -cam * stt, m01i = -sam * stt;
            const float m10r =  cam * stt, m10i = -sam * stt;
            const float m11r =  cap * ct,  m11i =  sap * ct;
            const int st = 8 >> w;
#pragma unroll
            for (int i = 0; i < 16; i++) {
                if (i & st) continue;
                const int j = i + st;
                const float xr = sr[i], xi = si[i], yr = sr[j], yi = si[j];
                sr[i] = m00r * xr - m00i * xi + m01r * yr - m01i * yi;
                si[i] = m00r * xi + m00i * xr + m01r * yi + m01i * yr;
                sr[j] = m10r * xr - m10i * xi + m11r * yr - m11i * yi;
                si[j] = m10r * xi + m10i * xr + m11r * yi + m11i * yr;
            }
        }
#pragma unroll
        for (int r = 0; r < 4; r++) {
            float tr = sr[8 + r], ti = si[8 + r];
            sr[8 + r] = sr[12 + r];  si[8 + r] = si[12 + r];
            sr[12 + r] = tr;         si[12 + r] = ti;
        }
    }
    float ev[4] = {0.f, 0.f, 0.f, 0.f};
#pragma unroll
    for (int i = 0; i < 16; i++) {
        const float pr = sr[i] * sr[i] + si[i] * si[i];
#pragma unroll
        for (int w = 0; w < 4; w++)
            ev[w] += ((i >> (3 - w)) & 1) ? -pr : pr;
    }
#pragma unroll
    for (int w = 0; w < 4; w++) vec[w * stride] = ev[w];
}

// ---------------------------------------------------------------------------
// FA2 attention (as R8): scores 2-term (Q split x K single), PV 1-term.
// fp16 epilogue into g_aoh. Grid: (16, 32), 256 thr.
// ---------------------------------------------------------------------------
#define AP      72
#define APB     (AP * 2)
#define KHI_O   0
#define VHI_O   (64 * APB)
#define ABUF_B  (2 * 64 * APB)         // 18432
#define ASMEM   (2 * ABUF_B)           // 36864

__global__ __launch_bounds__(256, 1)
void attention_mma_kernel()
{
    extern __shared__ char smem[];
    const uint32_t sb = smem_u32(smem);
    const int tid  = threadIdx.x;
    const int wid  = tid >> 5;
    const int lane = tid & 31;

    const int bh = blockIdx.y;
    const int q0 = blockIdx.x * 128;

    const float* qb = g_q + (size_t)bh * 2048 * 64;
    const float* kb = g_k + (size_t)bh * 2048 * 64;
    const float* vb = g_v + (size_t)bh * 64 * 2048;

    {
#pragma unroll
        for (int j = 0; j < 8; j++) {
            const int idx = j * 256 + tid;
            const int r = idx >> 4, c4 = idx & 15;
            float4 v = *(const float4*)(qb + (size_t)(q0 + r) * 64 + c4 * 4);
            uint2 h = cvt4_hi(v);
            uint2 l = cvt4_lo(v, h);
            const uint32_t ad = sb + (uint32_t)r * APB + (uint32_t)c4 * 8;
            STS64(ad, h);
            STS64(ad + 18432, l);
        }
    }
    __syncthreads();

    uint32_t qh[4][4], ql[4][4];
    {
        const uint32_t a0 = sb + (uint32_t)(wid * 16 + (lane & 15)) * APB
                          + (uint32_t)((lane >> 4) * 8) * 2;
#pragma unroll
        for (int j = 0; j < 4; j++) {
            ldmatrix_x4(qh[j], a0 + (uint32_t)(j * 16) * 2);
            ldmatrix_x4(ql[j], a0 + 18432 + (uint32_t)(j * 16) * 2);
        }
    }
    __syncthreads();

    float m0r = -1e30f, m1r = -1e30f, l0 = 0.f, l1 = 0.f;
    float o[8][4];
#pragma unroll
    for (int t = 0; t < 8; t++)
#pragma unroll
        for (int f = 0; f < 4; f++) o[t][f] = 0.f;

    const uint32_t brow4 = (uint32_t)((lane & 7) + ((lane >> 4) << 3)) * APB
                         + (uint32_t)(((lane >> 3) & 1) * 16);

    float4 pf[8];
    auto load_tile = [&](int kt) {
#pragma unroll
        for (int j = 0; j < 4; j++) {
            const int idx = j * 256 + tid;
            const int key = idx >> 4, c4 = idx & 15;
            pf[j] = *(const float4*)(kb + (size_t)(kt + key) * 64 + c4 * 4);
        }
#pragma unroll
        for (int j = 0; j < 4; j++) {
            const int idx = j * 256 + tid;
            const int d = idx >> 4, c4 = idx & 15;
            pf[4 + j] = *(const float4*)(vb + (size_t)d * 2048 + kt + c4 * 4);
        }
    };
    auto store_tile = [&](int buf) {
        const uint32_t bp = sb + (uint32_t)buf * ABUF_B;
#pragma unroll
        for (int j = 0; j < 4; j++) {
            const int idx = j * 256 + tid;
            const int key = idx >> 4, c4 = idx & 15;
            uint2 h = cvt4_hi(pf[j]);
            STS64(bp + KHI_O + (uint32_t)key * APB + (uint32_t)c4 * 8, h);
        }
#pragma unroll
        for (int j = 0; j < 4; j++) {
            const int idx = j * 256 + tid;
            const int d = idx >> 4, c4 = idx & 15;
            uint2 h = cvt4_hi(pf[4 + j]);
            STS64(bp + VHI_O + (uint32_t)d * APB + (uint32_t)c4 * 8, h);
        }
    };

    load_tile(0);
    store_tile(0);
    __syncthreads();

    for (int kt = 0; kt < 32; kt++) {
        const int buf = kt & 1;
        if (kt < 31) load_tile((kt + 1) * 64);

        const uint32_t bp = sb + (uint32_t)buf * ABUF_B;

        float s[8][4];
#pragma unroll
        for (int n = 0; n < 8; n++)
#pragma unroll
            for (int f = 0; f < 4; f++) s[n][f] = 0.f;

#pragma unroll
        for (int j = 0; j < 4; j++) {
            const uint32_t kb2 = (uint32_t)(j * 32);
            uint32_t kh[8][2];
#pragma unroll
            for (int p = 0; p < 4; p++) {
                const uint32_t ro = (uint32_t)(p * 16) * APB;
                uint32_t t4[4];
                ldmatrix_x4(t4, bp + KHI_O + brow4 + ro + kb2);
                kh[2 * p][0] = t4[0];     kh[2 * p][1] = t4[1];
                kh[2 * p + 1][0] = t4[2]; kh[2 * p + 1][1] = t4[3];
            }
#pragma unroll
            for (int n = 0; n < 8; n++) mma_f16(s[n], qh[j], kh[n]);
#pragma unroll
            for (int n = 0; n < 8; n++) mma_f16(s[n], ql[j], kh[n]);
        }

        float tm0 = -1e30f, tm1 = -1e30f;
#pragma unroll
        for (int n = 0; n < 8; n++) {
#pragma unroll
            for (int f = 0; f < 4; f++) s[n][f] *= 0.125f;
            tm0 = fmaxf(tm0, fmaxf(s[n][0], s[n][1]));
            tm1 = fmaxf(tm1, fmaxf(s[n][2], s[n][3]));
        }
        tm0 = fmaxf(tm0, __shfl_xor_sync(0xffffffffu, tm0, 1));
        tm0 = fmaxf(tm0, __shfl_xor_sync(0xffffffffu, tm0, 2));
        tm1 = fmaxf(tm1, __shfl_xor_sync(0xffffffffu, tm1, 1));
        tm1 = fmaxf(tm1, __shfl_xor_sync(0xffffffffu, tm1, 2));
        const float mn0 = fmaxf(m0r, tm0), mn1 = fmaxf(m1r, tm1);
        const float a0 = __expf(m0r - mn0), a1 = __expf(m1r - mn1);
        m0r = mn0; m1r = mn1;

        float rs0 = 0.f, rs1 = 0.f;
#pragma unroll
        for (int n = 0; n < 8; n++) {
            s[n][0] = __expf(s[n][0] - mn0);
            s[n][1] = __expf(s[n][1] - mn0);
            s[n][2] = __expf(s[n][2] - mn1);
            s[n][3] = __expf(s[n][3] - mn1);
            rs0 += s[n][0] + s[n][1];
            rs1 += s[n][2] + s[n][3];
        }
        rs0 += __shfl_xor_sync(0xffffffffu, rs0, 1);
        rs0 += __shfl_xor_sync(0xffffffffu, rs0, 2);
        rs1 += __shfl_xor_sync(0xffffffffu, rs1, 1);
        rs1 += __shfl_xor_sync(0xffffffffu, rs1, 2);
        l0 = l0 * a0 + rs0;
        l1 = l1 * a1 + rs1;

#pragma unroll
        for (int t = 0; t < 8; t++) {
            o[t][0] *= a0; o[t][1] *= a0; o[t][2] *= a1; o[t][3] *= a1;
        }

#pragma unroll
        for (int j = 0; j < 4; j++) {
            uint32_t ph[4];
            ph[0] = pack_f16x2(s[2 * j][0],     s[2 * j][1]);
            ph[1] = pack_f16x2(s[2 * j][2],     s[2 * j][3]);
            ph[2] = pack_f16x2(s[2 * j + 1][0], s[2 * j + 1][1]);
            ph[3] = pack_f16x2(s[2 * j + 1][2], s[2 * j + 1][3]);
            const uint32_t kb2 = (uint32_t)(j * 32);
            uint32_t vh[8][2];
#pragma unroll
            for (int p = 0; p < 4; p++) {
                const uint32_t ro = (uint32_t)(p * 16) * APB;
                uint32_t t4[4];
                ldmatrix_x4(t4, bp + VHI_O + brow4 + ro + kb2);
                vh[2 * p][0] = t4[0];     vh[2 * p][1] = t4[1];
                vh[2 * p + 1][0] = t4[2]; vh[2 * p + 1][1] = t4[3];
            }
#pragma unroll
            for (int t = 0; t < 8; t++) mma_f16(o[t], ph, vh[t]);
        }

        if (kt < 31) {
            store_tile(buf ^ 1);
            __syncthreads();
        }
    }

    const int b = bh >> 4, h = bh & 15;
    const int r0 = q0 + wid * 16 + (lane >> 2);
    const int c0 = h * 64 + (lane & 3) * 2;
    const float il0 = 1.f / l0, il1 = 1.f / l1;
    uint32_t* aoh = (uint32_t*)g_aoh;
#pragma unroll
    for (int t = 0; t < 8; t++) {
        const uint32_t p0 = pack_f16x2(o[t][0] * il0, o[t][1] * il0);
        const uint32_t p1 = pack_f16x2(o[t][2] * il1, o[t][3] * il1);
        aoh[((size_t)(b * 2048 + r0) * 1024 + c0 + t * 8) >> 1]     = p0;
        aoh[((size_t)(b * 2048 + r0 + 8) * 1024 + c0 + t * 8) >> 1] = p1;
    }
}

// ---------------------------------------------------------------------------
extern "C" void kernel_launch(void* const* d_in, const int* in_sizes, int n_in,
                              void* d_out, int out_size)
{
    const float* x      = (const float*)d_in[0];
    const float* params = (const float*)d_in[1];
    const float* wq     = (const float*)d_in[2];
    const float* wk     = (const float*)d_in[3];
    const float* wv     = (const float*)d_in[4];
    const float* wo     = (const float*)d_in[5];
    float* out = (float*)d_out;

    cudaFuncSetAttribute(gemm_mma_kernel,
                         cudaFuncAttributeMaxDynamicSharedMemorySize, GSMEM);
    cudaFuncSetAttribute(attention_mma_kernel,
                         cudaFuncAttributeMaxDynamicSharedMemorySize, ASMEM);

    __half *wh, *xh, *aoh;
    cudaGetSymbolAddress((void**)&wh,  g_wh);
    cudaGetSymbolAddress((void**)&xh,  g_xh);
    cudaGetSymbolAddress((void**)&aoh, g_aoh);

    cvt1_kernel<<<4096, 256>>>(x,  xh, 1048576);
    cvt1_kernel<<<1024, 256>>>(wq, wh + 0 * 1048576, 262144);
    cvt1_kernel<<<1024, 256>>>(wk, wh + 1 * 1048576, 262144);
    cvt1_kernel<<<1024, 256>>>(wv, wh + 2 * 1048576, 262144);
    cvt1_kernel<<<1024, 256>>>(wo, wh + 3 * 1048576, 262144);

    gemm_mma_kernel<<<dim3(8, 32, 3), 256, GSMEM>>>(xh, nullptr, 1);
    quantum_kernel<<<768, 256>>>(params);
    attention_mma_kernel<<<dim3(16, 32), 256, ASMEM>>>();
    gemm_mma_kernel<<<dim3(8, 32, 1), 256, GSMEM>>>(aoh, out, 0);
}

// round 10
// speedup vs baseline: 6.4517x; 1.1382x over previous
#include <cuda_runtime.h>
#include <cuda_fp16.h>
#include <cstdint>

// ---------------------------------------------------------------------------
// QuantumAttention  (B=2, S=2048, E=1024, H=16, dk=64, NQ=4, NL=2)
// Round 10: all-fp16 dataflow. Q/K/V stored fp16 by projection epilogue
// (V transposed); scores 1-term; quantum on fp16; fused cvt launch.
// ---------------------------------------------------------------------------

__device__ __half g_qh [2*16*2048*64];   // [b][h][s][d]
__device__ __half g_kh [2*16*2048*64];   // [b][h][s][d]
__device__ __half g_vh [2*16*2048*64];   // [b][h][d][s]  (transposed!)
__device__ __half g_aoh[4096*1024];      // attention out [b][s][h*64+d]
__device__ __half g_xh [4096*1024];      // x single-rounded
__device__ __half g_wh [4*1024*1024];    // q,k,v,o packed

// ---------------- helpers ---------------------------------------------------
__device__ __forceinline__ uint32_t smem_u32(const void* p) {
    uint32_t a;
    asm("{ .reg .u64 t; cvta.to.shared.u64 t, %1; cvt.u32.u64 %0, t; }" : "=r"(a) : "l"(p));
    return a;
}
#define CP_ASYNC16(dst, src) \
    asm volatile("cp.async.cg.shared.global [%0], [%1], 16;" :: "r"(dst), "l"(src) : "memory")
#define CP_COMMIT() asm volatile("cp.async.commit_group;" ::: "memory")
#define CP_WAIT(n)  asm volatile("cp.async.wait_group %0;" :: "n"(n) : "memory")

__device__ __forceinline__ void ldmatrix_x4(uint32_t (&r)[4], uint32_t addr) {
    asm volatile("ldmatrix.sync.aligned.m8n8.x4.shared.b16 {%0,%1,%2,%3}, [%4];"
                 : "=r"(r[0]), "=r"(r[1]), "=r"(r[2]), "=r"(r[3]) : "r"(addr));
}
__device__ __forceinline__ void mma_f16(float (&d)[4], const uint32_t (&a)[4],
                                        const uint32_t (&b)[2]) {
    asm volatile("mma.sync.aligned.m16n8k16.row.col.f32.f16.f16.f32 "
                 "{%0,%1,%2,%3}, {%4,%5,%6,%7}, {%8,%9}, {%0,%1,%2,%3};"
                 : "+f"(d[0]), "+f"(d[1]), "+f"(d[2]), "+f"(d[3])
                 : "r"(a[0]), "r"(a[1]), "r"(a[2]), "r"(a[3]), "r"(b[0]), "r"(b[1]));
}
__device__ __forceinline__ uint32_t pack_f16x2(float lo, float hi) {
    uint32_t r;
    asm("cvt.rn.f16x2.f32 %0, %1, %2;" : "=r"(r) : "f"(hi), "f"(lo));
    return r;
}
__device__ __forceinline__ uint2 cvt4_hi(const float4 v) {
    return make_uint2(pack_f16x2(v.x, v.y), pack_f16x2(v.z, v.w));
}
#define STS128(ad, v)                                                           \
    asm volatile("st.shared.v4.b32 [%0], {%1, %2, %3, %4};"                     \
        :: "r"(ad), "r"((v).x), "r"((v).y), "r"((v).z), "r"((v).w) : "memory")

// ---------------------------------------------------------------------------
// Fused fp32 -> fp16 convert: x (1M float4 units) + 4 weights (256K each)
// ---------------------------------------------------------------------------
__global__ void cvt_all_kernel(const float* __restrict__ x,
                               const float* __restrict__ wq,
                               const float* __restrict__ wk,
                               const float* __restrict__ wv,
                               const float* __restrict__ wo)
{
    const int i = blockIdx.x * 256 + threadIdx.x;     // 0..2097151
    const float* src;
    __half* dst;
    int off;
    if (i < 1048576) {
        src = x; dst = g_xh; off = i;
    } else {
        const int j = i - 1048576;
        const int sel = j >> 18;
        off = j & 262143;
        const float* ws[4] = {wq, wk, wv, wo};
        src = ws[sel];
        dst = g_wh + (size_t)sel * 1048576;
    }
    float4 v = ((const float4*)src)[off];
    ((uint2*)dst)[off] = cvt4_hi(v);
}

// ---------------------------------------------------------------------------
// mma.sync GEMM, 1-term:  C[m][n] = sum_k A[m][k] * B[n][k]
// is_proj=1: epilogue writes fp16 into g_qh/g_kh/g_vh. is_proj=0: fp32 Cout.
// ---------------------------------------------------------------------------
#define PITCH   40
#define PITCHB  (PITCH * 2)
#define MAT_B   (128 * PITCHB)
#define STAGE_B (2 * MAT_B)
#define NSTG    3
#define GSMEM   (NSTG * STAGE_B)

__global__ __launch_bounds__(256, 2)
void gemm_mma_kernel(const __half* __restrict__ A,
                     float* __restrict__ Cout, int is_proj)
{
    extern __shared__ char smem[];
    const uint32_t sb = smem_u32(smem);
    const int tid  = threadIdx.x;
    const int wid  = tid >> 5;
    const int lane = tid & 31;

    const int z  = blockIdx.z;
    const int m0 = blockIdx.y * 128;
    const int n0 = blockIdx.x * 128;
    const size_t woff = ((size_t)(is_proj ? z : 3)) << 20;

    const __half* gsrc[2] = { A + (size_t)m0 * 1024,
                              g_wh + woff + (size_t)n0 * 1024 };

    const int wm = wid & 1;
    const int wn = wid >> 1;
    const uint32_t a_addr0 = (uint32_t)(wm * 64 + (lane & 15)) * PITCHB
                           + (uint32_t)((lane >> 4) * 8) * 2;
    const uint32_t b_addr0 = (uint32_t)(wn * 32 + (lane & 7) + ((lane >> 4) << 3)) * PITCHB
                           + (uint32_t)(((lane >> 3) & 1) * 16);

    float acc[4][4][4];
#pragma unroll
    for (int i = 0; i < 4; i++)
#pragma unroll
        for (int t = 0; t < 4; t++)
#pragma unroll
            for (int f = 0; f < 4; f++) acc[i][t][f] = 0.f;

    auto load_stage = [&](int ch, int stg) {
        const int k0 = ch * 32;
        const uint32_t dst = sb + (uint32_t)stg * STAGE_B;
#pragma unroll
        for (int j = 0; j < 4; j++) {
            const int idx = j * 256 + tid;
            const int mat = idx >> 9;
            const int w   = idx & 511;
            const int row = w >> 2;
            const int c16 = w & 3;
            CP_ASYNC16(dst + (uint32_t)mat * MAT_B + (uint32_t)row * PITCHB
                           + (uint32_t)c16 * 16,
                       gsrc[mat] + (size_t)row * 1024 + k0 + c16 * 8);
        }
        CP_COMMIT();
    };

    load_stage(0, 0);
    load_stage(1, 1);

    for (int ch = 0; ch < 32; ch++) {
        CP_WAIT(1);
        __syncthreads();
        if (ch + 2 < 32) load_stage(ch + 2, (ch + 2) % NSTG);

        const uint32_t stg = sb + (uint32_t)(ch % NSTG) * STAGE_B;
#pragma unroll
        for (int ks = 0; ks < 2; ks++) {
            const uint32_t kb = (uint32_t)(ks * 32);
            uint32_t ah[4][4];
#pragma unroll
            for (int i = 0; i < 4; i++) {
                const uint32_t ro = (uint32_t)(i * 16) * PITCHB;
                ldmatrix_x4(ah[i], stg + 0 * MAT_B + a_addr0 + ro + kb);
            }
            uint32_t bh[4][2];
#pragma unroll
            for (int p = 0; p < 2; p++) {
                const uint32_t ro = (uint32_t)(p * 16) * PITCHB;
                uint32_t t4[4];
                ldmatrix_x4(t4, stg + 1 * MAT_B + b_addr0 + ro + kb);
                bh[2 * p][0] = t4[0];     bh[2 * p][1] = t4[1];
                bh[2 * p + 1][0] = t4[2]; bh[2 * p + 1][1] = t4[3];
            }
#pragma unroll
            for (int i = 0; i < 4; i++)
#pragma unroll
                for (int t = 0; t < 4; t++) mma_f16(acc[i][t], ah[i], bh[t]);
        }
    }

    const int r_in = lane >> 2;
    const int c_in = (lane & 3) * 2;
#pragma unroll
    for (int i = 0; i < 4; i++) {
#pragma unroll
        for (int half = 0; half < 2; half++) {
            const int m = m0 + wm * 64 + i * 16 + r_in + half * 8;
            const int b = m >> 11, s = m & 2047;
#pragma unroll
            for (int t = 0; t < 4; t++) {
                const int n = n0 + wn * 32 + t * 8 + c_in;
                const float v0 = acc[i][t][half * 2], v1 = acc[i][t][half * 2 + 1];
                if (is_proj) {
                    const int h = n >> 6, d = n & 63;
                    if (z == 2) {   // V transposed [b][h][d][s]: v0,v1 differ in d
                        __half* dst = g_vh + ((size_t)(((b << 4) + h) << 6) + d) * 2048 + s;
                        dst[0]    = __float2half(v0);
                        dst[2048] = __float2half(v1);
                    } else {
                        __half* O = (z == 0) ? g_qh : g_kh;
                        *(uint32_t*)(O + (((size_t)((b << 4) + h) * 2048 + s) << 6) + d)
                            = pack_f16x2(v0, v1);
                    }
                } else {
                    *(float2*)(Cout + (size_t)m * 1024 + n) = make_float2(v0, v1);
                }
            }
        }
    }
}

// ---------------------------------------------------------------------------
// Quantum block on fp16 tensors (V transposed: stride 2048 between wires)
// ---------------------------------------------------------------------------
__global__ void quantum_kernel(const float* __restrict__ params)
{
    const int id = blockIdx.x * 256 + threadIdx.x;
    if (id >= 3 * 65536) return;
    const int tensor = id >> 16;
    const int idx = id & 65535;
    __half* vec;
    int stride;
    if (tensor == 0)      { vec = g_qh + (size_t)idx * 64; stride = 1; }
    else if (tensor == 1) { vec = g_kh + (size_t)idx * 64; stride = 1; }
    else {
        const int bh = idx >> 11, s = idx & 2047;
        vec = g_vh + ((size_t)bh << 6) * 2048 + s; stride = 2048;
    }

    float ax[4];
#pragma unroll
    for (int w = 0; w < 4; w++) ax[w] = __half2float(vec[w * stride]);

    float sr[16], si[16];
#pragma unroll
    for (int i = 0; i < 16; i++) { sr[i] = 0.f; si[i] = 0.f; }
    sr[0] = 1.f;

#pragma unroll
    for (int w = 0; w < 4; w++) {
        const float a = 0.5f * ax[w];
        float s, c;
        sincosf(a, &s, &c);
        const int st = 8 >> w;
#pragma unroll
        for (int i = 0; i < 16; i++) {
            if (i & st) continue;
            const int j = i + st;
            const float xr = sr[i], xi = si[i], yr = sr[j], yi = si[j];
            sr[i] = c * xr + s * yi;  si[i] = c * xi - s * yr;
            sr[j] = c * yr + s * xi;  si[j] = c * yi - s * xr;
        }
    }
#pragma unroll
    for (int l = 0; l < 2; l++) {
#pragma unroll
        for (int w = 0; w < 4; w++) {
            const float phi = params[l * 12 + w * 3 + 0];
            const float th  = params[l * 12 + w * 3 + 1];
            const float om  = params[l * 12 + w * 3 + 2];
            float stt, ct;  sincosf(0.5f * th, &stt, &ct);
            float sap, cap; sincosf(0.5f * (phi + om), &sap, &cap);
            float sam, cam; sincosf(0.5f * (phi - om), &sam, &cam);
            const float m00r =  cap * ct,  m00i = -sap * ct;
            const float m01r = -cam * stt, m01i = -sam * stt;
            const float m10r =  cam * stt, m10i = -sam * stt;
            const float m11r =  cap * ct,  m11i =  sap * ct;
            const int st = 8 >> w;
#pragma unroll
            for (int i = 0; i < 16; i++) {
                if (i & st) continue;
                const int j = i + st;
                const float xr = sr[i], xi = si[i], yr = sr[j], yi = si[j];
                sr[i] = m00r * xr - m00i * xi + m01r * yr - m01i * yi;
                si[i] = m00r * xi + m00i * xr + m01r * yi + m01i * yr;
                sr[j] = m10r * xr - m10i * xi + m11r * yr - m11i * yi;
                si[j] = m10r * xi + m10i * xr + m11r * yi + m11i * yr;
            }
        }
#pragma unroll
        for (int r = 0; r < 4; r++) {
            float tr = sr[8 + r], ti = si[8 + r];
            sr[8 + r] = sr[12 + r];  si[8 + r] = si[12 + r];
            sr[12 + r] = tr;         si[12 + r] = ti;
        }
    }
    float ev[4] = {0.f, 0.f, 0.f, 0.f};
#pragma unroll
    for (int i = 0; i < 16; i++) {
        const float pr = sr[i] * sr[i] + si[i] * si[i];
#pragma unroll
        for (int w = 0; w < 4; w++)
            ev[w] += ((i >> (3 - w)) & 1) ? -pr : pr;
    }
#pragma unroll
    for (int w = 0; w < 4; w++) vec[w * stride] = __float2half(ev[w]);
}

// ---------------------------------------------------------------------------
// FA2 attention, all fp16 1-term: scores Q single x K single, PV P x V single.
// No conversions in the loop — straight uint4 global->smem copies.
// Grid: (16, 32), 256 threads. smem: Q stage 18432 | K,V tiles double-buffered.
// ---------------------------------------------------------------------------
#define AP      72
#define APB     (AP * 2)
#define KHI_O   0
#define VHI_O   (64 * APB)
#define ABUF_B  (2 * 64 * APB)         // 18432
#define ASMEM   (2 * ABUF_B)           // 36864

__global__ __launch_bounds__(256, 1)
void attention_mma_kernel()
{
    extern __shared__ char smem[];
    const uint32_t sb = smem_u32(smem);
    const int tid  = threadIdx.x;
    const int wid  = tid >> 5;
    const int lane = tid & 31;

    const int bh = blockIdx.y;
    const int q0 = blockIdx.x * 128;

    const __half* qb = g_qh + (size_t)bh * 2048 * 64;
    const __half* kb = g_kh + (size_t)bh * 2048 * 64;
    const __half* vb = g_vh + (size_t)bh * 64 * 2048;

    // Q staging: 128x64 halves -> smem (pitch APB), then ldmatrix
    {
#pragma unroll
        for (int j = 0; j < 4; j++) {
            const int idx = j * 256 + tid;           // 0..1023 chunks of 8 halves
            const int r = idx >> 3, c8 = idx & 7;
            uint4 v = *(const uint4*)(qb + (size_t)(q0 + r) * 64 + c8 * 8);
            STS128(sb + (uint32_t)r * APB + (uint32_t)c8 * 16, v);
        }
    }
    __syncthreads();

    uint32_t qh[4][4];
    {
        const uint32_t a0 = sb + (uint32_t)(wid * 16 + (lane & 15)) * APB
                          + (uint32_t)((lane >> 4) * 8) * 2;
#pragma unroll
        for (int j = 0; j < 4; j++)
            ldmatrix_x4(qh[j], a0 + (uint32_t)(j * 16) * 2);
    }
    __syncthreads();

    float m0r = -1e30f, m1r = -1e30f, l0 = 0.f, l1 = 0.f;
    float o[8][4];
#pragma unroll
    for (int t = 0; t < 8; t++)
#pragma unroll
        for (int f = 0; f < 4; f++) o[t][f] = 0.f;

    const uint32_t brow4 = (uint32_t)((lane & 7) + ((lane >> 4) << 3)) * APB
                         + (uint32_t)(((lane >> 3) & 1) * 16);

    uint4 pf[4];
    auto load_tile = [&](int kt) {
#pragma unroll
        for (int j = 0; j < 2; j++) {                // K: 64x64 halves = 512 chunks
            const int idx = j * 256 + tid;
            const int key = idx >> 3, c8 = idx & 7;
            pf[j] = *(const uint4*)(kb + (size_t)(kt + key) * 64 + c8 * 8);
        }
#pragma unroll
        for (int j = 0; j < 2; j++) {                // V: rows d, cols keys
            const int idx = j * 256 + tid;
            const int d = idx >> 3, c8 = idx & 7;
            pf[2 + j] = *(const uint4*)(vb + (size_t)d * 2048 + kt + c8 * 8);
        }
    };
    auto store_tile = [&](int buf) {
        const uint32_t bp = sb + (uint32_t)buf * ABUF_B;
#pragma unroll
        for (int j = 0; j < 2; j++) {
            const int idx = j * 256 + tid;
            const int key = idx >> 3, c8 = idx & 7;
            STS128(bp + KHI_O + (uint32_t)key * APB + (uint32_t)c8 * 16, pf[j]);
        }
#pragma unroll
        for (int j = 0; j < 2; j++) {
            const int idx = j * 256 + tid;
            const int d = idx >> 3, c8 = idx & 7;
            STS128(bp + VHI_O + (uint32_t)d * APB + (uint32_t)c8 * 16, pf[2 + j]);
        }
    };

    load_tile(0);
    store_tile(0);
    __syncthreads();

    for (int kt = 0; kt < 32; kt++) {
        const int buf = kt & 1;
        if (kt < 31) load_tile((kt + 1) * 64);

        const uint32_t bp = sb + (uint32_t)buf * ABUF_B;

        float s[8][4];
#pragma unroll
        for (int n = 0; n < 8; n++)
#pragma unroll
            for (int f = 0; f < 4; f++) s[n][f] = 0.f;

        // ---- scores: 1-term, paired-x4 K frags ----
#pragma unroll
        for (int j = 0; j < 4; j++) {
            const uint32_t kb2 = (uint32_t)(j * 32);
            uint32_t kh[8][2];
#pragma unroll
            for (int p = 0; p < 4; p++) {
                const uint32_t ro = (uint32_t)(p * 16) * APB;
                uint32_t t4[4];
                ldmatrix_x4(t4, bp + KHI_O + brow4 + ro + kb2);
                kh[2 * p][0] = t4[0];     kh[2 * p][1] = t4[1];
                kh[2 * p + 1][0] = t4[2]; kh[2 * p + 1][1] = t4[3];
            }
#pragma unroll
            for (int n = 0; n < 8; n++) mma_f16(s[n], qh[j], kh[n]);
        }

        // ---- online softmax ----
        float tm0 = -1e30f, tm1 = -1e30f;
#pragma unroll
        for (int n = 0; n < 8; n++) {
#pragma unroll
            for (int f = 0; f < 4; f++) s[n][f] *= 0.125f;
            tm0 = fmaxf(tm0, fmaxf(s[n][0], s[n][1]));
            tm1 = fmaxf(tm1, fmaxf(s[n][2], s[n][3]));
        }
        tm0 = fmaxf(tm0, __shfl_xor_sync(0xffffffffu, tm0, 1));
        tm0 = fmaxf(tm0, __shfl_xor_sync(0xffffffffu, tm0, 2));
        tm1 = fmaxf(tm1, __shfl_xor_sync(0xffffffffu, tm1, 1));
        tm1 = fmaxf(tm1, __shfl_xor_sync(0xffffffffu, tm1, 2));
        const float mn0 = fmaxf(m0r, tm0), mn1 = fmaxf(m1r, tm1);
        const float a0 = __expf(m0r - mn0), a1 = __expf(m1r - mn1);
        m0r = mn0; m1r = mn1;

        float rs0 = 0.f, rs1 = 0.f;
#pragma unroll
        for (int n = 0; n < 8; n++) {
            s[n][0] = __expf(s[n][0] - mn0);
            s[n][1] = __expf(s[n][1] - mn0);
            s[n][2] = __expf(s[n][2] - mn1);
            s[n][3] = __expf(s[n][3] - mn1);
            rs0 += s[n][0] + s[n][1];
            rs1 += s[n][2] + s[n][3];
        }
        rs0 += __shfl_xor_sync(0xffffffffu, rs0, 1);
        rs0 += __shfl_xor_sync(0xffffffffu, rs0, 2);
        rs1 += __shfl_xor_sync(0xffffffffu, rs1, 1);
        rs1 += __shfl_xor_sync(0xffffffffu, rs1, 2);
        l0 = l0 * a0 + rs0;
        l1 = l1 * a1 + rs1;

#pragma unroll
        for (int t = 0; t < 8; t++) {
            o[t][0] *= a0; o[t][1] *= a0; o[t][2] *= a1; o[t][3] *= a1;
        }

        // ---- PV: 1-term, paired-x4 V frags ----
#pragma unroll
        for (int j = 0; j < 4; j++) {
            uint32_t ph[4];
            ph[0] = pack_f16x2(s[2 * j][0],     s[2 * j][1]);
            ph[1] = pack_f16x2(s[2 * j][2],     s[2 * j][3]);
            ph[2] = pack_f16x2(s[2 * j + 1][0], s[2 * j + 1][1]);
            ph[3] = pack_f16x2(s[2 * j + 1][2], s[2 * j + 1][3]);
            const uint32_t kb2 = (uint32_t)(j * 32);
            uint32_t vh[8][2];
#pragma unroll
            for (int p = 0; p < 4; p++) {
                const uint32_t ro = (uint32_t)(p * 16) * APB;
                uint32_t t4[4];
                ldmatrix_x4(t4, bp + VHI_O + brow4 + ro + kb2);
                vh[2 * p][0] = t4[0];     vh[2 * p][1] = t4[1];
                vh[2 * p + 1][0] = t4[2]; vh[2 * p + 1][1] = t4[3];
            }
#pragma unroll
            for (int t = 0; t < 8; t++) mma_f16(o[t], ph, vh[t]);
        }

        if (kt < 31) {
            store_tile(buf ^ 1);
            __syncthreads();
        }
    }

    // ---- fp16 epilogue into g_aoh [b][s][h*64+d] ----
    const int b = bh >> 4, h = bh & 15;
    const int r0 = q0 + wid * 16 + (lane >> 2);
    const int c0 = h * 64 + (lane & 3) * 2;
    const float il0 = 1.f / l0, il1 = 1.f / l1;
    uint32_t* aoh = (uint32_t*)g_aoh;
#pragma unroll
    for (int t = 0; t < 8; t++) {
        const uint32_t p0 = pack_f16x2(o[t][0] * il0, o[t][1] * il0);
        const uint32_t p1 = pack_f16x2(o[t][2] * il1, o[t][3] * il1);
        aoh[((size_t)(b * 2048 + r0) * 1024 + c0 + t * 8) >> 1]     = p0;
        aoh[((size_t)(b * 2048 + r0 + 8) * 1024 + c0 + t * 8) >> 1] = p1;
    }
}

// ---------------------------------------------------------------------------
extern "C" void kernel_launch(void* const* d_in, const int* in_sizes, int n_in,
                              void* d_out, int out_size)
{
    const float* x      = (const float*)d_in[0];
    const float* params = (const float*)d_in[1];
    const float* wq     = (const float*)d_in[2];
    const float* wk     = (const float*)d_in[3];
    const float* wv     = (const float*)d_in[4];
    const float* wo     = (const float*)d_in[5];
    float* out = (float*)d_out;

    cudaFuncSetAttribute(gemm_mma_kernel,
                         cudaFuncAttributeMaxDynamicSharedMemorySize, GSMEM);
    cudaFuncSetAttribute(attention_mma_kernel,
                         cudaFuncAttributeMaxDynamicSharedMemorySize, ASMEM);

    __half *xh, *aoh;
    cudaGetSymbolAddress((void**)&xh,  g_xh);
    cudaGetSymbolAddress((void**)&aoh, g_aoh);

    cvt_all_kernel<<<8192, 256>>>(x, wq, wk, wv, wo);
    gemm_mma_kernel<<<dim3(8, 32, 3), 256, GSMEM>>>(xh, nullptr, 1);
    quantum_kernel<<<768, 256>>>(params);
    attention_mma_kernel<<<dim3(16, 32), 256, ASMEM>>>();
    gemm_mma_kernel<<<dim3(8, 32, 1), 256, GSMEM>>>(aoh, out, 0);
}

// round 11
// speedup vs baseline: 7.0191x; 1.0879x over previous
#include <cuda_runtime.h>
#include <cuda_fp16.h>
#include <cstdint>

// ---------------------------------------------------------------------------
// QuantumAttention  (B=2, S=2048, E=1024, H=16, dk=64, NQ=4, NL=2)
// Round 11: attention occupancy rework — 128-thr CTAs (3/SM), cp.async K/V
// ring, 1/sqrt(dk) folded into Q staging (exact in fp16). GEMMs as R10.
// ---------------------------------------------------------------------------

__device__ __half g_qh [2*16*2048*64];   // [b][h][s][d]
__device__ __half g_kh [2*16*2048*64];   // [b][h][s][d]
__device__ __half g_vh [2*16*2048*64];   // [b][h][d][s]  (transposed!)
__device__ __half g_aoh[4096*1024];      // attention out [b][s][h*64+d]
__device__ __half g_xh [4096*1024];      // x single-rounded
__device__ __half g_wh [4*1024*1024];    // q,k,v,o packed

// ---------------- helpers ---------------------------------------------------
__device__ __forceinline__ uint32_t smem_u32(const void* p) {
    uint32_t a;
    asm("{ .reg .u64 t; cvta.to.shared.u64 t, %1; cvt.u32.u64 %0, t; }" : "=r"(a) : "l"(p));
    return a;
}
#define CP_ASYNC16(dst, src) \
    asm volatile("cp.async.cg.shared.global [%0], [%1], 16;" :: "r"(dst), "l"(src) : "memory")
#define CP_COMMIT() asm volatile("cp.async.commit_group;" ::: "memory")
#define CP_WAIT(n)  asm volatile("cp.async.wait_group %0;" :: "n"(n) : "memory")

__device__ __forceinline__ void ldmatrix_x4(uint32_t (&r)[4], uint32_t addr) {
    asm volatile("ldmatrix.sync.aligned.m8n8.x4.shared.b16 {%0,%1,%2,%3}, [%4];"
                 : "=r"(r[0]), "=r"(r[1]), "=r"(r[2]), "=r"(r[3]) : "r"(addr));
}
__device__ __forceinline__ void mma_f16(float (&d)[4], const uint32_t (&a)[4],
                                        const uint32_t (&b)[2]) {
    asm volatile("mma.sync.aligned.m16n8k16.row.col.f32.f16.f16.f32 "
                 "{%0,%1,%2,%3}, {%4,%5,%6,%7}, {%8,%9}, {%0,%1,%2,%3};"
                 : "+f"(d[0]), "+f"(d[1]), "+f"(d[2]), "+f"(d[3])
                 : "r"(a[0]), "r"(a[1]), "r"(a[2]), "r"(a[3]), "r"(b[0]), "r"(b[1]));
}
__device__ __forceinline__ uint32_t pack_f16x2(float lo, float hi) {
    uint32_t r;
    asm("cvt.rn.f16x2.f32 %0, %1, %2;" : "=r"(r) : "f"(hi), "f"(lo));
    return r;
}
__device__ __forceinline__ uint2 cvt4_hi(const float4 v) {
    return make_uint2(pack_f16x2(v.x, v.y), pack_f16x2(v.z, v.w));
}
#define STS128(ad, v)                                                           \
    asm volatile("st.shared.v4.b32 [%0], {%1, %2, %3, %4};"                     \
        :: "r"(ad), "r"((v).x), "r"((v).y), "r"((v).z), "r"((v).w) : "memory")

// ---------------------------------------------------------------------------
// Fused fp32 -> fp16 convert: x (1M float4 units) + 4 weights (256K each)
// ---------------------------------------------------------------------------
__global__ void cvt_all_kernel(const float* __restrict__ x,
                               const float* __restrict__ wq,
                               const float* __restrict__ wk,
                               const float* __restrict__ wv,
                               const float* __restrict__ wo)
{
    const int i = blockIdx.x * 256 + threadIdx.x;
    const float* src;
    __half* dst;
    int off;
    if (i < 1048576) {
        src = x; dst = g_xh; off = i;
    } else {
        const int j = i - 1048576;
        const int sel = j >> 18;
        off = j & 262143;
        const float* ws[4] = {wq, wk, wv, wo};
        src = ws[sel];
        dst = g_wh + (size_t)sel * 1048576;
    }
    float4 v = ((const float4*)src)[off];
    ((uint2*)dst)[off] = cvt4_hi(v);
}

// ---------------------------------------------------------------------------
// mma.sync GEMM, 1-term (as R10)
// ---------------------------------------------------------------------------
#define PITCH   40
#define PITCHB  (PITCH * 2)
#define MAT_B   (128 * PITCHB)
#define STAGE_B (2 * MAT_B)
#define NSTG    3
#define GSMEM   (NSTG * STAGE_B)

__global__ __launch_bounds__(256, 2)
void gemm_mma_kernel(const __half* __restrict__ A,
                     float* __restrict__ Cout, int is_proj)
{
    extern __shared__ char smem[];
    const uint32_t sb = smem_u32(smem);
    const int tid  = threadIdx.x;
    const int wid  = tid >> 5;
    const int lane = tid & 31;

    const int z  = blockIdx.z;
    const int m0 = blockIdx.y * 128;
    const int n0 = blockIdx.x * 128;
    const size_t woff = ((size_t)(is_proj ? z : 3)) << 20;

    const __half* gsrc[2] = { A + (size_t)m0 * 1024,
                              g_wh + woff + (size_t)n0 * 1024 };

    const int wm = wid & 1;
    const int wn = wid >> 1;
    const uint32_t a_addr0 = (uint32_t)(wm * 64 + (lane & 15)) * PITCHB
                           + (uint32_t)((lane >> 4) * 8) * 2;
    const uint32_t b_addr0 = (uint32_t)(wn * 32 + (lane & 7) + ((lane >> 4) << 3)) * PITCHB
                           + (uint32_t)(((lane >> 3) & 1) * 16);

    float acc[4][4][4];
#pragma unroll
    for (int i = 0; i < 4; i++)
#pragma unroll
        for (int t = 0; t < 4; t++)
#pragma unroll
            for (int f = 0; f < 4; f++) acc[i][t][f] = 0.f;

    auto load_stage = [&](int ch, int stg) {
        const int k0 = ch * 32;
        const uint32_t dst = sb + (uint32_t)stg * STAGE_B;
#pragma unroll
        for (int j = 0; j < 4; j++) {
            const int idx = j * 256 + tid;
            const int mat = idx >> 9;
            const int w   = idx & 511;
            const int row = w >> 2;
            const int c16 = w & 3;
            CP_ASYNC16(dst + (uint32_t)mat * MAT_B + (uint32_t)row * PITCHB
                           + (uint32_t)c16 * 16,
                       gsrc[mat] + (size_t)row * 1024 + k0 + c16 * 8);
        }
        CP_COMMIT();
    };

    load_stage(0, 0);
    load_stage(1, 1);

    for (int ch = 0; ch < 32; ch++) {
        CP_WAIT(1);
        __syncthreads();
        if (ch + 2 < 32) load_stage(ch + 2, (ch + 2) % NSTG);

        const uint32_t stg = sb + (uint32_t)(ch % NSTG) * STAGE_B;
#pragma unroll
        for (int ks = 0; ks < 2; ks++) {
            const uint32_t kb = (uint32_t)(ks * 32);
            uint32_t ah[4][4];
#pragma unroll
            for (int i = 0; i < 4; i++) {
                const uint32_t ro = (uint32_t)(i * 16) * PITCHB;
                ldmatrix_x4(ah[i], stg + 0 * MAT_B + a_addr0 + ro + kb);
            }
            uint32_t bh[4][2];
#pragma unroll
            for (int p = 0; p < 2; p++) {
                const uint32_t ro = (uint32_t)(p * 16) * PITCHB;
                uint32_t t4[4];
                ldmatrix_x4(t4, stg + 1 * MAT_B + b_addr0 + ro + kb);
                bh[2 * p][0] = t4[0];     bh[2 * p][1] = t4[1];
                bh[2 * p + 1][0] = t4[2]; bh[2 * p + 1][1] = t4[3];
            }
#pragma unroll
            for (int i = 0; i < 4; i++)
#pragma unroll
                for (int t = 0; t < 4; t++) mma_f16(acc[i][t], ah[i], bh[t]);
        }
    }

    const int r_in = lane >> 2;
    const int c_in = (lane & 3) * 2;
#pragma unroll
    for (int i = 0; i < 4; i++) {
#pragma unroll
        for (int half = 0; half < 2; half++) {
            const int m = m0 + wm * 64 + i * 16 + r_in + half * 8;
            const int b = m >> 11, s = m & 2047;
#pragma unroll
            for (int t = 0; t < 4; t++) {
                const int n = n0 + wn * 32 + t * 8 + c_in;
                const float v0 = acc[i][t][half * 2], v1 = acc[i][t][half * 2 + 1];
                if (is_proj) {
                    const int h = n >> 6, d = n & 63;
                    if (z == 2) {
                        __half* dst = g_vh + ((size_t)(((b << 4) + h) << 6) + d) * 2048 + s;
                        dst[0]    = __float2half(v0);
                        dst[2048] = __float2half(v1);
                    } else {
                        __half* O = (z == 0) ? g_qh : g_kh;
                        *(uint32_t*)(O + (((size_t)((b << 4) + h) * 2048 + s) << 6) + d)
                            = pack_f16x2(v0, v1);
                    }
                } else {
                    *(float2*)(Cout + (size_t)m * 1024 + n) = make_float2(v0, v1);
                }
            }
        }
    }
}

// ---------------------------------------------------------------------------
// Quantum block on fp16 tensors (as R10)
// ---------------------------------------------------------------------------
__global__ void quantum_kernel(const float* __restrict__ params)
{
    const int id = blockIdx.x * 256 + threadIdx.x;
    if (id >= 3 * 65536) return;
    const int tensor = id >> 16;
    const int idx = id & 65535;
    __half* vec;
    int stride;
    if (tensor == 0)      { vec = g_qh + (size_t)idx * 64; stride = 1; }
    else if (tensor == 1) { vec = g_kh + (size_t)idx * 64; stride = 1; }
    else {
        const int bh = idx >> 11, s = idx & 2047;
        vec = g_vh + ((size_t)bh << 6) * 2048 + s; stride = 2048;
    }

    float ax[4];
#pragma unroll
    for (int w = 0; w < 4; w++) ax[w] = __half2float(vec[w * stride]);

    float sr[16], si[16];
#pragma unroll
    for (int i = 0; i < 16; i++) { sr[i] = 0.f; si[i] = 0.f; }
    sr[0] = 1.f;

#pragma unroll
    for (int w = 0; w < 4; w++) {
        const float a = 0.5f * ax[w];
        float s, c;
        sincosf(a, &s, &c);
        const int st = 8 >> w;
#pragma unroll
        for (int i = 0; i < 16; i++) {
            if (i & st) continue;
            const int j = i + st;
            const float xr = sr[i], xi = si[i], yr = sr[j], yi = si[j];
            sr[i] = c * xr + s * yi;  si[i] = c * xi - s * yr;
            sr[j] = c * yr + s * xi;  si[j] = c * yi - s * xr;
        }
    }
#pragma unroll
    for (int l = 0; l < 2; l++) {
#pragma unroll
        for (int w = 0; w < 4; w++) {
            const float phi = params[l * 12 + w * 3 + 0];
            const float th  = params[l * 12 + w * 3 + 1];
            const float om  = params[l * 12 + w * 3 + 2];
            float stt, ct;  sincosf(0.5f * th, &stt, &ct);
            float sap, cap; sincosf(0.5f * (phi + om), &sap, &cap);
            float sam, cam; sincosf(0.5f * (phi - om), &sam, &cam);
            const float m00r =  cap * ct,  m00i = -sap * ct;
            const float m01r = -cam * stt, m01i = -sam * stt;
            const float m10r =  cam * stt, m10i = -sam * stt;
            const float m11r =  cap * ct,  m11i =  sap * ct;
            const int st = 8 >> w;
#pragma unroll
            for (int i = 0; i < 16; i++) {
                if (i & st) continue;
                const int j = i + st;
                const float xr = sr[i], xi = si[i], yr = sr[j], yi = si[j];
                sr[i] = m00r * xr - m00i * xi + m01r * yr - m01i * yi;
                si[i] = m00r * xi + m00i * xr + m01r * yi + m01i * yr;
                sr[j] = m10r * xr - m10i * xi + m11r * yr - m11i * yi;
                si[j] = m10r * xi + m10i * xr + m11r * yi + m11i * yr;
            }
        }
#pragma unroll
        for (int r = 0; r < 4; r++) {
            float tr = sr[8 + r], ti = si[8 + r];
            sr[8 + r] = sr[12 + r];  si[8 + r] = si[12 + r];
            sr[12 + r] = tr;         si[12 + r] = ti;
        }
    }
    float ev[4] = {0.f, 0.f, 0.f, 0.f};
#pragma unroll
    for (int i = 0; i < 16; i++) {
        const float pr = sr[i] * sr[i] + si[i] * si[i];
#pragma unroll
        for (int w = 0; w < 4; w++)
            ev[w] += ((i >> (3 - w)) & 1) ? -pr : pr;
    }
#pragma unroll
    for (int w = 0; w < 4; w++) vec[w * stride] = __float2half(ev[w]);
}

// ---------------------------------------------------------------------------
// FA2 attention: 128 threads (4 warps x 16 q-rows = 64 q-rows/CTA), 3 CTAs/SM.
// K/V via cp.async 2-stage ring. Q pre-scaled by 1/8 at staging (exact fp16).
// Grid: (32, 32).
// ---------------------------------------------------------------------------
#define AP      72
#define APB     (AP * 2)
#define KO      0
#define VO      (64 * APB)             // 9216
#define ABUF_B  (2 * 64 * APB)         // 18432 per stage (K + V)
#define ASMEM   (2 * ABUF_B)           // 36864

__global__ __launch_bounds__(128, 3)
void attention_mma_kernel()
{
    extern __shared__ char smem[];
    const uint32_t sb = smem_u32(smem);
    const int tid  = threadIdx.x;
    const int wid  = tid >> 5;
    const int lane = tid & 31;

    const int bh = blockIdx.y;
    const int q0 = blockIdx.x * 64;

    const __half* qb = g_qh + (size_t)bh * 2048 * 64;
    const __half* kb = g_kh + (size_t)bh * 2048 * 64;
    const __half* vb = g_vh + (size_t)bh * 64 * 2048;

    // ---- Q staging (64 rows x 64 halves), pre-scaled by 0.125 (exact) ------
    {
        const __half2 sc = __float2half2_rn(0.125f);
#pragma unroll
        for (int j = 0; j < 4; j++) {
            const int idx = j * 128 + tid;           // 0..511 chunks of 8 halves
            const int r = idx >> 3, c8 = idx & 7;
            uint4 v = *(const uint4*)(qb + (size_t)(q0 + r) * 64 + c8 * 8);
            __half2* h = reinterpret_cast<__half2*>(&v);
            h[0] = __hmul2(h[0], sc); h[1] = __hmul2(h[1], sc);
            h[2] = __hmul2(h[2], sc); h[3] = __hmul2(h[3], sc);
            STS128(sb + (uint32_t)r * APB + (uint32_t)c8 * 16, v);
        }
    }
    __syncthreads();

    uint32_t qh[4][4];
    {
        const uint32_t a0 = sb + (uint32_t)(wid * 16 + (lane & 15)) * APB
                          + (uint32_t)((lane >> 4) * 8) * 2;
#pragma unroll
        for (int j = 0; j < 4; j++)
            ldmatrix_x4(qh[j], a0 + (uint32_t)(j * 16) * 2);
    }
    __syncthreads();

    // ---- cp.async K/V ring -------------------------------------------------
    auto load_stage = [&](int kt, int stg) {
        const uint32_t bp = sb + (uint32_t)stg * ABUF_B;
#pragma unroll
        for (int j = 0; j < 8; j++) {
            const int idx = j * 128 + tid;           // 0..1023
            if (idx < 512) {
                const int key = idx >> 3, c8 = idx & 7;
                CP_ASYNC16(bp + KO + (uint32_t)key * APB + (uint32_t)c8 * 16,
                           kb + (size_t)(kt + key) * 64 + c8 * 8);
            } else {
                const int w = idx - 512;
                const int d = w >> 3, c8 = w & 7;
                CP_ASYNC16(bp + VO + (uint32_t)d * APB + (uint32_t)c8 * 16,
                           vb + (size_t)d * 2048 + kt + c8 * 8);
            }
        }
        CP_COMMIT();
    };

    load_stage(0, 0);
    load_stage(64, 1);

    float m0r = -1e30f, m1r = -1e30f, l0 = 0.f, l1 = 0.f;
    float o[8][4];
#pragma unroll
    for (int t = 0; t < 8; t++)
#pragma unroll
        for (int f = 0; f < 4; f++) o[t][f] = 0.f;

    const uint32_t brow4 = (uint32_t)((lane & 7) + ((lane >> 4) << 3)) * APB
                         + (uint32_t)(((lane >> 3) & 1) * 16);

    for (int kt = 0; kt < 32; kt++) {
        if (kt < 31) { CP_WAIT(1); } else { CP_WAIT(0); }
        __syncthreads();

        const uint32_t bp = sb + (uint32_t)(kt & 1) * ABUF_B;

        float s[8][4];
#pragma unroll
        for (int n = 0; n < 8; n++)
#pragma unroll
            for (int f = 0; f < 4; f++) s[n][f] = 0.f;

        // ---- scores (Q pre-scaled) ----
#pragma unroll
        for (int j = 0; j < 4; j++) {
            const uint32_t kb2 = (uint32_t)(j * 32);
            uint32_t kh[8][2];
#pragma unroll
            for (int p = 0; p < 4; p++) {
                const uint32_t ro = (uint32_t)(p * 16) * APB;
                uint32_t t4[4];
                ldmatrix_x4(t4, bp + KO + brow4 + ro + kb2);
                kh[2 * p][0] = t4[0];     kh[2 * p][1] = t4[1];
                kh[2 * p + 1][0] = t4[2]; kh[2 * p + 1][1] = t4[3];
            }
#pragma unroll
            for (int n = 0; n < 8; n++) mma_f16(s[n], qh[j], kh[n]);
        }

        // ---- online softmax ----
        float tm0 = -1e30f, tm1 = -1e30f;
#pragma unroll
        for (int n = 0; n < 8; n++) {
            tm0 = fmaxf(tm0, fmaxf(s[n][0], s[n][1]));
            tm1 = fmaxf(tm1, fmaxf(s[n][2], s[n][3]));
        }
        tm0 = fmaxf(tm0, __shfl_xor_sync(0xffffffffu, tm0, 1));
        tm0 = fmaxf(tm0, __shfl_xor_sync(0xffffffffu, tm0, 2));
        tm1 = fmaxf(tm1, __shfl_xor_sync(0xffffffffu, tm1, 1));
        tm1 = fmaxf(tm1, __shfl_xor_sync(0xffffffffu, tm1, 2));
        const float mn0 = fmaxf(m0r, tm0), mn1 = fmaxf(m1r, tm1);
        const float a0 = __expf(m0r - mn0), a1 = __expf(m1r - mn1);
        m0r = mn0; m1r = mn1;

        float rs0 = 0.f, rs1 = 0.f;
#pragma unroll
        for (int n = 0; n < 8; n++) {
            s[n][0] = __expf(s[n][0] - mn0);
            s[n][1] = __expf(s[n][1] - mn0);
            s[n][2] = __expf(s[n][2] - mn1);
            s[n][3] = __expf(s[n][3] - mn1);
            rs0 += s[n][0] + s[n][1];
            rs1 += s[n][2] + s[n][3];
        }
        rs0 += __shfl_xor_sync(0xffffffffu, rs0, 1);
        rs0 += __shfl_xor_sync(0xffffffffu, rs0, 2);
        rs1 += __shfl_xor_sync(0xffffffffu, rs1, 1);
        rs1 += __shfl_xor_sync(0xffffffffu, rs1, 2);
        l0 = l0 * a0 + rs0;
        l1 = l1 * a1 + rs1;

#pragma unroll
        for (int t = 0; t < 8; t++) {
            o[t][0] *= a0; o[t][1] *= a0; o[t][2] *= a1; o[t][3] *= a1;
        }

        // ---- PV ----
#pragma unroll
        for (int j = 0; j < 4; j++) {
            uint32_t ph[4];
            ph[0] = pack_f16x2(s[2 * j][0],     s[2 * j][1]);
            ph[1] = pack_f16x2(s[2 * j][2],     s[2 * j][3]);
            ph[2] = pack_f16x2(s[2 * j + 1][0], s[2 * j + 1][1]);
            ph[3] = pack_f16x2(s[2 * j + 1][2], s[2 * j + 1][3]);
            const uint32_t kb2 = (uint32_t)(j * 32);
            uint32_t vh[8][2];
#pragma unroll
            for (int p = 0; p < 4; p++) {
                const uint32_t ro = (uint32_t)(p * 16) * APB;
                uint32_t t4[4];
                ldmatrix_x4(t4, bp + VO + brow4 + ro + kb2);
                vh[2 * p][0] = t4[0];     vh[2 * p][1] = t4[1];
                vh[2 * p + 1][0] = t4[2]; vh[2 * p + 1][1] = t4[3];
            }
#pragma unroll
            for (int t = 0; t < 8; t++) mma_f16(o[t], ph, vh[t]);
        }

        __syncthreads();   // all reads of buf (kt&1) done before refill
        if (kt + 2 < 32) load_stage((kt + 2) * 64, kt & 1);
    }

    // ---- fp16 epilogue into g_aoh [b][s][h*64+d] ----
    const int b = bh >> 4, h = bh & 15;
    const int r0 = q0 + wid * 16 + (lane >> 2);
    const int c0 = h * 64 + (lane & 3) * 2;
    const float il0 = 1.f / l0, il1 = 1.f / l1;
    uint32_t* aoh = (uint32_t*)g_aoh;
#pragma unroll
    for (int t = 0; t < 8; t++) {
        const uint32_t p0 = pack_f16x2(o[t][0] * il0, o[t][1] * il0);
        const uint32_t p1 = pack_f16x2(o[t][2] * il1, o[t][3] * il1);
        aoh[((size_t)(b * 2048 + r0) * 1024 + c0 + t * 8) >> 1]     = p0;
        aoh[((size_t)(b * 2048 + r0 + 8) * 1024 + c0 + t * 8) >> 1] = p1;
    }
}

// ---------------------------------------------------------------------------
extern "C" void kernel_launch(void* const* d_in, const int* in_sizes, int n_in,
                              void* d_out, int out_size)
{
    const float* x      = (const float*)d_in[0];
    const float* params = (const float*)d_in[1];
    const float* wq     = (const float*)d_in[2];
    const float* wk     = (const float*)d_in[3];
    const float* wv     = (const float*)d_in[4];
    const float* wo     = (const float*)d_in[5];
    float* out = (float*)d_out;

    cudaFuncSetAttribute(gemm_mma_kernel,
                         cudaFuncAttributeMaxDynamicSharedMemorySize, GSMEM);
    cudaFuncSetAttribute(attention_mma_kernel,
                         cudaFuncAttributeMaxDynamicSharedMemorySize, ASMEM);

    __half *xh, *aoh;
    cudaGetSymbolAddress((void**)&xh,  g_xh);
    cudaGetSymbolAddress((void**)&aoh, g_aoh);

    cvt_all_kernel<<<8192, 256>>>(x, wq, wk, wv, wo);
    gemm_mma_kernel<<<dim3(8, 32, 3), 256, GSMEM>>>(xh, nullptr, 1);
    quantum_kernel<<<768, 256>>>(params);
    attention_mma_kernel<<<dim3(32, 32), 128, ASMEM>>>();
    gemm_mma_kernel<<<dim3(8, 32, 1), 256, GSMEM>>>(aoh, out, 0);
}